// round 1
// baseline (speedup 1.0000x reference)
#include <cuda_runtime.h>

#define HEADS 12
#define SEQ   2048
#define BATCH 4
#define DH    64
#define CDIM  768

// Scratch (allocation-free): Q/K/V in [B,H,N,D], attention output in [B,N,C]
__device__ float g_q[(size_t)BATCH * HEADS * SEQ * DH];
__device__ float g_k[(size_t)BATCH * HEADS * SEQ * DH];
__device__ float g_v[(size_t)BATCH * HEADS * SEQ * DH];
__device__ float g_attn[(size_t)BATCH * SEQ * CDIM];

// ---------------------------------------------------------------------------
// Tiled SGEMM: C[M, Ncols] = A[M,768] @ W[Ncols,768]^T + bias
// BM=BN=64, BK=16, 256 threads, 4x4 microtile per thread.
// MODE 0: A = x, scatter columns into g_q/g_k/g_v ([B,H,N,D] layout)
// MODE 1: A = g_attn, plain row-major output to `out`
// ---------------------------------------------------------------------------
template <int MODE>
__global__ __launch_bounds__(256)
void gemm_kernel(const float* __restrict__ A, const float* __restrict__ W,
                 const float* __restrict__ bias, float* __restrict__ out)
{
    __shared__ float As[16 * 68];   // A^T tile: As[k][m], stride 68 (conflict-free, 16B aligned)
    __shared__ float Bs[16 * 68];   // W^T tile: Bs[k][n]

    const int bx  = blockIdx.x;           // column tile
    const int by  = blockIdx.y;           // row tile
    const int tid = threadIdx.x;
    const int tx  = tid & 15;             // 0..15 (column group)
    const int ty  = tid >> 4;             // 0..15 (row group)
    const int lr  = tid >> 2;             // 0..63 load row
    const int lk  = (tid & 3) * 4;        // 0,4,8,12 load k base

    const float* Aptr = (MODE == 0) ? A : g_attn;
    const float* Ag = Aptr + (size_t)(by * 64 + lr) * CDIM + lk;
    const float* Wg = W    + (size_t)(bx * 64 + lr) * CDIM + lk;

    float acc[4][4] = {};

    for (int k0 = 0; k0 < CDIM; k0 += 16) {
        float4 av = *(const float4*)(Ag + k0);
        float4 wv = *(const float4*)(Wg + k0);
        __syncthreads();
        As[(lk + 0) * 68 + lr] = av.x;
        As[(lk + 1) * 68 + lr] = av.y;
        As[(lk + 2) * 68 + lr] = av.z;
        As[(lk + 3) * 68 + lr] = av.w;
        Bs[(lk + 0) * 68 + lr] = wv.x;
        Bs[(lk + 1) * 68 + lr] = wv.y;
        Bs[(lk + 2) * 68 + lr] = wv.z;
        Bs[(lk + 3) * 68 + lr] = wv.w;
        __syncthreads();

        #pragma unroll
        for (int k = 0; k < 16; ++k) {
            float4 a = *(const float4*)&As[k * 68 + ty * 4];
            float4 b = *(const float4*)&Bs[k * 68 + tx * 4];
            float af[4] = {a.x, a.y, a.z, a.w};
            float bf[4] = {b.x, b.y, b.z, b.w};
            #pragma unroll
            for (int i = 0; i < 4; ++i)
                #pragma unroll
                for (int j = 0; j < 4; ++j)
                    acc[i][j] += af[i] * bf[j];
        }
    }

    float4 bv = *(const float4*)&bias[bx * 64 + tx * 4];
    float bf[4] = {bv.x, bv.y, bv.z, bv.w};

    if (MODE == 0) {
        // column block bx in [0,36): t = bx/12 selects q/k/v, h = bx%12
        const int t = bx / HEADS;
        const int h = bx - t * HEADS;
        float* dst = (t == 0) ? g_q : (t == 1) ? g_k : g_v;
        #pragma unroll
        for (int i = 0; i < 4; ++i) {
            const int m = by * 64 + ty * 4 + i;
            const int b = m >> 11;         // / 2048
            const int n = m & 2047;
            float4 o;
            o.x = acc[i][0] + bf[0];
            o.y = acc[i][1] + bf[1];
            o.z = acc[i][2] + bf[2];
            o.w = acc[i][3] + bf[3];
            *(float4*)&dst[(((size_t)b * HEADS + h) * SEQ + n) * DH + tx * 4] = o;
        }
    } else {
        #pragma unroll
        for (int i = 0; i < 4; ++i) {
            const int m = by * 64 + ty * 4 + i;
            float4 o;
            o.x = acc[i][0] + bf[0];
            o.y = acc[i][1] + bf[1];
            o.z = acc[i][2] + bf[2];
            o.w = acc[i][3] + bf[3];
            *(float4*)&out[(size_t)m * CDIM + bx * 64 + tx * 4] = o;
        }
    }
}

// ---------------------------------------------------------------------------
// Flash attention: one block per (64 q rows, head, batch). fp32, online softmax.
// Smem: Qs[d][r] (Q^T, pre-scaled), KPs = K^T tile then reused for P[r][j], Vs[j][d].
// ---------------------------------------------------------------------------
__global__ __launch_bounds__(256)
void attn_kernel()
{
    __shared__ float Qs[64 * 64];
    __shared__ float KPs[64 * 64];
    __shared__ float Vs[64 * 64];

    const int q0 = blockIdx.x * 64;
    const int h  = blockIdx.y;
    const int b  = blockIdx.z;
    const size_t base = ((size_t)(b * HEADS + h)) * SEQ * DH;

    const int tid = threadIdx.x;
    const int tx  = tid & 15;
    const int ty  = tid >> 4;
    const int lr  = tid >> 2;        // 0..63
    const int ld  = (tid & 3) * 16;  // 0,16,32,48

    // Load Q tile transposed into Qs[d][r], pre-multiplied by 1/sqrt(D)=0.125
    {
        const float* qg = g_q + base + (size_t)(q0 + lr) * DH + ld;
        #pragma unroll
        for (int u = 0; u < 4; ++u) {
            float4 v = *(const float4*)(qg + u * 4);
            Qs[(ld + u * 4 + 0) * 64 + lr] = v.x * 0.125f;
            Qs[(ld + u * 4 + 1) * 64 + lr] = v.y * 0.125f;
            Qs[(ld + u * 4 + 2) * 64 + lr] = v.z * 0.125f;
            Qs[(ld + u * 4 + 3) * 64 + lr] = v.w * 0.125f;
        }
    }

    float m_i[4], l_i[4], o[4][4];
    #pragma unroll
    for (int i = 0; i < 4; ++i) {
        m_i[i] = -1e30f;
        l_i[i] = 0.f;
        #pragma unroll
        for (int w = 0; w < 4; ++w) o[i][w] = 0.f;
    }

    for (int k0 = 0; k0 < SEQ; k0 += 64) {
        // Prefetch K/V tile into registers before the barrier
        const float* kg = g_k + base + (size_t)(k0 + lr) * DH + ld;
        const float* vg = g_v + base + (size_t)(k0 + lr) * DH + ld;
        float4 kv[4], vv[4];
        #pragma unroll
        for (int u = 0; u < 4; ++u) {
            kv[u] = *(const float4*)(kg + u * 4);
            vv[u] = *(const float4*)(vg + u * 4);
        }
        __syncthreads();   // previous iteration's consumers (and Q store) done
        #pragma unroll
        for (int u = 0; u < 4; ++u) {
            KPs[(ld + u * 4 + 0) * 64 + lr] = kv[u].x;   // K^T: KPs[d][kr]
            KPs[(ld + u * 4 + 1) * 64 + lr] = kv[u].y;
            KPs[(ld + u * 4 + 2) * 64 + lr] = kv[u].z;
            KPs[(ld + u * 4 + 3) * 64 + lr] = kv[u].w;
            *(float4*)&Vs[lr * 64 + ld + u * 4] = vv[u]; // V: Vs[kr][d]
        }
        __syncthreads();

        // S = (Q * scale) @ K^T : 4x4 per thread
        float s[4][4] = {};
        #pragma unroll
        for (int d = 0; d < 64; ++d) {
            float4 qv = *(const float4*)&Qs[d * 64 + ty * 4];
            float4 kk = *(const float4*)&KPs[d * 64 + tx * 4];
            float qf[4] = {qv.x, qv.y, qv.z, qv.w};
            float kf[4] = {kk.x, kk.y, kk.z, kk.w};
            #pragma unroll
            for (int i = 0; i < 4; ++i)
                #pragma unroll
                for (int j = 0; j < 4; ++j)
                    s[i][j] += qf[i] * kf[j];
        }

        // Online softmax (row reductions across the 16-lane tx group)
        #pragma unroll
        for (int i = 0; i < 4; ++i) {
            float mx = fmaxf(fmaxf(s[i][0], s[i][1]), fmaxf(s[i][2], s[i][3]));
            #pragma unroll
            for (int off = 8; off >= 1; off >>= 1)
                mx = fmaxf(mx, __shfl_xor_sync(0xffffffffu, mx, off));
            const float mn = fmaxf(m_i[i], mx);
            const float alpha = __expf(m_i[i] - mn);
            m_i[i] = mn;
            float r = 0.f;
            #pragma unroll
            for (int j = 0; j < 4; ++j) {
                const float p = __expf(s[i][j] - mn);
                s[i][j] = p;
                r += p;
            }
            #pragma unroll
            for (int off = 8; off >= 1; off >>= 1)
                r += __shfl_xor_sync(0xffffffffu, r, off);
            l_i[i] = l_i[i] * alpha + r;
            #pragma unroll
            for (int w = 0; w < 4; ++w) o[i][w] *= alpha;
        }

        __syncthreads();   // all threads done reading KPs as K
        // Store P into KPs as P[r][j] (float4 rows -> conflict-free)
        #pragma unroll
        for (int i = 0; i < 4; ++i) {
            float4 p4 = make_float4(s[i][0], s[i][1], s[i][2], s[i][3]);
            *(float4*)&KPs[(ty * 4 + i) * 64 + tx * 4] = p4;
        }
        __syncthreads();

        // O += P @ V
        #pragma unroll
        for (int j = 0; j < 64; ++j) {
            float4 v4 = *(const float4*)&Vs[j * 64 + tx * 4];
            float vf[4] = {v4.x, v4.y, v4.z, v4.w};
            float p0 = KPs[(ty * 4 + 0) * 64 + j];
            float p1 = KPs[(ty * 4 + 1) * 64 + j];
            float p2 = KPs[(ty * 4 + 2) * 64 + j];
            float p3 = KPs[(ty * 4 + 3) * 64 + j];
            #pragma unroll
            for (int w = 0; w < 4; ++w) {
                o[0][w] += p0 * vf[w];
                o[1][w] += p1 * vf[w];
                o[2][w] += p2 * vf[w];
                o[3][w] += p3 * vf[w];
            }
        }
    }

    // Epilogue: normalize and write [B,N,C] layout
    #pragma unroll
    for (int i = 0; i < 4; ++i) {
        const float inv = 1.f / l_i[i];
        const int q = q0 + ty * 4 + i;
        float4 ov;
        ov.x = o[i][0] * inv;
        ov.y = o[i][1] * inv;
        ov.z = o[i][2] * inv;
        ov.w = o[i][3] * inv;
        *(float4*)&g_attn[((size_t)b * SEQ + q) * CDIM + h * DH + tx * 4] = ov;
    }
}

// ---------------------------------------------------------------------------
extern "C" void kernel_launch(void* const* d_in, const int* in_sizes, int n_in,
                              void* d_out, int out_size)
{
    const float* x      = (const float*)d_in[0];
    const float* qkv_w  = (const float*)d_in[1];
    const float* qkv_b  = (const float*)d_in[2];
    const float* proj_w = (const float*)d_in[3];
    const float* proj_b = (const float*)d_in[4];
    float* out = (float*)d_out;

    dim3 blk(256);

    // 1) QKV projection -> g_q/g_k/g_v  (cols: 3*768 = 36 tiles; rows: 8192 = 128 tiles)
    gemm_kernel<0><<<dim3(36, 128), blk>>>(x, qkv_w, qkv_b, nullptr);

    // 2) Flash attention -> g_attn [B,N,C]
    attn_kernel<<<dim3(SEQ / 64, HEADS, BATCH), blk>>>();

    // 3) Output projection -> d_out
    gemm_kernel<1><<<dim3(CDIM / 64, 128), blk>>>(nullptr, proj_w, proj_b, out);
}

// round 2
// speedup vs baseline: 1.2223x; 1.2223x over previous
#include <cuda_runtime.h>

#define HEADS 12
#define SEQ   2048
#define BATCH 4
#define DH    64
#define CDIM  768

// Scratch (allocation-free): Q/K/V in [B,H,N,D], attention output in [B,N,C]
__device__ float g_q[(size_t)BATCH * HEADS * SEQ * DH];
__device__ float g_k[(size_t)BATCH * HEADS * SEQ * DH];
__device__ float g_v[(size_t)BATCH * HEADS * SEQ * DH];
__device__ float g_attn[(size_t)BATCH * SEQ * CDIM];

// ---------------------------------------------------------------------------
// SGEMM: C[M, Ncols] = A[M,768] @ W[Ncols,768]^T + bias
// BM=BN=128, BK=8, 256 threads, 8x8 microtile (two 4x4 quadrants at +0/+64),
// double-buffered smem, stride 132 (conflict-free transposed stores, 16B aligned).
// MODE 0: A = x, scatter columns into g_q/g_k/g_v ([B,H,N,D] layout)
// MODE 1: A = g_attn, plain row-major output to `out`
// ---------------------------------------------------------------------------
#define KS 132   // smem row stride (words): 132*4=528 bytes, 16B aligned, 4*132%32==16

template <int MODE>
__global__ __launch_bounds__(256, 2)
void gemm_kernel(const float* __restrict__ A, const float* __restrict__ W,
                 const float* __restrict__ bias, float* __restrict__ out)
{
    __shared__ __align__(16) float As[2][8 * KS];
    __shared__ __align__(16) float Bs[2][8 * KS];

    const int bx  = blockIdx.x;           // column tile (128 cols)
    const int by  = blockIdx.y;           // row tile (128 rows)
    const int tid = threadIdx.x;
    const int tx  = tid & 15;             // 0..15
    const int ty  = tid >> 4;             // 0..15
    const int lr  = tid >> 1;             // 0..127 load row
    const int lk  = (tid & 1) * 4;        // 0 or 4

    const float* Aptr = (MODE == 0) ? A : g_attn;
    const float* Ag = Aptr + (size_t)(by * 128 + lr) * CDIM + lk;
    const float* Wg = W    + (size_t)(bx * 128 + lr) * CDIM + lk;

    // Preload tile 0
    {
        float4 av = *(const float4*)(Ag);
        float4 wv = *(const float4*)(Wg);
        As[0][(lk + 0) * KS + lr] = av.x;
        As[0][(lk + 1) * KS + lr] = av.y;
        As[0][(lk + 2) * KS + lr] = av.z;
        As[0][(lk + 3) * KS + lr] = av.w;
        Bs[0][(lk + 0) * KS + lr] = wv.x;
        Bs[0][(lk + 1) * KS + lr] = wv.y;
        Bs[0][(lk + 2) * KS + lr] = wv.z;
        Bs[0][(lk + 3) * KS + lr] = wv.w;
    }
    __syncthreads();

    float acc[8][8] = {};
    int p = 0;

    for (int k0 = 8; k0 <= CDIM; k0 += 8) {
        float4 av2, wv2;
        const bool more = (k0 < CDIM);
        if (more) {
            av2 = *(const float4*)(Ag + k0);
            wv2 = *(const float4*)(Wg + k0);
        }

        #pragma unroll
        for (int k = 0; k < 8; ++k) {
            const float* as = &As[p][k * KS];
            const float* bs = &Bs[p][k * KS];
            float4 a0 = *(const float4*)(as + ty * 4);
            float4 a1 = *(const float4*)(as + 64 + ty * 4);
            float4 b0 = *(const float4*)(bs + tx * 4);
            float4 b1 = *(const float4*)(bs + 64 + tx * 4);
            float af[8] = {a0.x, a0.y, a0.z, a0.w, a1.x, a1.y, a1.z, a1.w};
            float bf[8] = {b0.x, b0.y, b0.z, b0.w, b1.x, b1.y, b1.z, b1.w};
            #pragma unroll
            for (int i = 0; i < 8; ++i)
                #pragma unroll
                for (int j = 0; j < 8; ++j)
                    acc[i][j] += af[i] * bf[j];
        }

        if (more) {
            p ^= 1;
            As[p][(lk + 0) * KS + lr] = av2.x;
            As[p][(lk + 1) * KS + lr] = av2.y;
            As[p][(lk + 2) * KS + lr] = av2.z;
            As[p][(lk + 3) * KS + lr] = av2.w;
            Bs[p][(lk + 0) * KS + lr] = wv2.x;
            Bs[p][(lk + 1) * KS + lr] = wv2.y;
            Bs[p][(lk + 2) * KS + lr] = wv2.z;
            Bs[p][(lk + 3) * KS + lr] = wv2.w;
            __syncthreads();
        }
    }

    // Epilogue: rows {by*128 + ty*4 + i, by*128 + 64 + ty*4 + i},
    //           cols {bx*128 + tx*4 + j, bx*128 + 64 + tx*4 + j}
    #pragma unroll
    for (int cq = 0; cq < 2; ++cq) {
        const int c = bx * 128 + cq * 64 + tx * 4;
        float4 bv = *(const float4*)&bias[c];

        if (MODE == 0) {
            const int t   = c / CDIM;
            const int rem = c - t * CDIM;
            const int h   = rem >> 6;
            const int d   = rem & 63;
            float* dst = (t == 0) ? g_q : (t == 1) ? g_k : g_v;
            #pragma unroll
            for (int i = 0; i < 8; ++i) {
                const int m = by * 128 + ((i < 4) ? (ty * 4 + i) : (64 + ty * 4 + i - 4));
                const int b = m >> 11;
                const int n = m & 2047;
                float4 o;
                o.x = acc[i][cq * 4 + 0] + bv.x;
                o.y = acc[i][cq * 4 + 1] + bv.y;
                o.z = acc[i][cq * 4 + 2] + bv.z;
                o.w = acc[i][cq * 4 + 3] + bv.w;
                *(float4*)&dst[(((size_t)b * HEADS + h) * SEQ + n) * DH + d] = o;
            }
        } else {
            #pragma unroll
            for (int i = 0; i < 8; ++i) {
                const int m = by * 128 + ((i < 4) ? (ty * 4 + i) : (64 + ty * 4 + i - 4));
                float4 o;
                o.x = acc[i][cq * 4 + 0] + bv.x;
                o.y = acc[i][cq * 4 + 1] + bv.y;
                o.z = acc[i][cq * 4 + 2] + bv.z;
                o.w = acc[i][cq * 4 + 3] + bv.w;
                *(float4*)&out[(size_t)m * CDIM + c] = o;
            }
        }
    }
}

// ---------------------------------------------------------------------------
// Flash attention: one block per (64 q rows, head, batch). 128 threads,
// 8x4 microtile. fp32 online softmax. Smem exactly 48 KB:
//   Qs = Q^T [d][q] (pre-scaled), KPs = K^T [d][k] then reused as P [q][k],
//   Vs = V [k][d].
// ---------------------------------------------------------------------------
__global__ __launch_bounds__(128, 4)
void attn_kernel()
{
    __shared__ __align__(16) float Qs [64 * 64];
    __shared__ __align__(16) float KPs[64 * 64];
    __shared__ __align__(16) float Vs [64 * 64];

    const int q0 = blockIdx.x * 64;
    const int h  = blockIdx.y;
    const int b  = blockIdx.z;
    const size_t base = ((size_t)(b * HEADS + h)) * SEQ * DH;

    const int tid  = threadIdx.x;
    const int tx   = tid & 15;        // cols tx*4..+3
    const int ty   = tid >> 4;        // rows ty*8..+7
    const int lr   = tid >> 1;        // 0..63 load row
    const int half = (tid & 1) * 4;   // 0 or 4

    // Load Q tile transposed, pre-scaled by 1/sqrt(64)
    {
        const float* qg = g_q + base + (size_t)(q0 + lr) * DH + half;
        #pragma unroll
        for (int u = 0; u < 8; ++u) {
            float4 v = *(const float4*)(qg + u * 8);
            const int d0 = half + u * 8;
            Qs[(d0 + 0) * 64 + lr] = v.x * 0.125f;
            Qs[(d0 + 1) * 64 + lr] = v.y * 0.125f;
            Qs[(d0 + 2) * 64 + lr] = v.z * 0.125f;
            Qs[(d0 + 3) * 64 + lr] = v.w * 0.125f;
        }
    }

    float m_i[8], l_i[8], o[8][4];
    #pragma unroll
    for (int i = 0; i < 8; ++i) {
        m_i[i] = -1e30f;
        l_i[i] = 0.f;
        #pragma unroll
        for (int w = 0; w < 4; ++w) o[i][w] = 0.f;
    }

    for (int k0 = 0; k0 < SEQ; k0 += 64) {
        const float* kg = g_k + base + (size_t)(k0 + lr) * DH + half;
        const float* vg = g_v + base + (size_t)(k0 + lr) * DH + half;

        __syncthreads();   // previous tile fully consumed (incl. Q store on iter 0)
        #pragma unroll
        for (int u = 0; u < 8; ++u) {
            float4 kv = *(const float4*)(kg + u * 8);
            const int d0 = half + u * 8;
            KPs[(d0 + 0) * 64 + lr] = kv.x;
            KPs[(d0 + 1) * 64 + lr] = kv.y;
            KPs[(d0 + 2) * 64 + lr] = kv.z;
            KPs[(d0 + 3) * 64 + lr] = kv.w;
            *(float4*)&Vs[lr * 64 + d0] = *(const float4*)(vg + u * 8);
        }
        __syncthreads();

        // S = (Q*scale) @ K^T : 8x4 per thread
        float s[8][4] = {};
        #pragma unroll
        for (int d = 0; d < 64; ++d) {
            float4 q0v = *(const float4*)&Qs[d * 64 + ty * 8];
            float4 q1v = *(const float4*)&Qs[d * 64 + ty * 8 + 4];
            float4 kk  = *(const float4*)&KPs[d * 64 + tx * 4];
            float qf[8] = {q0v.x, q0v.y, q0v.z, q0v.w, q1v.x, q1v.y, q1v.z, q1v.w};
            float kf[4] = {kk.x, kk.y, kk.z, kk.w};
            #pragma unroll
            for (int i = 0; i < 8; ++i)
                #pragma unroll
                for (int j = 0; j < 4; ++j)
                    s[i][j] += qf[i] * kf[j];
        }

        // Online softmax (reduce across the 16-lane tx group)
        #pragma unroll
        for (int i = 0; i < 8; ++i) {
            float mx = fmaxf(fmaxf(s[i][0], s[i][1]), fmaxf(s[i][2], s[i][3]));
            #pragma unroll
            for (int off = 8; off >= 1; off >>= 1)
                mx = fmaxf(mx, __shfl_xor_sync(0xffffffffu, mx, off));
            const float mn = fmaxf(m_i[i], mx);
            const float alpha = __expf(m_i[i] - mn);
            m_i[i] = mn;
            float r = 0.f;
            #pragma unroll
            for (int j = 0; j < 4; ++j) {
                const float pv = __expf(s[i][j] - mn);
                s[i][j] = pv;
                r += pv;
            }
            #pragma unroll
            for (int off = 8; off >= 1; off >>= 1)
                r += __shfl_xor_sync(0xffffffffu, r, off);
            l_i[i] = l_i[i] * alpha + r;
            #pragma unroll
            for (int w = 0; w < 4; ++w) o[i][w] *= alpha;
        }

        __syncthreads();   // all threads done reading KPs as K
        #pragma unroll
        for (int i = 0; i < 8; ++i)
            *(float4*)&KPs[(ty * 8 + i) * 64 + tx * 4] =
                make_float4(s[i][0], s[i][1], s[i][2], s[i][3]);
        __syncthreads();

        // O += P @ V
        #pragma unroll 4
        for (int j = 0; j < 64; ++j) {
            float4 v4 = *(const float4*)&Vs[j * 64 + tx * 4];
            float vf[4] = {v4.x, v4.y, v4.z, v4.w};
            #pragma unroll
            for (int i = 0; i < 8; ++i) {
                const float pv = KPs[(ty * 8 + i) * 64 + j];
                #pragma unroll
                for (int w = 0; w < 4; ++w) o[i][w] += pv * vf[w];
            }
        }
    }

    // Epilogue: normalize, write [B,N,C]
    #pragma unroll
    for (int i = 0; i < 8; ++i) {
        const float inv = 1.f / l_i[i];
        const int q = q0 + ty * 8 + i;
        float4 ov;
        ov.x = o[i][0] * inv;
        ov.y = o[i][1] * inv;
        ov.z = o[i][2] * inv;
        ov.w = o[i][3] * inv;
        *(float4*)&g_attn[((size_t)b * SEQ + q) * CDIM + h * DH + tx * 4] = ov;
    }
}

// ---------------------------------------------------------------------------
extern "C" void kernel_launch(void* const* d_in, const int* in_sizes, int n_in,
                              void* d_out, int out_size)
{
    const float* x      = (const float*)d_in[0];
    const float* qkv_w  = (const float*)d_in[1];
    const float* qkv_b  = (const float*)d_in[2];
    const float* proj_w = (const float*)d_in[3];
    const float* proj_b = (const float*)d_in[4];
    float* out = (float*)d_out;

    // 1) QKV projection -> g_q/g_k/g_v   (N=2304 -> 18 col tiles, M=8192 -> 64 row tiles)
    gemm_kernel<0><<<dim3(18, 64), 256>>>(x, qkv_w, qkv_b, nullptr);

    // 2) Flash attention -> g_attn [B,N,C]
    attn_kernel<<<dim3(SEQ / 64, HEADS, BATCH), 128>>>();

    // 3) Output projection -> d_out   (N=768 -> 6 col tiles)
    gemm_kernel<1><<<dim3(6, 64), 256>>>(nullptr, proj_w, proj_b, out);
}

// round 4
// speedup vs baseline: 1.3007x; 1.0641x over previous
#include <cuda_runtime.h>
#include <cuda_bf16.h>
#include <cstdint>

#define HEADS 12
#define SEQ   2048
#define BATCH 4
#define DH    64
#define CDIM  768
#define MTOT  8192   // BATCH*SEQ

// ---------------- scratch (allocation-free) ----------------
__device__ float g_q[(size_t)BATCH * HEADS * SEQ * DH];
__device__ float g_k[(size_t)BATCH * HEADS * SEQ * DH];
__device__ float g_v[(size_t)BATCH * HEADS * SEQ * DH];
__device__ float g_attn[(size_t)MTOT * CDIM];
__device__ __align__(16) __nv_bfloat16 g_a_hi[(size_t)MTOT * CDIM];
__device__ __align__(16) __nv_bfloat16 g_a_lo[(size_t)MTOT * CDIM];
__device__ __align__(16) __nv_bfloat16 g_w_hi[(size_t)3 * CDIM * CDIM];
__device__ __align__(16) __nv_bfloat16 g_w_lo[(size_t)3 * CDIM * CDIM];

// ---------------- helpers ----------------
__device__ __forceinline__ uint32_t smem_u32(const void* p) {
    uint32_t a;
    asm("{ .reg .u64 t; cvta.to.shared.u64 t, %1; cvt.u32.u64 %0, t; }" : "=r"(a) : "l"(p));
    return a;
}

__device__ __forceinline__ void ldsm4(uint32_t& r0, uint32_t& r1, uint32_t& r2, uint32_t& r3,
                                      uint32_t addr) {
    asm volatile("ldmatrix.sync.aligned.m8n8.x4.shared.b16 {%0,%1,%2,%3}, [%4];"
                 : "=r"(r0), "=r"(r1), "=r"(r2), "=r"(r3) : "r"(addr));
}

__device__ __forceinline__ void mma16816(float* c, const uint32_t* a, uint32_t b0, uint32_t b1) {
    asm volatile("mma.sync.aligned.m16n8k16.row.col.f32.bf16.bf16.f32 "
                 "{%0,%1,%2,%3}, {%4,%5,%6,%7}, {%8,%9}, {%0,%1,%2,%3};"
                 : "+f"(c[0]), "+f"(c[1]), "+f"(c[2]), "+f"(c[3])
                 : "r"(a[0]), "r"(a[1]), "r"(a[2]), "r"(a[3]), "r"(b0), "r"(b1));
}

// ---------------------------------------------------------------------------
// bf16 split: hi = bf16(x), lo = bf16(x - hi)   (vectorized x4)
// ---------------------------------------------------------------------------
__global__ void split_kernel(const float4* __restrict__ src,
                             __nv_bfloat162* __restrict__ hi,
                             __nv_bfloat162* __restrict__ lo, int n4)
{
    int i = blockIdx.x * 256 + threadIdx.x;
    if (i < n4) {
        float4 v = src[i];
        __nv_bfloat16 hx = __float2bfloat16(v.x);
        __nv_bfloat16 hy = __float2bfloat16(v.y);
        __nv_bfloat16 hz = __float2bfloat16(v.z);
        __nv_bfloat16 hw = __float2bfloat16(v.w);
        hi[2 * i]     = __nv_bfloat162(hx, hy);
        hi[2 * i + 1] = __nv_bfloat162(hz, hw);
        lo[2 * i]     = __nv_bfloat162(__float2bfloat16(v.x - __bfloat162float(hx)),
                                       __float2bfloat16(v.y - __bfloat162float(hy)));
        lo[2 * i + 1] = __nv_bfloat162(__float2bfloat16(v.z - __bfloat162float(hz)),
                                       __float2bfloat16(v.w - __bfloat162float(hw)));
    }
}

// ---------------------------------------------------------------------------
// HMMA bf16x3 GEMM: C = A_hi@W_hi^T + A_lo@W_hi^T + A_hi@W_lo^T + bias
// CTA 128x128, BK=64, 256 threads (8 warps, 2m x 4n), warp tile 64x32,
// m16n8k16 mma.sync, smem stride 72 bf16 (conflict-free ldmatrix + stores),
// double-buffered with register prefetch. K loop: 36 chunks (3 segs x 768).
// MODE 0: scatter into g_q/g_k/g_v ([B,H,N,D]); MODE 1: row-major into out.
// ---------------------------------------------------------------------------
#define LDT 72
#define GEMM_SMEM (2 * 2 * 128 * LDT * 2)   // 73728 bytes

template <int MODE>
__global__ void __launch_bounds__(256)
mma_gemm(const __nv_bfloat16* __restrict__ a_hi, const __nv_bfloat16* __restrict__ a_lo,
         const __nv_bfloat16* __restrict__ w_hi, const __nv_bfloat16* __restrict__ w_lo,
         const float* __restrict__ bias, float* __restrict__ out)
{
    extern __shared__ __nv_bfloat16 sm[];
    const int tid  = threadIdx.x;
    const int lane = tid & 31;
    const int wrp  = tid >> 5;
    const int wm   = wrp & 1;         // 0..1 : 64-row half
    const int wn   = wrp >> 1;        // 0..3 : 32-col slice
    const int rowBase = blockIdx.y * 128;
    const int colBase = blockIdx.x * 128;
    const int lrow = tid >> 3;        // 0..31
    const int lch  = tid & 7;         // 0..7 (16B chunk within 64-k row)

    const int BUF = 2 * 128 * LDT;    // elems per buffer (A then B)

    // ldmatrix lane offsets
    const int a_r = lane & 15;
    const int a_k = (lane >> 4) * 8;
    const int b_r = (lane & 7) + ((lane >> 4) << 3);
    const int b_k = ((lane >> 3) & 1) * 8;

    float acc[4][4][4] = {};

    uint4 ra[4], rb[4];
    // chunk t -> (segment, k offset); segment selects hi/lo sources
    #define LOAD_GLOBAL(t)                                                           \
        do {                                                                         \
            const int _seg = (t) / 12;                                               \
            const int _kk  = ((t) - _seg * 12) * 64;                                 \
            const __nv_bfloat16* _A = (_seg == 1) ? a_lo : a_hi;                     \
            const __nv_bfloat16* _W = (_seg == 2) ? w_lo : w_hi;                     \
            _Pragma("unroll")                                                        \
            for (int it = 0; it < 4; ++it) {                                         \
                const int r = it * 32 + lrow;                                        \
                ra[it] = *(const uint4*)(_A + (size_t)(rowBase + r) * CDIM + _kk + lch * 8); \
                rb[it] = *(const uint4*)(_W + (size_t)(colBase + r) * CDIM + _kk + lch * 8); \
            }                                                                        \
        } while (0)

    #define STORE_SMEM(p)                                                            \
        do {                                                                         \
            _Pragma("unroll")                                                        \
            for (int it = 0; it < 4; ++it) {                                         \
                const int r = it * 32 + lrow;                                        \
                *(uint4*)&sm[(p) * BUF + r * LDT + lch * 8] = ra[it];                \
                *(uint4*)&sm[(p) * BUF + 128 * LDT + r * LDT + lch * 8] = rb[it];    \
            }                                                                        \
        } while (0)

    LOAD_GLOBAL(0);
    STORE_SMEM(0);
    __syncthreads();

    int p = 0;
    for (int t = 0; t < 36; ++t) {
        if (t < 35) LOAD_GLOBAL(t + 1);

        const uint32_t aBase = smem_u32(&sm[p * BUF]);
        const uint32_t bBase = smem_u32(&sm[p * BUF + 128 * LDT]);
        #pragma unroll
        for (int ks = 0; ks < 4; ++ks) {
            uint32_t af[4][4], bf2[2][4];
            #pragma unroll
            for (int mt = 0; mt < 4; ++mt) {
                const int row = wm * 64 + mt * 16 + a_r;
                const int col = ks * 16 + a_k;
                ldsm4(af[mt][0], af[mt][1], af[mt][2], af[mt][3],
                      aBase + (uint32_t)(row * LDT + col) * 2);
            }
            #pragma unroll
            for (int np2 = 0; np2 < 2; ++np2) {
                const int row = wn * 32 + np2 * 16 + b_r;
                const int col = ks * 16 + b_k;
                ldsm4(bf2[np2][0], bf2[np2][1], bf2[np2][2], bf2[np2][3],
                      bBase + (uint32_t)(row * LDT + col) * 2);
            }
            #pragma unroll
            for (int mt = 0; mt < 4; ++mt)
                #pragma unroll
                for (int nt = 0; nt < 4; ++nt)
                    mma16816(acc[mt][nt], af[mt],
                             bf2[nt >> 1][(nt & 1) * 2], bf2[nt >> 1][(nt & 1) * 2 + 1]);
        }
        __syncthreads();
        if (t < 35) {
            STORE_SMEM(p ^ 1);
            __syncthreads();
            p ^= 1;
        }
    }

    // Epilogue: c frag -> rows {base, base+8}, cols {c, c+1}
    #pragma unroll
    for (int mt = 0; mt < 4; ++mt) {
        const int r0 = rowBase + wm * 64 + mt * 16 + (lane >> 2);
        #pragma unroll
        for (int nt = 0; nt < 4; ++nt) {
            const int c = colBase + wn * 32 + nt * 8 + (lane & 3) * 2;
            const float2 bv = *(const float2*)&bias[c];
            float2 v0, v1;
            v0.x = acc[mt][nt][0] + bv.x;
            v0.y = acc[mt][nt][1] + bv.y;
            v1.x = acc[mt][nt][2] + bv.x;
            v1.y = acc[mt][nt][3] + bv.y;
            if (MODE == 0) {
                const int tsel = c / CDIM;
                const int rem  = c - tsel * CDIM;
                const int h = rem >> 6, d = c & 63;
                float* dst = (tsel == 0) ? g_q : (tsel == 1) ? g_k : g_v;
                {
                    const int m = r0, b = m >> 11, n = m & 2047;
                    *(float2*)&dst[(((size_t)b * HEADS + h) * SEQ + n) * DH + d] = v0;
                }
                {
                    const int m = r0 + 8, b = m >> 11, n = m & 2047;
                    *(float2*)&dst[(((size_t)b * HEADS + h) * SEQ + n) * DH + d] = v1;
                }
            } else {
                *(float2*)&out[(size_t)r0 * CDIM + c] = v0;
                *(float2*)&out[(size_t)(r0 + 8) * CDIM + c] = v1;
            }
        }
    }
    #undef LOAD_GLOBAL
    #undef STORE_SMEM
}

// ---------------------------------------------------------------------------
// Flash attention fp32: 128 q-rows x 128 k-cols tiles, 256 threads, 8x8 microtile.
// Dynamic smem: Qs[64][132] (Q^T, pre-scaled), KT[64][132], Vs[128][64], Ps[128][132].
// ---------------------------------------------------------------------------
#define AST 132
#define ATTN_SMEM ((64 * AST + 64 * AST + 128 * 64 + 128 * AST) * 4)

__global__ void __launch_bounds__(256)
attn_kernel()
{
    extern __shared__ float afs[];
    float* Qs = afs;                 // [64][132]
    float* KT = Qs + 64 * AST;       // [64][132]
    float* Vs = KT + 64 * AST;       // [128][64]
    float* Ps = Vs + 128 * 64;       // [128][132]

    const int q0 = blockIdx.x * 128;
    const int h  = blockIdx.y;
    const int b  = blockIdx.z;
    const size_t base = ((size_t)(b * HEADS + h)) * SEQ * DH;

    const int tid = threadIdx.x;
    const int tx  = tid & 15;
    const int ty  = tid >> 4;
    const int lr  = tid >> 1;        // 0..127
    const int hf  = (tid & 1) * 32;  // d offset 0/32

    {
        const float* qg = g_q + base + (size_t)(q0 + lr) * DH + hf;
        #pragma unroll
        for (int u = 0; u < 8; ++u) {
            float4 v = *(const float4*)(qg + u * 4);
            const int d0 = hf + u * 4;
            Qs[(d0 + 0) * AST + lr] = v.x * 0.125f;
            Qs[(d0 + 1) * AST + lr] = v.y * 0.125f;
            Qs[(d0 + 2) * AST + lr] = v.z * 0.125f;
            Qs[(d0 + 3) * AST + lr] = v.w * 0.125f;
        }
    }

    float m_i[8], l_i[8], o[8][4];
    #pragma unroll
    for (int i = 0; i < 8; ++i) {
        m_i[i] = -1e30f; l_i[i] = 0.f;
        #pragma unroll
        for (int w = 0; w < 4; ++w) o[i][w] = 0.f;
    }

    for (int k0 = 0; k0 < SEQ; k0 += 128) {
        __syncthreads();
        {
            const float* kg = g_k + base + (size_t)(k0 + lr) * DH + hf;
            const float* vg = g_v + base + (size_t)(k0 + lr) * DH + hf;
            #pragma unroll
            for (int u = 0; u < 8; ++u) {
                float4 kv = *(const float4*)(kg + u * 4);
                const int d0 = hf + u * 4;
                KT[(d0 + 0) * AST + lr] = kv.x;
                KT[(d0 + 1) * AST + lr] = kv.y;
                KT[(d0 + 2) * AST + lr] = kv.z;
                KT[(d0 + 3) * AST + lr] = kv.w;
                *(float4*)&Vs[lr * 64 + d0] = *(const float4*)(vg + u * 4);
            }
        }
        __syncthreads();

        float s[8][8] = {};
        #pragma unroll
        for (int d = 0; d < 64; ++d) {
            float4 qa = *(const float4*)&Qs[d * AST + ty * 8];
            float4 qb = *(const float4*)&Qs[d * AST + ty * 8 + 4];
            float4 ka = *(const float4*)&KT[d * AST + tx * 8];
            float4 kb = *(const float4*)&KT[d * AST + tx * 8 + 4];
            float qf[8] = {qa.x, qa.y, qa.z, qa.w, qb.x, qb.y, qb.z, qb.w};
            float kf[8] = {ka.x, ka.y, ka.z, ka.w, kb.x, kb.y, kb.z, kb.w};
            #pragma unroll
            for (int i = 0; i < 8; ++i)
                #pragma unroll
                for (int j = 0; j < 8; ++j)
                    s[i][j] += qf[i] * kf[j];
        }

        #pragma unroll
        for (int i = 0; i < 8; ++i) {
            float mx = s[i][0];
            #pragma unroll
            for (int j = 1; j < 8; ++j) mx = fmaxf(mx, s[i][j]);
            #pragma unroll
            for (int off = 8; off >= 1; off >>= 1)
                mx = fmaxf(mx, __shfl_xor_sync(0xffffffffu, mx, off));
            const float mn = fmaxf(m_i[i], mx);
            const float alpha = __expf(m_i[i] - mn);
            m_i[i] = mn;
            float r = 0.f;
            #pragma unroll
            for (int j = 0; j < 8; ++j) {
                const float pv = __expf(s[i][j] - mn);
                s[i][j] = pv;
                r += pv;
            }
            #pragma unroll
            for (int off = 8; off >= 1; off >>= 1)
                r += __shfl_xor_sync(0xffffffffu, r, off);
            l_i[i] = l_i[i] * alpha + r;
            #pragma unroll
            for (int w = 0; w < 4; ++w) o[i][w] *= alpha;
        }

        #pragma unroll
        for (int i = 0; i < 8; ++i) {
            *(float4*)&Ps[(ty * 8 + i) * AST + tx * 8]     = make_float4(s[i][0], s[i][1], s[i][2], s[i][3]);
            *(float4*)&Ps[(ty * 8 + i) * AST + tx * 8 + 4] = make_float4(s[i][4], s[i][5], s[i][6], s[i][7]);
        }
        __syncthreads();

        #pragma unroll 2
        for (int j = 0; j < 128; j += 4) {
            float4 v0 = *(const float4*)&Vs[(j + 0) * 64 + tx * 4];
            float4 v1 = *(const float4*)&Vs[(j + 1) * 64 + tx * 4];
            float4 v2 = *(const float4*)&Vs[(j + 2) * 64 + tx * 4];
            float4 v3 = *(const float4*)&Vs[(j + 3) * 64 + tx * 4];
            #pragma unroll
            for (int i = 0; i < 8; ++i) {
                float4 pv = *(const float4*)&Ps[(ty * 8 + i) * AST + j];
                o[i][0] += pv.x * v0.x + pv.y * v1.x + pv.z * v2.x + pv.w * v3.x;
                o[i][1] += pv.x * v0.y + pv.y * v1.y + pv.z * v2.y + pv.w * v3.y;
                o[i][2] += pv.x * v0.z + pv.y * v1.z + pv.z * v2.z + pv.w * v3.z;
                o[i][3] += pv.x * v0.w + pv.y * v1.w + pv.z * v2.w + pv.w * v3.w;
            }
        }
    }

    #pragma unroll
    for (int i = 0; i < 8; ++i) {
        const float inv = 1.f / l_i[i];
        const int q = q0 + ty * 8 + i;
        float4 ov;
        ov.x = o[i][0] * inv;
        ov.y = o[i][1] * inv;
        ov.z = o[i][2] * inv;
        ov.w = o[i][3] * inv;
        *(float4*)&g_attn[((size_t)b * SEQ + q) * CDIM + h * DH + tx * 4] = ov;
    }
}

// ---------------------------------------------------------------------------
extern "C" void kernel_launch(void* const* d_in, const int* in_sizes, int n_in,
                              void* d_out, int out_size)
{
    const float* x      = (const float*)d_in[0];
    const float* qkv_w  = (const float*)d_in[1];
    const float* qkv_b  = (const float*)d_in[2];
    const float* proj_w = (const float*)d_in[3];
    const float* proj_b = (const float*)d_in[4];
    float* out = (float*)d_out;

    cudaFuncSetAttribute(mma_gemm<0>, cudaFuncAttributeMaxDynamicSharedMemorySize, GEMM_SMEM);
    cudaFuncSetAttribute(mma_gemm<1>, cudaFuncAttributeMaxDynamicSharedMemorySize, GEMM_SMEM);
    cudaFuncSetAttribute(attn_kernel, cudaFuncAttributeMaxDynamicSharedMemorySize, ATTN_SMEM);

    __nv_bfloat16 *a_hi, *a_lo, *w_hi, *w_lo;
    cudaGetSymbolAddress((void**)&a_hi, g_a_hi);
    cudaGetSymbolAddress((void**)&a_lo, g_a_lo);
    cudaGetSymbolAddress((void**)&w_hi, g_w_hi);
    cudaGetSymbolAddress((void**)&w_lo, g_w_lo);
    float* attn_ptr;
    cudaGetSymbolAddress((void**)&attn_ptr, g_attn);

    const int nx4 = MTOT * CDIM / 4;       // 1572864
    const int nw4 = 3 * CDIM * CDIM / 4;   // 442368
    const int np4 = CDIM * CDIM / 4;       // 147456

    // 1) split x and qkv_w into bf16 hi/lo
    split_kernel<<<(nx4 + 255) / 256, 256>>>((const float4*)x,
        (__nv_bfloat162*)a_hi, (__nv_bfloat162*)a_lo, nx4);
    split_kernel<<<(nw4 + 255) / 256, 256>>>((const float4*)qkv_w,
        (__nv_bfloat162*)w_hi, (__nv_bfloat162*)w_lo, nw4);

    // 2) QKV projection (HMMA bf16x3) -> g_q/g_k/g_v
    mma_gemm<0><<<dim3(18, 64), 256, GEMM_SMEM>>>(a_hi, a_lo, w_hi, w_lo, qkv_b, nullptr);

    // 3) Flash attention -> g_attn [B,N,C]
    attn_kernel<<<dim3(SEQ / 128, HEADS, BATCH), 256, ATTN_SMEM>>>();

    // 4) split g_attn and proj_w
    split_kernel<<<(nx4 + 255) / 256, 256>>>((const float4*)attn_ptr,
        (__nv_bfloat162*)a_hi, (__nv_bfloat162*)a_lo, nx4);
    split_kernel<<<(np4 + 255) / 256, 256>>>((const float4*)proj_w,
        (__nv_bfloat162*)w_hi, (__nv_bfloat162*)w_lo, np4);

    // 5) Output projection (HMMA bf16x3) -> d_out
    mma_gemm<1><<<dim3(6, 64), 256, GEMM_SMEM>>>(a_hi, a_lo, w_hi, w_lo, proj_b, out);
}

// round 5
// speedup vs baseline: 2.1401x; 1.6454x over previous
#include <cuda_runtime.h>
#include <cuda_bf16.h>
#include <cstdint>

#define HEADS 12
#define SEQ   2048
#define BATCH 4
#define DH    64
#define CDIM  768
#define MTOT  8192   // BATCH*SEQ

// ---------------- scratch (allocation-free) ----------------
__device__ float g_q[(size_t)BATCH * HEADS * SEQ * DH];
__device__ float g_k[(size_t)BATCH * HEADS * SEQ * DH];
__device__ float g_v[(size_t)BATCH * HEADS * SEQ * DH];
__device__ float g_attn[(size_t)MTOT * CDIM];
__device__ __align__(16) __nv_bfloat16 g_a_hi[(size_t)MTOT * CDIM];
__device__ __align__(16) __nv_bfloat16 g_a_lo[(size_t)MTOT * CDIM];
__device__ __align__(16) __nv_bfloat16 g_w_hi[(size_t)3 * CDIM * CDIM];
__device__ __align__(16) __nv_bfloat16 g_w_lo[(size_t)3 * CDIM * CDIM];

// ---------------- helpers ----------------
__device__ __forceinline__ uint32_t smem_u32(const void* p) {
    uint32_t a;
    asm("{ .reg .u64 t; cvta.to.shared.u64 t, %1; cvt.u32.u64 %0, t; }" : "=r"(a) : "l"(p));
    return a;
}

__device__ __forceinline__ void ldsm4(uint32_t& r0, uint32_t& r1, uint32_t& r2, uint32_t& r3,
                                      uint32_t addr) {
    asm volatile("ldmatrix.sync.aligned.m8n8.x4.shared.b16 {%0,%1,%2,%3}, [%4];"
                 : "=r"(r0), "=r"(r1), "=r"(r2), "=r"(r3) : "r"(addr));
}

__device__ __forceinline__ void mma16816(float* c, const uint32_t* a, uint32_t b0, uint32_t b1) {
    asm volatile("mma.sync.aligned.m16n8k16.row.col.f32.bf16.bf16.f32 "
                 "{%0,%1,%2,%3}, {%4,%5,%6,%7}, {%8,%9}, {%0,%1,%2,%3};"
                 : "+f"(c[0]), "+f"(c[1]), "+f"(c[2]), "+f"(c[3])
                 : "r"(a[0]), "r"(a[1]), "r"(a[2]), "r"(a[3]), "r"(b0), "r"(b1));
}

// ---------------------------------------------------------------------------
// bf16 split: hi = bf16(x), lo = bf16(x - hi)   (vectorized x4)
// ---------------------------------------------------------------------------
__global__ void split_kernel(const float4* __restrict__ src,
                             __nv_bfloat162* __restrict__ hi,
                             __nv_bfloat162* __restrict__ lo, int n4)
{
    int i = blockIdx.x * 256 + threadIdx.x;
    if (i < n4) {
        float4 v = src[i];
        __nv_bfloat16 hx = __float2bfloat16(v.x);
        __nv_bfloat16 hy = __float2bfloat16(v.y);
        __nv_bfloat16 hz = __float2bfloat16(v.z);
        __nv_bfloat16 hw = __float2bfloat16(v.w);
        hi[2 * i]     = __nv_bfloat162(hx, hy);
        hi[2 * i + 1] = __nv_bfloat162(hz, hw);
        lo[2 * i]     = __nv_bfloat162(__float2bfloat16(v.x - __bfloat162float(hx)),
                                       __float2bfloat16(v.y - __bfloat162float(hy)));
        lo[2 * i + 1] = __nv_bfloat162(__float2bfloat16(v.z - __bfloat162float(hz)),
                                       __float2bfloat16(v.w - __bfloat162float(hw)));
    }
}

// ---------------------------------------------------------------------------
// HMMA bf16x3 GEMM (unchanged from round 4): C = Ahi@Whi^T + Alo@Whi^T + Ahi@Wlo^T + bias
// ---------------------------------------------------------------------------
#define LDT 72
#define GEMM_SMEM (2 * 2 * 128 * LDT * 2)   // 73728 bytes

template <int MODE>
__global__ void __launch_bounds__(256)
mma_gemm(const __nv_bfloat16* __restrict__ a_hi, const __nv_bfloat16* __restrict__ a_lo,
         const __nv_bfloat16* __restrict__ w_hi, const __nv_bfloat16* __restrict__ w_lo,
         const float* __restrict__ bias, float* __restrict__ out)
{
    extern __shared__ __nv_bfloat16 sm[];
    const int tid  = threadIdx.x;
    const int lane = tid & 31;
    const int wrp  = tid >> 5;
    const int wm   = wrp & 1;
    const int wn   = wrp >> 1;
    const int rowBase = blockIdx.y * 128;
    const int colBase = blockIdx.x * 128;
    const int lrow = tid >> 3;
    const int lch  = tid & 7;

    const int BUF = 2 * 128 * LDT;

    const int a_r = lane & 15;
    const int a_k = (lane >> 4) * 8;
    const int b_r = (lane & 7) + ((lane >> 4) << 3);
    const int b_k = ((lane >> 3) & 1) * 8;

    float acc[4][4][4] = {};

    uint4 ra[4], rb[4];
    #define LOAD_GLOBAL(t)                                                           \
        do {                                                                         \
            const int _seg = (t) / 12;                                               \
            const int _kk  = ((t) - _seg * 12) * 64;                                 \
            const __nv_bfloat16* _A = (_seg == 1) ? a_lo : a_hi;                     \
            const __nv_bfloat16* _W = (_seg == 2) ? w_lo : w_hi;                     \
            _Pragma("unroll")                                                        \
            for (int it = 0; it < 4; ++it) {                                         \
                const int r = it * 32 + lrow;                                        \
                ra[it] = *(const uint4*)(_A + (size_t)(rowBase + r) * CDIM + _kk + lch * 8); \
                rb[it] = *(const uint4*)(_W + (size_t)(colBase + r) * CDIM + _kk + lch * 8); \
            }                                                                        \
        } while (0)

    #define STORE_SMEM(p)                                                            \
        do {                                                                         \
            _Pragma("unroll")                                                        \
            for (int it = 0; it < 4; ++it) {                                         \
                const int r = it * 32 + lrow;                                        \
                *(uint4*)&sm[(p) * BUF + r * LDT + lch * 8] = ra[it];                \
                *(uint4*)&sm[(p) * BUF + 128 * LDT + r * LDT + lch * 8] = rb[it];    \
            }                                                                        \
        } while (0)

    LOAD_GLOBAL(0);
    STORE_SMEM(0);
    __syncthreads();

    int p = 0;
    for (int t = 0; t < 36; ++t) {
        if (t < 35) LOAD_GLOBAL(t + 1);

        const uint32_t aBase = smem_u32(&sm[p * BUF]);
        const uint32_t bBase = smem_u32(&sm[p * BUF + 128 * LDT]);
        #pragma unroll
        for (int ks = 0; ks < 4; ++ks) {
            uint32_t af[4][4], bf2[2][4];
            #pragma unroll
            for (int mt = 0; mt < 4; ++mt) {
                const int row = wm * 64 + mt * 16 + a_r;
                const int col = ks * 16 + a_k;
                ldsm4(af[mt][0], af[mt][1], af[mt][2], af[mt][3],
                      aBase + (uint32_t)(row * LDT + col) * 2);
            }
            #pragma unroll
            for (int np2 = 0; np2 < 2; ++np2) {
                const int row = wn * 32 + np2 * 16 + b_r;
                const int col = ks * 16 + b_k;
                ldsm4(bf2[np2][0], bf2[np2][1], bf2[np2][2], bf2[np2][3],
                      bBase + (uint32_t)(row * LDT + col) * 2);
            }
            #pragma unroll
            for (int mt = 0; mt < 4; ++mt)
                #pragma unroll
                for (int nt = 0; nt < 4; ++nt)
                    mma16816(acc[mt][nt], af[mt],
                             bf2[nt >> 1][(nt & 1) * 2], bf2[nt >> 1][(nt & 1) * 2 + 1]);
        }
        __syncthreads();
        if (t < 35) {
            STORE_SMEM(p ^ 1);
            __syncthreads();
            p ^= 1;
        }
    }

    #pragma unroll
    for (int mt = 0; mt < 4; ++mt) {
        const int r0 = rowBase + wm * 64 + mt * 16 + (lane >> 2);
        #pragma unroll
        for (int nt = 0; nt < 4; ++nt) {
            const int c = colBase + wn * 32 + nt * 8 + (lane & 3) * 2;
            const float2 bv = *(const float2*)&bias[c];
            float2 v0, v1;
            v0.x = acc[mt][nt][0] + bv.x;
            v0.y = acc[mt][nt][1] + bv.y;
            v1.x = acc[mt][nt][2] + bv.x;
            v1.y = acc[mt][nt][3] + bv.y;
            if (MODE == 0) {
                const int tsel = c / CDIM;
                const int rem  = c - tsel * CDIM;
                const int h = rem >> 6, d = c & 63;
                float* dst = (tsel == 0) ? g_q : (tsel == 1) ? g_k : g_v;
                {
                    const int m = r0, b = m >> 11, n = m & 2047;
                    *(float2*)&dst[(((size_t)b * HEADS + h) * SEQ + n) * DH + d] = v0;
                }
                {
                    const int m = r0 + 8, b = m >> 11, n = m & 2047;
                    *(float2*)&dst[(((size_t)b * HEADS + h) * SEQ + n) * DH + d] = v1;
                }
            } else {
                *(float2*)&out[(size_t)r0 * CDIM + c] = v0;
                *(float2*)&out[(size_t)(r0 + 8) * CDIM + c] = v1;
            }
        }
    }
    #undef LOAD_GLOBAL
    #undef STORE_SMEM
}

// ---------------------------------------------------------------------------
// HMMA flash attention: 128 q-rows x 128 k-cols per tile, 8 warps (16 rows each).
// S = QK^T via bf16x3 (Qhi*Khi + Qlo*Khi + Qhi*Klo); softmax warp-local;
// PV via bf16x3 (Phi*Vhi + Phi*Vlo + Plo*Vhi) with per-warp P buffer reuse.
// Smem (bf16): Qhi/Qlo[128][72], Khi/Klo[128][72], VThi/VTlo[64][136], P[128][136]
// ---------------------------------------------------------------------------
#define QLD 72
#define PLD 136
#define OQHI 0
#define OQLO (128 * QLD)
#define OKHI (2 * 128 * QLD)
#define OKLO (3 * 128 * QLD)
#define OVHI (4 * 128 * QLD)
#define OVLO (OVHI + 64 * PLD)
#define OPBUF (OVLO + 64 * PLD)
#define ATTN_SMEM ((OPBUF + 128 * PLD) * 2)   // 143360 bytes

__global__ void __launch_bounds__(256)
attn_kernel()
{
    extern __shared__ __nv_bfloat16 sm[];

    const int q0 = blockIdx.x * 128;
    const int h  = blockIdx.y;
    const int b  = blockIdx.z;
    const size_t base = ((size_t)(b * HEADS + h)) * SEQ * DH;

    const int tid  = threadIdx.x;
    const int lane = tid & 31;
    const int wrp  = tid >> 5;
    const int wq   = wrp * 16;          // warp's q-row base within tile
    const int lrow = tid >> 1;          // 0..127 (tile load row)
    const int hf   = (tid & 1) * 32;    // d offset 0/32

    const int a_r = lane & 15;
    const int a_k = (lane >> 4) * 8;
    const int b_r = (lane & 7) + ((lane >> 4) << 3);
    const int b_k = ((lane >> 3) & 1) * 8;
    const int qr  = lane >> 2;          // quad row 0..7
    const int qc  = (lane & 3) * 2;     // quad col 0,2,4,6

    const uint32_t smb = smem_u32(sm);

    // ---- load Q tile once: prescale 0.125, split hi/lo, store [q][d] ----
    {
        const float* qg = g_q + base + (size_t)(q0 + lrow) * DH + hf;
        #pragma unroll
        for (int u = 0; u < 8; ++u) {
            float4 v = *(const float4*)(qg + u * 4);
            v.x *= 0.125f; v.y *= 0.125f; v.z *= 0.125f; v.w *= 0.125f;
            __nv_bfloat16 hx = __float2bfloat16(v.x), hy = __float2bfloat16(v.y);
            __nv_bfloat16 hz = __float2bfloat16(v.z), hw = __float2bfloat16(v.w);
            const int d0 = hf + u * 4;
            *(__nv_bfloat162*)&sm[OQHI + lrow * QLD + d0]     = __nv_bfloat162(hx, hy);
            *(__nv_bfloat162*)&sm[OQHI + lrow * QLD + d0 + 2] = __nv_bfloat162(hz, hw);
            *(__nv_bfloat162*)&sm[OQLO + lrow * QLD + d0] =
                __nv_bfloat162(__float2bfloat16(v.x - __bfloat162float(hx)),
                               __float2bfloat16(v.y - __bfloat162float(hy)));
            *(__nv_bfloat162*)&sm[OQLO + lrow * QLD + d0 + 2] =
                __nv_bfloat162(__float2bfloat16(v.z - __bfloat162float(hz)),
                               __float2bfloat16(v.w - __bfloat162float(hw)));
        }
    }

    float m_i[2] = {-1e30f, -1e30f};
    float l_i[2] = {0.f, 0.f};
    float oacc[8][4] = {};

    for (int k0 = 0; k0 < SEQ; k0 += 128) {
        __syncthreads();   // everyone done with previous K/VT (and Q visible on iter 0)

        // ---- load K tile [k][d] hi/lo and V transposed [d][k] hi/lo ----
        {
            const float* kg = g_k + base + (size_t)(k0 + lrow) * DH + hf;
            const float* vg = g_v + base + (size_t)(k0 + lrow) * DH + hf;
            #pragma unroll
            for (int u = 0; u < 8; ++u) {
                const int d0 = hf + u * 4;
                float4 kv = *(const float4*)(kg + u * 4);
                __nv_bfloat16 hx = __float2bfloat16(kv.x), hy = __float2bfloat16(kv.y);
                __nv_bfloat16 hz = __float2bfloat16(kv.z), hw = __float2bfloat16(kv.w);
                *(__nv_bfloat162*)&sm[OKHI + lrow * QLD + d0]     = __nv_bfloat162(hx, hy);
                *(__nv_bfloat162*)&sm[OKHI + lrow * QLD + d0 + 2] = __nv_bfloat162(hz, hw);
                *(__nv_bfloat162*)&sm[OKLO + lrow * QLD + d0] =
                    __nv_bfloat162(__float2bfloat16(kv.x - __bfloat162float(hx)),
                                   __float2bfloat16(kv.y - __bfloat162float(hy)));
                *(__nv_bfloat162*)&sm[OKLO + lrow * QLD + d0 + 2] =
                    __nv_bfloat162(__float2bfloat16(kv.z - __bfloat162float(hz)),
                                   __float2bfloat16(kv.w - __bfloat162float(hw)));

                float4 vv = *(const float4*)(vg + u * 4);
                __nv_bfloat16 vx = __float2bfloat16(vv.x), vy = __float2bfloat16(vv.y);
                __nv_bfloat16 vz = __float2bfloat16(vv.z), vw = __float2bfloat16(vv.w);
                sm[OVHI + (d0 + 0) * PLD + lrow] = vx;
                sm[OVHI + (d0 + 1) * PLD + lrow] = vy;
                sm[OVHI + (d0 + 2) * PLD + lrow] = vz;
                sm[OVHI + (d0 + 3) * PLD + lrow] = vw;
                sm[OVLO + (d0 + 0) * PLD + lrow] = __float2bfloat16(vv.x - __bfloat162float(vx));
                sm[OVLO + (d0 + 1) * PLD + lrow] = __float2bfloat16(vv.y - __bfloat162float(vy));
                sm[OVLO + (d0 + 2) * PLD + lrow] = __float2bfloat16(vv.z - __bfloat162float(vz));
                sm[OVLO + (d0 + 3) * PLD + lrow] = __float2bfloat16(vv.w - __bfloat162float(vw));
            }
        }
        __syncthreads();

        // ---- S = QK^T : 16 rows x 128 cols per warp, 3 error-comp passes ----
        float sacc[16][4] = {};
        #pragma unroll
        for (int pass = 0; pass < 3; ++pass) {
            const uint32_t qBase = smb + ((pass == 1) ? OQLO : OQHI) * 2;
            const uint32_t kBase = smb + ((pass == 2) ? OKLO : OKHI) * 2;
            #pragma unroll
            for (int ks = 0; ks < 4; ++ks) {
                uint32_t af[4];
                ldsm4(af[0], af[1], af[2], af[3],
                      qBase + (uint32_t)((wq + a_r) * QLD + ks * 16 + a_k) * 2);
                #pragma unroll
                for (int ng = 0; ng < 8; ++ng) {
                    uint32_t bf[4];
                    ldsm4(bf[0], bf[1], bf[2], bf[3],
                          kBase + (uint32_t)((ng * 16 + b_r) * QLD + ks * 16 + b_k) * 2);
                    mma16816(sacc[ng * 2 + 0], af, bf[0], bf[1]);
                    mma16816(sacc[ng * 2 + 1], af, bf[2], bf[3]);
                }
            }
        }

        // ---- online softmax: rows qr and qr+8 (warp-local) ----
        #pragma unroll
        for (int ri = 0; ri < 2; ++ri) {
            float mx = -1e30f;
            #pragma unroll
            for (int nt = 0; nt < 16; ++nt) {
                mx = fmaxf(mx, sacc[nt][ri * 2 + 0]);
                mx = fmaxf(mx, sacc[nt][ri * 2 + 1]);
            }
            mx = fmaxf(mx, __shfl_xor_sync(0xffffffffu, mx, 1));
            mx = fmaxf(mx, __shfl_xor_sync(0xffffffffu, mx, 2));
            const float mn = fmaxf(m_i[ri], mx);
            const float alpha = __expf(m_i[ri] - mn);
            m_i[ri] = mn;
            float r = 0.f;
            #pragma unroll
            for (int nt = 0; nt < 16; ++nt) {
                float p0 = __expf(sacc[nt][ri * 2 + 0] - mn);
                float p1 = __expf(sacc[nt][ri * 2 + 1] - mn);
                sacc[nt][ri * 2 + 0] = p0;
                sacc[nt][ri * 2 + 1] = p1;
                r += p0 + p1;
            }
            r += __shfl_xor_sync(0xffffffffu, r, 1);
            r += __shfl_xor_sync(0xffffffffu, r, 2);
            l_i[ri] = l_i[ri] * alpha + r;
            #pragma unroll
            for (int nt = 0; nt < 8; ++nt) {
                oacc[nt][ri * 2 + 0] *= alpha;
                oacc[nt][ri * 2 + 1] *= alpha;
            }
        }

        // ---- P hi -> smem (warp-local rows) ----
        #pragma unroll
        for (int nt = 0; nt < 16; ++nt) {
            const int col = nt * 8 + qc;
            *(__nv_bfloat162*)&sm[OPBUF + (wq + qr) * PLD + col] =
                __nv_bfloat162(__float2bfloat16(sacc[nt][0]), __float2bfloat16(sacc[nt][1]));
            *(__nv_bfloat162*)&sm[OPBUF + (wq + qr + 8) * PLD + col] =
                __nv_bfloat162(__float2bfloat16(sacc[nt][2]), __float2bfloat16(sacc[nt][3]));
        }
        __syncwarp();

        // ---- O += Phi@Vhi + Phi@Vlo ----
        #pragma unroll
        for (int pass = 0; pass < 2; ++pass) {
            const uint32_t vBase = smb + ((pass == 0) ? OVHI : OVLO) * 2;
            const uint32_t pBase = smb + OPBUF * 2;
            #pragma unroll
            for (int ks = 0; ks < 8; ++ks) {
                uint32_t af[4];
                ldsm4(af[0], af[1], af[2], af[3],
                      pBase + (uint32_t)((wq + a_r) * PLD + ks * 16 + a_k) * 2);
                #pragma unroll
                for (int ng = 0; ng < 4; ++ng) {
                    uint32_t bf[4];
                    ldsm4(bf[0], bf[1], bf[2], bf[3],
                          vBase + (uint32_t)((ng * 16 + b_r) * PLD + ks * 16 + b_k) * 2);
                    mma16816(oacc[ng * 2 + 0], af, bf[0], bf[1]);
                    mma16816(oacc[ng * 2 + 1], af, bf[2], bf[3]);
                }
            }
        }
        __syncwarp();

        // ---- P lo -> smem, O += Plo@Vhi ----
        #pragma unroll
        for (int nt = 0; nt < 16; ++nt) {
            const int col = nt * 8 + qc;
            float p0 = sacc[nt][0], p1 = sacc[nt][1], p2 = sacc[nt][2], p3 = sacc[nt][3];
            __nv_bfloat16 h0 = __float2bfloat16(p0), h1 = __float2bfloat16(p1);
            __nv_bfloat16 h2 = __float2bfloat16(p2), h3 = __float2bfloat16(p3);
            *(__nv_bfloat162*)&sm[OPBUF + (wq + qr) * PLD + col] =
                __nv_bfloat162(__float2bfloat16(p0 - __bfloat162float(h0)),
                               __float2bfloat16(p1 - __bfloat162float(h1)));
            *(__nv_bfloat162*)&sm[OPBUF + (wq + qr + 8) * PLD + col] =
                __nv_bfloat162(__float2bfloat16(p2 - __bfloat162float(h2)),
                               __float2bfloat16(p3 - __bfloat162float(h3)));
        }
        __syncwarp();
        {
            const uint32_t vBase = smb + OVHI * 2;
            const uint32_t pBase = smb + OPBUF * 2;
            #pragma unroll
            for (int ks = 0; ks < 8; ++ks) {
                uint32_t af[4];
                ldsm4(af[0], af[1], af[2], af[3],
                      pBase + (uint32_t)((wq + a_r) * PLD + ks * 16 + a_k) * 2);
                #pragma unroll
                for (int ng = 0; ng < 4; ++ng) {
                    uint32_t bf[4];
                    ldsm4(bf[0], bf[1], bf[2], bf[3],
                          vBase + (uint32_t)((ng * 16 + b_r) * PLD + ks * 16 + b_k) * 2);
                    mma16816(oacc[ng * 2 + 0], af, bf[0], bf[1]);
                    mma16816(oacc[ng * 2 + 1], af, bf[2], bf[3]);
                }
            }
        }
    }

    // ---- epilogue: normalize, write [B,N,C] ----
    const float inv0 = 1.f / l_i[0];
    const float inv1 = 1.f / l_i[1];
    const int row0 = q0 + wq + qr;
    #pragma unroll
    for (int nt = 0; nt < 8; ++nt) {
        const int col = h * DH + nt * 8 + qc;
        float2 v0, v1;
        v0.x = oacc[nt][0] * inv0;
        v0.y = oacc[nt][1] * inv0;
        v1.x = oacc[nt][2] * inv1;
        v1.y = oacc[nt][3] * inv1;
        *(float2*)&g_attn[((size_t)b * SEQ + row0) * CDIM + col] = v0;
        *(float2*)&g_attn[((size_t)b * SEQ + row0 + 8) * CDIM + col] = v1;
    }
}

// ---------------------------------------------------------------------------
extern "C" void kernel_launch(void* const* d_in, const int* in_sizes, int n_in,
                              void* d_out, int out_size)
{
    const float* x      = (const float*)d_in[0];
    const float* qkv_w  = (const float*)d_in[1];
    const float* qkv_b  = (const float*)d_in[2];
    const float* proj_w = (const float*)d_in[3];
    const float* proj_b = (const float*)d_in[4];
    float* out = (float*)d_out;

    cudaFuncSetAttribute(mma_gemm<0>, cudaFuncAttributeMaxDynamicSharedMemorySize, GEMM_SMEM);
    cudaFuncSetAttribute(mma_gemm<1>, cudaFuncAttributeMaxDynamicSharedMemorySize, GEMM_SMEM);
    cudaFuncSetAttribute(attn_kernel, cudaFuncAttributeMaxDynamicSharedMemorySize, ATTN_SMEM);

    __nv_bfloat16 *a_hi, *a_lo, *w_hi, *w_lo;
    cudaGetSymbolAddress((void**)&a_hi, g_a_hi);
    cudaGetSymbolAddress((void**)&a_lo, g_a_lo);
    cudaGetSymbolAddress((void**)&w_hi, g_w_hi);
    cudaGetSymbolAddress((void**)&w_lo, g_w_lo);
    float* attn_ptr;
    cudaGetSymbolAddress((void**)&attn_ptr, g_attn);

    const int nx4 = MTOT * CDIM / 4;
    const int nw4 = 3 * CDIM * CDIM / 4;
    const int np4 = CDIM * CDIM / 4;

    split_kernel<<<(nx4 + 255) / 256, 256>>>((const float4*)x,
        (__nv_bfloat162*)a_hi, (__nv_bfloat162*)a_lo, nx4);
    split_kernel<<<(nw4 + 255) / 256, 256>>>((const float4*)qkv_w,
        (__nv_bfloat162*)w_hi, (__nv_bfloat162*)w_lo, nw4);

    mma_gemm<0><<<dim3(18, 64), 256, GEMM_SMEM>>>(a_hi, a_lo, w_hi, w_lo, qkv_b, nullptr);

    attn_kernel<<<dim3(SEQ / 128, HEADS, BATCH), 256, ATTN_SMEM>>>();

    split_kernel<<<(nx4 + 255) / 256, 256>>>((const float4*)attn_ptr,
        (__nv_bfloat162*)a_hi, (__nv_bfloat162*)a_lo, nx4);
    split_kernel<<<(np4 + 255) / 256, 256>>>((const float4*)proj_w,
        (__nv_bfloat162*)w_hi, (__nv_bfloat162*)w_lo, np4);

    mma_gemm<1><<<dim3(6, 64), 256, GEMM_SMEM>>>(a_hi, a_lo, w_hi, w_lo, proj_b, out);
}

// round 6
// speedup vs baseline: 2.7866x; 1.3021x over previous
#include <cuda_runtime.h>
#include <cuda_bf16.h>
#include <cstdint>

#define HEADS 12
#define SEQ   2048
#define BATCH 4
#define DH    64
#define CDIM  768
#define MTOT  8192   // BATCH*SEQ
#define NQKV ((size_t)BATCH * HEADS * SEQ * DH)

// ---------------- scratch (allocation-free) ----------------
// Q (prescaled), K in [B,H,N,D]; V transposed in [B,H,D,N]; all bf16 hi/lo
__device__ __align__(16) __nv_bfloat16 g_qhi[NQKV], g_qlo[NQKV];
__device__ __align__(16) __nv_bfloat16 g_khi[NQKV], g_klo[NQKV];
__device__ __align__(16) __nv_bfloat16 g_vthi[NQKV], g_vtlo[NQKV];
// activation hi/lo (x split, then attn output split), weight hi/lo
__device__ __align__(16) __nv_bfloat16 g_a_hi[(size_t)MTOT * CDIM];
__device__ __align__(16) __nv_bfloat16 g_a_lo[(size_t)MTOT * CDIM];
__device__ __align__(16) __nv_bfloat16 g_w_hi[(size_t)3 * CDIM * CDIM];
__device__ __align__(16) __nv_bfloat16 g_w_lo[(size_t)3 * CDIM * CDIM];

// ---------------- helpers ----------------
__device__ __forceinline__ uint32_t smem_u32(const void* p) {
    uint32_t a;
    asm("{ .reg .u64 t; cvta.to.shared.u64 t, %1; cvt.u32.u64 %0, t; }" : "=r"(a) : "l"(p));
    return a;
}
__device__ __forceinline__ void ldsm4(uint32_t& r0, uint32_t& r1, uint32_t& r2, uint32_t& r3,
                                      uint32_t addr) {
    asm volatile("ldmatrix.sync.aligned.m8n8.x4.shared.b16 {%0,%1,%2,%3}, [%4];"
                 : "=r"(r0), "=r"(r1), "=r"(r2), "=r"(r3) : "r"(addr));
}
__device__ __forceinline__ void mma16816(float* c, const uint32_t* a, uint32_t b0, uint32_t b1) {
    asm volatile("mma.sync.aligned.m16n8k16.row.col.f32.bf16.bf16.f32 "
                 "{%0,%1,%2,%3}, {%4,%5,%6,%7}, {%8,%9}, {%0,%1,%2,%3};"
                 : "+f"(c[0]), "+f"(c[1]), "+f"(c[2]), "+f"(c[3])
                 : "r"(a[0]), "r"(a[1]), "r"(a[2]), "r"(a[3]), "r"(b0), "r"(b1));
}
__device__ __forceinline__ __nv_bfloat16 bhi(float x) { return __float2bfloat16(x); }
__device__ __forceinline__ __nv_bfloat16 blo(float x, __nv_bfloat16 h) {
    return __float2bfloat16(x - __bfloat162float(h));
}

#define CP_ASYNC16(dst, src) \
    asm volatile("cp.async.cg.shared.global [%0], [%1], 16;" :: "r"(dst), "l"(src))
#define CP_COMMIT() asm volatile("cp.async.commit_group;")
#define CP_WAIT1()  asm volatile("cp.async.wait_group 1;")
#define CP_WAIT0()  asm volatile("cp.async.wait_group 0;")

// ---------------------------------------------------------------------------
// bf16 split: hi = bf16(x), lo = bf16(x - hi)   (vectorized x4)
// ---------------------------------------------------------------------------
__global__ void split_kernel(const float4* __restrict__ src,
                             __nv_bfloat162* __restrict__ hi,
                             __nv_bfloat162* __restrict__ lo, int n4)
{
    int i = blockIdx.x * 256 + threadIdx.x;
    if (i < n4) {
        float4 v = src[i];
        __nv_bfloat16 hx = __float2bfloat16(v.x);
        __nv_bfloat16 hy = __float2bfloat16(v.y);
        __nv_bfloat16 hz = __float2bfloat16(v.z);
        __nv_bfloat16 hw = __float2bfloat16(v.w);
        hi[2 * i]     = __nv_bfloat162(hx, hy);
        hi[2 * i + 1] = __nv_bfloat162(hz, hw);
        lo[2 * i]     = __nv_bfloat162(blo(v.x, hx), blo(v.y, hy));
        lo[2 * i + 1] = __nv_bfloat162(blo(v.z, hz), blo(v.w, hw));
    }
}

// ---------------------------------------------------------------------------
// HMMA bf16x3 GEMM. MODE 0: epilogue splits into bf16 hi/lo Q(prescaled)/K/VT.
// MODE 1: fp32 row-major output.
// ---------------------------------------------------------------------------
#define LDT 72
#define GEMM_SMEM (2 * 2 * 128 * LDT * 2)   // 73728 bytes

template <int MODE>
__global__ void __launch_bounds__(256)
mma_gemm(const __nv_bfloat16* __restrict__ a_hi, const __nv_bfloat16* __restrict__ a_lo,
         const __nv_bfloat16* __restrict__ w_hi, const __nv_bfloat16* __restrict__ w_lo,
         const float* __restrict__ bias, float* __restrict__ out)
{
    extern __shared__ __nv_bfloat16 sm[];
    const int tid  = threadIdx.x;
    const int lane = tid & 31;
    const int wrp  = tid >> 5;
    const int wm   = wrp & 1;
    const int wn   = wrp >> 1;
    const int rowBase = blockIdx.y * 128;
    const int colBase = blockIdx.x * 128;
    const int lrow = tid >> 3;
    const int lch  = tid & 7;

    const int BUF = 2 * 128 * LDT;

    const int a_r = lane & 15;
    const int a_k = (lane >> 4) * 8;
    const int b_r = (lane & 7) + ((lane >> 4) << 3);
    const int b_k = ((lane >> 3) & 1) * 8;

    float acc[4][4][4] = {};

    uint4 ra[4], rb[4];
    #define LOAD_GLOBAL(t)                                                           \
        do {                                                                         \
            const int _seg = (t) / 12;                                               \
            const int _kk  = ((t) - _seg * 12) * 64;                                 \
            const __nv_bfloat16* _A = (_seg == 1) ? a_lo : a_hi;                     \
            const __nv_bfloat16* _W = (_seg == 2) ? w_lo : w_hi;                     \
            _Pragma("unroll")                                                        \
            for (int it = 0; it < 4; ++it) {                                         \
                const int r = it * 32 + lrow;                                        \
                ra[it] = *(const uint4*)(_A + (size_t)(rowBase + r) * CDIM + _kk + lch * 8); \
                rb[it] = *(const uint4*)(_W + (size_t)(colBase + r) * CDIM + _kk + lch * 8); \
            }                                                                        \
        } while (0)

    #define STORE_SMEM(p)                                                            \
        do {                                                                         \
            _Pragma("unroll")                                                        \
            for (int it = 0; it < 4; ++it) {                                         \
                const int r = it * 32 + lrow;                                        \
                *(uint4*)&sm[(p) * BUF + r * LDT + lch * 8] = ra[it];                \
                *(uint4*)&sm[(p) * BUF + 128 * LDT + r * LDT + lch * 8] = rb[it];    \
            }                                                                        \
        } while (0)

    LOAD_GLOBAL(0);
    STORE_SMEM(0);
    __syncthreads();

    int p = 0;
    for (int t = 0; t < 36; ++t) {
        if (t < 35) LOAD_GLOBAL(t + 1);

        const uint32_t aBase = smem_u32(&sm[p * BUF]);
        const uint32_t bBase = smem_u32(&sm[p * BUF + 128 * LDT]);
        #pragma unroll
        for (int ks = 0; ks < 4; ++ks) {
            uint32_t af[4][4], bf2[2][4];
            #pragma unroll
            for (int mt = 0; mt < 4; ++mt) {
                const int row = wm * 64 + mt * 16 + a_r;
                const int col = ks * 16 + a_k;
                ldsm4(af[mt][0], af[mt][1], af[mt][2], af[mt][3],
                      aBase + (uint32_t)(row * LDT + col) * 2);
            }
            #pragma unroll
            for (int np2 = 0; np2 < 2; ++np2) {
                const int row = wn * 32 + np2 * 16 + b_r;
                const int col = ks * 16 + b_k;
                ldsm4(bf2[np2][0], bf2[np2][1], bf2[np2][2], bf2[np2][3],
                      bBase + (uint32_t)(row * LDT + col) * 2);
            }
            #pragma unroll
            for (int mt = 0; mt < 4; ++mt)
                #pragma unroll
                for (int nt = 0; nt < 4; ++nt)
                    mma16816(acc[mt][nt], af[mt],
                             bf2[nt >> 1][(nt & 1) * 2], bf2[nt >> 1][(nt & 1) * 2 + 1]);
        }
        __syncthreads();
        if (t < 35) {
            STORE_SMEM(p ^ 1);
            __syncthreads();
            p ^= 1;
        }
    }

    #pragma unroll
    for (int mt = 0; mt < 4; ++mt) {
        const int r0 = rowBase + wm * 64 + mt * 16 + (lane >> 2);
        #pragma unroll
        for (int nt = 0; nt < 4; ++nt) {
            const int c = colBase + wn * 32 + nt * 8 + (lane & 3) * 2;
            const float2 bv = *(const float2*)&bias[c];
            float vx0 = acc[mt][nt][0] + bv.x, vy0 = acc[mt][nt][1] + bv.y;
            float vx1 = acc[mt][nt][2] + bv.x, vy1 = acc[mt][nt][3] + bv.y;
            if (MODE == 0) {
                const int tsel = c / CDIM;
                const int rem  = c - tsel * CDIM;
                const int hh = rem >> 6, d = rem & 63;
                const int m0 = r0, b0 = m0 >> 11, n0 = m0 & 2047;
                const int n1 = n0 + 8;   // same b (tiles never straddle 2048)
                if (tsel == 0) { vx0 *= 0.125f; vy0 *= 0.125f; vx1 *= 0.125f; vy1 *= 0.125f; }
                __nv_bfloat16 h00 = bhi(vx0), h01 = bhi(vy0), h10 = bhi(vx1), h11 = bhi(vy1);
                if (tsel < 2) {
                    __nv_bfloat16* dh = tsel ? g_khi : g_qhi;
                    __nv_bfloat16* dl = tsel ? g_klo : g_qlo;
                    const size_t i0 = (((size_t)b0 * HEADS + hh) * SEQ + n0) * DH + d;
                    const size_t i1 = (((size_t)b0 * HEADS + hh) * SEQ + n1) * DH + d;
                    *(__nv_bfloat162*)&dh[i0] = __nv_bfloat162(h00, h01);
                    *(__nv_bfloat162*)&dl[i0] = __nv_bfloat162(blo(vx0, h00), blo(vy0, h01));
                    *(__nv_bfloat162*)&dh[i1] = __nv_bfloat162(h10, h11);
                    *(__nv_bfloat162*)&dl[i1] = __nv_bfloat162(blo(vx1, h10), blo(vy1, h11));
                } else {
                    // V transposed: [B,H,D,N]
                    const size_t tb = (((size_t)b0 * HEADS + hh) * DH + d) * SEQ;
                    g_vthi[tb + n0]       = h00;
                    g_vthi[tb + SEQ + n0] = h01;
                    g_vthi[tb + n1]       = h10;
                    g_vthi[tb + SEQ + n1] = h11;
                    g_vtlo[tb + n0]       = blo(vx0, h00);
                    g_vtlo[tb + SEQ + n0] = blo(vy0, h01);
                    g_vtlo[tb + n1]       = blo(vx1, h10);
                    g_vtlo[tb + SEQ + n1] = blo(vy1, h11);
                }
            } else {
                float2 v0, v1;
                v0.x = vx0; v0.y = vy0; v1.x = vx1; v1.y = vy1;
                *(float2*)&out[(size_t)r0 * CDIM + c] = v0;
                *(float2*)&out[(size_t)(r0 + 8) * CDIM + c] = v1;
            }
        }
    }
    #undef LOAD_GLOBAL
    #undef STORE_SMEM
}

// ---------------------------------------------------------------------------
// HMMA flash attention v2: pre-split inputs, cp.async double-buffered K/VT.
// 128q x 128k tiles, 8 warps x 16 q-rows. Smem (bf16 elems):
//   Qhi[128][72], Qlo[128][72] | 2 x { Khi[128][72], Klo[128][72],
//   VThi[64][136], VTlo[64][136] } | P[128][136]
// ---------------------------------------------------------------------------
#define QLD 72
#define VLD 136
#define OQHI 0
#define OQLO (128 * QLD)
#define OBUF (2 * 128 * QLD)                    // 18432
#define BKHI 0
#define BKLO (128 * QLD)
#define BVHI (2 * 128 * QLD)
#define BVLO (2 * 128 * QLD + 64 * VLD)
#define BUFSZ (2 * 128 * QLD + 2 * 64 * VLD)    // 35840
#define OP   (OBUF + 2 * BUFSZ)                 // 90112
#define ATTN_SMEM ((OP + 128 * VLD) * 2)        // 215040 bytes

__global__ void __launch_bounds__(256)
attn_kernel()
{
    extern __shared__ __nv_bfloat16 sm[];
    const uint32_t smb = smem_u32(sm);

    const int q0 = blockIdx.x * 128;
    const int h  = blockIdx.y;
    const int b  = blockIdx.z;
    const size_t base  = ((size_t)(b * HEADS + h)) * SEQ * DH;   // K layout
    const size_t baseT = ((size_t)(b * HEADS + h)) * DH * SEQ;   // VT layout

    const int tid  = threadIdx.x;
    const int lane = tid & 31;
    const int wrp  = tid >> 5;
    const int wq   = wrp * 16;

    const int a_r = lane & 15;
    const int a_k = (lane >> 4) * 8;
    const int b_r = (lane & 7) + ((lane >> 4) << 3);
    const int b_k = ((lane >> 3) & 1) * 8;
    const int qr  = lane >> 2;
    const int qc  = (lane & 3) * 2;

    // ---- Q tiles (pre-split, prescaled) -> smem, plain uint4 copies ----
    #pragma unroll
    for (int i = 0; i < 4; ++i) {
        const int idx = i * 256 + tid;       // 0..1023
        const int r = idx >> 3, c8 = idx & 7;
        *(uint4*)&sm[OQHI + r * QLD + c8 * 8] =
            *(const uint4*)&g_qhi[base + (size_t)(q0 + r) * DH + c8 * 8];
        *(uint4*)&sm[OQLO + r * QLD + c8 * 8] =
            *(const uint4*)&g_qlo[base + (size_t)(q0 + r) * DH + c8 * 8];
    }

    // cp.async tile loader
    #define LOAD_TILE(k0, buf)                                                        \
        do {                                                                          \
            const uint32_t _bb = smb + (uint32_t)(OBUF + (buf) * BUFSZ) * 2;          \
            const __nv_bfloat16* _kh = g_khi + base + (size_t)(k0) * DH;              \
            const __nv_bfloat16* _kl = g_klo + base + (size_t)(k0) * DH;              \
            _Pragma("unroll")                                                         \
            for (int _i = 0; _i < 4; ++_i) {                                          \
                const int _idx = _i * 256 + tid;                                      \
                const int _r = _idx >> 3, _c = _idx & 7;                              \
                CP_ASYNC16(_bb + (uint32_t)(BKHI + _r * QLD + _c * 8) * 2,            \
                           _kh + _r * 64 + _c * 8);                                   \
                CP_ASYNC16(_bb + (uint32_t)(BKLO + _r * QLD + _c * 8) * 2,            \
                           _kl + _r * 64 + _c * 8);                                   \
            }                                                                         \
            const __nv_bfloat16* _vh = g_vthi + baseT + (k0);                         \
            const __nv_bfloat16* _vl = g_vtlo + baseT + (k0);                         \
            _Pragma("unroll")                                                         \
            for (int _i = 0; _i < 4; ++_i) {                                          \
                const int _idx = _i * 256 + tid;                                      \
                const int _d = _idx >> 4, _c = _idx & 15;                             \
                CP_ASYNC16(_bb + (uint32_t)(BVHI + _d * VLD + _c * 8) * 2,            \
                           _vh + (size_t)_d * SEQ + _c * 8);                          \
                CP_ASYNC16(_bb + (uint32_t)(BVLO + _d * VLD + _c * 8) * 2,            \
                           _vl + (size_t)_d * SEQ + _c * 8);                          \
            }                                                                         \
        } while (0)

    LOAD_TILE(0, 0);
    CP_COMMIT();

    float m_i[2] = {-1e30f, -1e30f};
    float l_i[2] = {0.f, 0.f};
    float oacc[8][4] = {};

    for (int t = 0; t < 16; ++t) {
        const int buf = t & 1;
        __syncthreads();   // all warps done reading buf^1 (from iter t-1); Q visible at t=0
        if (t < 15) {
            LOAD_TILE((t + 1) * 128, buf ^ 1);
            CP_COMMIT();
            CP_WAIT1();
        } else {
            CP_WAIT0();
        }
        __syncthreads();   // tile t data visible to all

        const uint32_t kh = smb + (uint32_t)(OBUF + buf * BUFSZ + BKHI) * 2;
        const uint32_t kl = smb + (uint32_t)(OBUF + buf * BUFSZ + BKLO) * 2;
        const uint32_t vh = smb + (uint32_t)(OBUF + buf * BUFSZ + BVHI) * 2;
        const uint32_t vl = smb + (uint32_t)(OBUF + buf * BUFSZ + BVLO) * 2;
        const uint32_t pB = smb + (uint32_t)OP * 2;

        // ---- S = QK^T : (Qhi+Qlo)*Khi then Qhi*Klo ----
        float sacc[16][4] = {};
        #pragma unroll
        for (int ks = 0; ks < 4; ++ks) {
            uint32_t ah[4], al[4];
            ldsm4(ah[0], ah[1], ah[2], ah[3],
                  smb + (uint32_t)(OQHI + (wq + a_r) * QLD + ks * 16 + a_k) * 2);
            ldsm4(al[0], al[1], al[2], al[3],
                  smb + (uint32_t)(OQLO + (wq + a_r) * QLD + ks * 16 + a_k) * 2);
            #pragma unroll
            for (int ng = 0; ng < 8; ++ng) {
                uint32_t bf[4];
                ldsm4(bf[0], bf[1], bf[2], bf[3],
                      kh + (uint32_t)((ng * 16 + b_r) * QLD + ks * 16 + b_k) * 2);
                mma16816(sacc[ng * 2 + 0], ah, bf[0], bf[1]);
                mma16816(sacc[ng * 2 + 1], ah, bf[2], bf[3]);
                mma16816(sacc[ng * 2 + 0], al, bf[0], bf[1]);
                mma16816(sacc[ng * 2 + 1], al, bf[2], bf[3]);
            }
        }
        #pragma unroll
        for (int ks = 0; ks < 4; ++ks) {
            uint32_t ah[4];
            ldsm4(ah[0], ah[1], ah[2], ah[3],
                  smb + (uint32_t)(OQHI + (wq + a_r) * QLD + ks * 16 + a_k) * 2);
            #pragma unroll
            for (int ng = 0; ng < 8; ++ng) {
                uint32_t bf[4];
                ldsm4(bf[0], bf[1], bf[2], bf[3],
                      kl + (uint32_t)((ng * 16 + b_r) * QLD + ks * 16 + b_k) * 2);
                mma16816(sacc[ng * 2 + 0], ah, bf[0], bf[1]);
                mma16816(sacc[ng * 2 + 1], ah, bf[2], bf[3]);
            }
        }

        // ---- online softmax (warp-local rows qr, qr+8) ----
        #pragma unroll
        for (int ri = 0; ri < 2; ++ri) {
            float mx = -1e30f;
            #pragma unroll
            for (int nt = 0; nt < 16; ++nt) {
                mx = fmaxf(mx, sacc[nt][ri * 2 + 0]);
                mx = fmaxf(mx, sacc[nt][ri * 2 + 1]);
            }
            mx = fmaxf(mx, __shfl_xor_sync(0xffffffffu, mx, 1));
            mx = fmaxf(mx, __shfl_xor_sync(0xffffffffu, mx, 2));
            const float mn = fmaxf(m_i[ri], mx);
            const float alpha = __expf(m_i[ri] - mn);
            m_i[ri] = mn;
            float r = 0.f;
            #pragma unroll
            for (int nt = 0; nt < 16; ++nt) {
                float p0 = __expf(sacc[nt][ri * 2 + 0] - mn);
                float p1 = __expf(sacc[nt][ri * 2 + 1] - mn);
                sacc[nt][ri * 2 + 0] = p0;
                sacc[nt][ri * 2 + 1] = p1;
                r += p0 + p1;
            }
            r += __shfl_xor_sync(0xffffffffu, r, 1);
            r += __shfl_xor_sync(0xffffffffu, r, 2);
            l_i[ri] = l_i[ri] * alpha + r;
            #pragma unroll
            for (int nt = 0; nt < 8; ++nt) {
                oacc[nt][ri * 2 + 0] *= alpha;
                oacc[nt][ri * 2 + 1] *= alpha;
            }
        }

        // ---- P hi -> smem (warp-local rows) ----
        #pragma unroll
        for (int nt = 0; nt < 16; ++nt) {
            const int col = nt * 8 + qc;
            *(__nv_bfloat162*)&sm[OP + (wq + qr) * VLD + col] =
                __nv_bfloat162(bhi(sacc[nt][0]), bhi(sacc[nt][1]));
            *(__nv_bfloat162*)&sm[OP + (wq + qr + 8) * VLD + col] =
                __nv_bfloat162(bhi(sacc[nt][2]), bhi(sacc[nt][3]));
        }
        __syncwarp();

        // ---- O += Phi@(Vhi + Vlo) ----
        #pragma unroll
        for (int ks = 0; ks < 8; ++ks) {
            uint32_t ap[4];
            ldsm4(ap[0], ap[1], ap[2], ap[3],
                  pB + (uint32_t)((wq + a_r) * VLD + ks * 16 + a_k) * 2);
            #pragma unroll
            for (int ng = 0; ng < 4; ++ng) {
                uint32_t bh[4], bl[4];
                ldsm4(bh[0], bh[1], bh[2], bh[3],
                      vh + (uint32_t)((ng * 16 + b_r) * VLD + ks * 16 + b_k) * 2);
                ldsm4(bl[0], bl[1], bl[2], bl[3],
                      vl + (uint32_t)((ng * 16 + b_r) * VLD + ks * 16 + b_k) * 2);
                mma16816(oacc[ng * 2 + 0], ap, bh[0], bh[1]);
                mma16816(oacc[ng * 2 + 1], ap, bh[2], bh[3]);
                mma16816(oacc[ng * 2 + 0], ap, bl[0], bl[1]);
                mma16816(oacc[ng * 2 + 1], ap, bl[2], bl[3]);
            }
        }
        __syncwarp();

        // ---- P lo -> smem, O += Plo@Vhi ----
        #pragma unroll
        for (int nt = 0; nt < 16; ++nt) {
            const int col = nt * 8 + qc;
            float p0 = sacc[nt][0], p1 = sacc[nt][1], p2 = sacc[nt][2], p3 = sacc[nt][3];
            __nv_bfloat16 h0 = bhi(p0), h1 = bhi(p1), h2 = bhi(p2), h3 = bhi(p3);
            *(__nv_bfloat162*)&sm[OP + (wq + qr) * VLD + col] =
                __nv_bfloat162(blo(p0, h0), blo(p1, h1));
            *(__nv_bfloat162*)&sm[OP + (wq + qr + 8) * VLD + col] =
                __nv_bfloat162(blo(p2, h2), blo(p3, h3));
        }
        __syncwarp();
        #pragma unroll
        for (int ks = 0; ks < 8; ++ks) {
            uint32_t ap[4];
            ldsm4(ap[0], ap[1], ap[2], ap[3],
                  pB + (uint32_t)((wq + a_r) * VLD + ks * 16 + a_k) * 2);
            #pragma unroll
            for (int ng = 0; ng < 4; ++ng) {
                uint32_t bh[4];
                ldsm4(bh[0], bh[1], bh[2], bh[3],
                      vh + (uint32_t)((ng * 16 + b_r) * VLD + ks * 16 + b_k) * 2);
                mma16816(oacc[ng * 2 + 0], ap, bh[0], bh[1]);
                mma16816(oacc[ng * 2 + 1], ap, bh[2], bh[3]);
            }
        }
    }

    // ---- epilogue: normalize, split hi/lo, write a_hi/a_lo [B,N,C] ----
    const float inv0 = 1.f / l_i[0];
    const float inv1 = 1.f / l_i[1];
    const int row0 = q0 + wq + qr;
    #pragma unroll
    for (int nt = 0; nt < 8; ++nt) {
        const int col = h * DH + nt * 8 + qc;
        const size_t i0 = ((size_t)b * SEQ + row0) * CDIM + col;
        const size_t i1 = ((size_t)b * SEQ + row0 + 8) * CDIM + col;
        float o00 = oacc[nt][0] * inv0, o01 = oacc[nt][1] * inv0;
        float o10 = oacc[nt][2] * inv1, o11 = oacc[nt][3] * inv1;
        __nv_bfloat16 h00 = bhi(o00), h01 = bhi(o01), h10 = bhi(o10), h11 = bhi(o11);
        *(__nv_bfloat162*)&g_a_hi[i0] = __nv_bfloat162(h00, h01);
        *(__nv_bfloat162*)&g_a_lo[i0] = __nv_bfloat162(blo(o00, h00), blo(o01, h01));
        *(__nv_bfloat162*)&g_a_hi[i1] = __nv_bfloat162(h10, h11);
        *(__nv_bfloat162*)&g_a_lo[i1] = __nv_bfloat162(blo(o10, h10), blo(o11, h11));
    }
    #undef LOAD_TILE
}

// ---------------------------------------------------------------------------
extern "C" void kernel_launch(void* const* d_in, const int* in_sizes, int n_in,
                              void* d_out, int out_size)
{
    const float* x      = (const float*)d_in[0];
    const float* qkv_w  = (const float*)d_in[1];
    const float* qkv_b  = (const float*)d_in[2];
    const float* proj_w = (const float*)d_in[3];
    const float* proj_b = (const float*)d_in[4];
    float* out = (float*)d_out;

    cudaFuncSetAttribute(mma_gemm<0>, cudaFuncAttributeMaxDynamicSharedMemorySize, GEMM_SMEM);
    cudaFuncSetAttribute(mma_gemm<1>, cudaFuncAttributeMaxDynamicSharedMemorySize, GEMM_SMEM);
    cudaFuncSetAttribute(attn_kernel, cudaFuncAttributeMaxDynamicSharedMemorySize, ATTN_SMEM);

    __nv_bfloat16 *a_hi, *a_lo, *w_hi, *w_lo;
    cudaGetSymbolAddress((void**)&a_hi, g_a_hi);
    cudaGetSymbolAddress((void**)&a_lo, g_a_lo);
    cudaGetSymbolAddress((void**)&w_hi, g_w_hi);
    cudaGetSymbolAddress((void**)&w_lo, g_w_lo);

    const int nx4 = MTOT * CDIM / 4;
    const int nw4 = 3 * CDIM * CDIM / 4;
    const int np4 = CDIM * CDIM / 4;

    // 1) split x and qkv_w
    split_kernel<<<(nx4 + 255) / 256, 256>>>((const float4*)x,
        (__nv_bfloat162*)a_hi, (__nv_bfloat162*)a_lo, nx4);
    split_kernel<<<(nw4 + 255) / 256, 256>>>((const float4*)qkv_w,
        (__nv_bfloat162*)w_hi, (__nv_bfloat162*)w_lo, nw4);

    // 2) QKV projection -> pre-split Q(prescaled)/K (B,H,N,D) + VT (B,H,D,N)
    mma_gemm<0><<<dim3(18, 64), 256, GEMM_SMEM>>>(a_hi, a_lo, w_hi, w_lo, qkv_b, nullptr);

    // 3) Flash attention -> a_hi/a_lo (bf16 hi/lo, [B,N,C])
    attn_kernel<<<dim3(SEQ / 128, HEADS, BATCH), 256, ATTN_SMEM>>>();

    // 4) split proj_w, then output projection reading a_hi/a_lo
    split_kernel<<<(np4 + 255) / 256, 256>>>((const float4*)proj_w,
        (__nv_bfloat162*)w_hi, (__nv_bfloat162*)w_lo, np4);
    mma_gemm<1><<<dim3(6, 64), 256, GEMM_SMEM>>>(a_hi, a_lo, w_hi, w_lo, proj_b, out);
}

// round 7
// speedup vs baseline: 2.9105x; 1.0445x over previous
#include <cuda_runtime.h>
#include <cuda_bf16.h>
#include <cstdint>

#define HEADS 12
#define SEQ   2048
#define BATCH 4
#define DH    64
#define CDIM  768
#define MTOT  8192   // BATCH*SEQ
#define NQKV ((size_t)BATCH * HEADS * SEQ * DH)

// ---------------- scratch (allocation-free) ----------------
__device__ __align__(16) __nv_bfloat16 g_qhi[NQKV], g_qlo[NQKV];
__device__ __align__(16) __nv_bfloat16 g_khi[NQKV], g_klo[NQKV];
__device__ __align__(16) __nv_bfloat16 g_vthi[NQKV], g_vtlo[NQKV];
__device__ __align__(16) __nv_bfloat16 g_a_hi[(size_t)MTOT * CDIM];
__device__ __align__(16) __nv_bfloat16 g_a_lo[(size_t)MTOT * CDIM];
__device__ __align__(16) __nv_bfloat16 g_w_hi[(size_t)3 * CDIM * CDIM];
__device__ __align__(16) __nv_bfloat16 g_w_lo[(size_t)3 * CDIM * CDIM];

// ---------------- helpers ----------------
__device__ __forceinline__ uint32_t smem_u32(const void* p) {
    uint32_t a;
    asm("{ .reg .u64 t; cvta.to.shared.u64 t, %1; cvt.u32.u64 %0, t; }" : "=r"(a) : "l"(p));
    return a;
}
__device__ __forceinline__ void ldsm4(uint32_t& r0, uint32_t& r1, uint32_t& r2, uint32_t& r3,
                                      uint32_t addr) {
    asm volatile("ldmatrix.sync.aligned.m8n8.x4.shared.b16 {%0,%1,%2,%3}, [%4];"
                 : "=r"(r0), "=r"(r1), "=r"(r2), "=r"(r3) : "r"(addr));
}
__device__ __forceinline__ void mma16816(float* c, const uint32_t* a, uint32_t b0, uint32_t b1) {
    asm volatile("mma.sync.aligned.m16n8k16.row.col.f32.bf16.bf16.f32 "
                 "{%0,%1,%2,%3}, {%4,%5,%6,%7}, {%8,%9}, {%0,%1,%2,%3};"
                 : "+f"(c[0]), "+f"(c[1]), "+f"(c[2]), "+f"(c[3])
                 : "r"(a[0]), "r"(a[1]), "r"(a[2]), "r"(a[3]), "r"(b0), "r"(b1));
}
__device__ __forceinline__ __nv_bfloat16 bhi(float x) { return __float2bfloat16(x); }
__device__ __forceinline__ __nv_bfloat16 blo(float x, __nv_bfloat16 h) {
    return __float2bfloat16(x - __bfloat162float(h));
}

#define CP_ASYNC16(dst, src) \
    asm volatile("cp.async.cg.shared.global [%0], [%1], 16;" :: "r"(dst), "l"(src))
#define CP_COMMIT() asm volatile("cp.async.commit_group;")
#define CP_WAIT1()  asm volatile("cp.async.wait_group 1;")
#define CP_WAIT0()  asm volatile("cp.async.wait_group 0;")

// ---------------------------------------------------------------------------
__global__ void split_kernel(const float4* __restrict__ src,
                             __nv_bfloat162* __restrict__ hi,
                             __nv_bfloat162* __restrict__ lo, int n4)
{
    int i = blockIdx.x * 256 + threadIdx.x;
    if (i < n4) {
        float4 v = src[i];
        __nv_bfloat16 hx = __float2bfloat16(v.x);
        __nv_bfloat16 hy = __float2bfloat16(v.y);
        __nv_bfloat16 hz = __float2bfloat16(v.z);
        __nv_bfloat16 hw = __float2bfloat16(v.w);
        hi[2 * i]     = __nv_bfloat162(hx, hy);
        hi[2 * i + 1] = __nv_bfloat162(hz, hw);
        lo[2 * i]     = __nv_bfloat162(blo(v.x, hx), blo(v.y, hy));
        lo[2 * i + 1] = __nv_bfloat162(blo(v.z, hz), blo(v.w, hw));
    }
}

// ---------------------------------------------------------------------------
// HMMA bf16x3 GEMM (unchanged). MODE 0: split epilogue -> Q(prescaled)/K/VT.
// MODE 1: fp32 row-major output.
// ---------------------------------------------------------------------------
#define LDT 72
#define GEMM_SMEM (2 * 2 * 128 * LDT * 2)   // 73728 bytes

template <int MODE>
__global__ void __launch_bounds__(256)
mma_gemm(const __nv_bfloat16* __restrict__ a_hi, const __nv_bfloat16* __restrict__ a_lo,
         const __nv_bfloat16* __restrict__ w_hi, const __nv_bfloat16* __restrict__ w_lo,
         const float* __restrict__ bias, float* __restrict__ out)
{
    extern __shared__ __nv_bfloat16 sm[];
    const int tid  = threadIdx.x;
    const int lane = tid & 31;
    const int wrp  = tid >> 5;
    const int wm   = wrp & 1;
    const int wn   = wrp >> 1;
    const int rowBase = blockIdx.y * 128;
    const int colBase = blockIdx.x * 128;
    const int lrow = tid >> 3;
    const int lch  = tid & 7;

    const int BUF = 2 * 128 * LDT;

    const int a_r = lane & 15;
    const int a_k = (lane >> 4) * 8;
    const int b_r = (lane & 7) + ((lane >> 4) << 3);
    const int b_k = ((lane >> 3) & 1) * 8;

    float acc[4][4][4] = {};

    uint4 ra[4], rb[4];
    #define LOAD_GLOBAL(t)                                                           \
        do {                                                                         \
            const int _seg = (t) / 12;                                               \
            const int _kk  = ((t) - _seg * 12) * 64;                                 \
            const __nv_bfloat16* _A = (_seg == 1) ? a_lo : a_hi;                     \
            const __nv_bfloat16* _W = (_seg == 2) ? w_lo : w_hi;                     \
            _Pragma("unroll")                                                        \
            for (int it = 0; it < 4; ++it) {                                         \
                const int r = it * 32 + lrow;                                        \
                ra[it] = *(const uint4*)(_A + (size_t)(rowBase + r) * CDIM + _kk + lch * 8); \
                rb[it] = *(const uint4*)(_W + (size_t)(colBase + r) * CDIM + _kk + lch * 8); \
            }                                                                        \
        } while (0)

    #define STORE_SMEM(p)                                                            \
        do {                                                                         \
            _Pragma("unroll")                                                        \
            for (int it = 0; it < 4; ++it) {                                         \
                const int r = it * 32 + lrow;                                        \
                *(uint4*)&sm[(p) * BUF + r * LDT + lch * 8] = ra[it];                \
                *(uint4*)&sm[(p) * BUF + 128 * LDT + r * LDT + lch * 8] = rb[it];    \
            }                                                                        \
        } while (0)

    LOAD_GLOBAL(0);
    STORE_SMEM(0);
    __syncthreads();

    int p = 0;
    for (int t = 0; t < 36; ++t) {
        if (t < 35) LOAD_GLOBAL(t + 1);

        const uint32_t aBase = smem_u32(&sm[p * BUF]);
        const uint32_t bBase = smem_u32(&sm[p * BUF + 128 * LDT]);
        #pragma unroll
        for (int ks = 0; ks < 4; ++ks) {
            uint32_t af[4][4], bf2[2][4];
            #pragma unroll
            for (int mt = 0; mt < 4; ++mt) {
                const int row = wm * 64 + mt * 16 + a_r;
                const int col = ks * 16 + a_k;
                ldsm4(af[mt][0], af[mt][1], af[mt][2], af[mt][3],
                      aBase + (uint32_t)(row * LDT + col) * 2);
            }
            #pragma unroll
            for (int np2 = 0; np2 < 2; ++np2) {
                const int row = wn * 32 + np2 * 16 + b_r;
                const int col = ks * 16 + b_k;
                ldsm4(bf2[np2][0], bf2[np2][1], bf2[np2][2], bf2[np2][3],
                      bBase + (uint32_t)(row * LDT + col) * 2);
            }
            #pragma unroll
            for (int mt = 0; mt < 4; ++mt)
                #pragma unroll
                for (int nt = 0; nt < 4; ++nt)
                    mma16816(acc[mt][nt], af[mt],
                             bf2[nt >> 1][(nt & 1) * 2], bf2[nt >> 1][(nt & 1) * 2 + 1]);
        }
        __syncthreads();
        if (t < 35) {
            STORE_SMEM(p ^ 1);
            __syncthreads();
            p ^= 1;
        }
    }

    #pragma unroll
    for (int mt = 0; mt < 4; ++mt) {
        const int r0 = rowBase + wm * 64 + mt * 16 + (lane >> 2);
        #pragma unroll
        for (int nt = 0; nt < 4; ++nt) {
            const int c = colBase + wn * 32 + nt * 8 + (lane & 3) * 2;
            const float2 bv = *(const float2*)&bias[c];
            float vx0 = acc[mt][nt][0] + bv.x, vy0 = acc[mt][nt][1] + bv.y;
            float vx1 = acc[mt][nt][2] + bv.x, vy1 = acc[mt][nt][3] + bv.y;
            if (MODE == 0) {
                const int tsel = c / CDIM;
                const int rem  = c - tsel * CDIM;
                const int hh = rem >> 6, d = rem & 63;
                const int m0 = r0, b0 = m0 >> 11, n0 = m0 & 2047;
                const int n1 = n0 + 8;
                if (tsel == 0) { vx0 *= 0.125f; vy0 *= 0.125f; vx1 *= 0.125f; vy1 *= 0.125f; }
                __nv_bfloat16 h00 = bhi(vx0), h01 = bhi(vy0), h10 = bhi(vx1), h11 = bhi(vy1);
                if (tsel < 2) {
                    __nv_bfloat16* dh = tsel ? g_khi : g_qhi;
                    __nv_bfloat16* dl = tsel ? g_klo : g_qlo;
                    const size_t i0 = (((size_t)b0 * HEADS + hh) * SEQ + n0) * DH + d;
                    const size_t i1 = (((size_t)b0 * HEADS + hh) * SEQ + n1) * DH + d;
                    *(__nv_bfloat162*)&dh[i0] = __nv_bfloat162(h00, h01);
                    *(__nv_bfloat162*)&dl[i0] = __nv_bfloat162(blo(vx0, h00), blo(vy0, h01));
                    *(__nv_bfloat162*)&dh[i1] = __nv_bfloat162(h10, h11);
                    *(__nv_bfloat162*)&dl[i1] = __nv_bfloat162(blo(vx1, h10), blo(vy1, h11));
                } else {
                    const size_t tb = (((size_t)b0 * HEADS + hh) * DH + d) * SEQ;
                    g_vthi[tb + n0]       = h00;
                    g_vthi[tb + SEQ + n0] = h01;
                    g_vthi[tb + n1]       = h10;
                    g_vthi[tb + SEQ + n1] = h11;
                    g_vtlo[tb + n0]       = blo(vx0, h00);
                    g_vtlo[tb + SEQ + n0] = blo(vy0, h01);
                    g_vtlo[tb + n1]       = blo(vx1, h10);
                    g_vtlo[tb + SEQ + n1] = blo(vy1, h11);
                }
            } else {
                float2 v0, v1;
                v0.x = vx0; v0.y = vy0; v1.x = vx1; v1.y = vy1;
                *(float2*)&out[(size_t)r0 * CDIM + c] = v0;
                *(float2*)&out[(size_t)(r0 + 8) * CDIM + c] = v1;
            }
        }
    }
    #undef LOAD_GLOBAL
    #undef STORE_SMEM
}

// ---------------------------------------------------------------------------
// HMMA flash attention v3: 64q x 64k tiles, 128 threads (4 warps x 16 q-rows),
// 99KB smem -> 2 CTAs/SM for cross-CTA latency hiding.
// Smem (bf16 elems): Qhi/Qlo[64][72] | 2 x { Khi/Klo[64][72], VThi/VTlo[64][72] }
//                    | P[64][72]
// ---------------------------------------------------------------------------
#define QLD 72
#define OQHI 0
#define OQLO (64 * QLD)
#define OBUF (2 * 64 * QLD)                 // 9216
#define BKHI 0
#define BKLO (64 * QLD)
#define BVHI (2 * 64 * QLD)
#define BVLO (3 * 64 * QLD)
#define BUFSZ (4 * 64 * QLD)                // 18432
#define OP   (OBUF + 2 * BUFSZ)             // 46080
#define ATTN_SMEM ((OP + 64 * QLD) * 2)     // 101376 bytes

__global__ void __launch_bounds__(128)
attn_kernel()
{
    extern __shared__ __nv_bfloat16 sm[];
    const uint32_t smb = smem_u32(sm);

    const int q0 = blockIdx.x * 64;
    const int h  = blockIdx.y;
    const int b  = blockIdx.z;
    const size_t base  = ((size_t)(b * HEADS + h)) * SEQ * DH;   // Q/K layout
    const size_t baseT = ((size_t)(b * HEADS + h)) * DH * SEQ;   // VT layout

    const int tid  = threadIdx.x;
    const int lane = tid & 31;
    const int wrp  = tid >> 5;
    const int wq   = wrp * 16;

    const int a_r = lane & 15;
    const int a_k = (lane >> 4) * 8;
    const int b_r = (lane & 7) + ((lane >> 4) << 3);
    const int b_k = ((lane >> 3) & 1) * 8;
    const int qr  = lane >> 2;
    const int qc  = (lane & 3) * 2;

    // ---- Q tiles -> smem (64 rows x 8 chunks, hi+lo) ----
    #pragma unroll
    for (int i = 0; i < 4; ++i) {
        const int idx = i * 128 + tid;       // 0..511
        const int r = idx >> 3, c8 = idx & 7;
        *(uint4*)&sm[OQHI + r * QLD + c8 * 8] =
            *(const uint4*)&g_qhi[base + (size_t)(q0 + r) * DH + c8 * 8];
        *(uint4*)&sm[OQLO + r * QLD + c8 * 8] =
            *(const uint4*)&g_qlo[base + (size_t)(q0 + r) * DH + c8 * 8];
    }

    #define LOAD_TILE(k0, buf)                                                        \
        do {                                                                          \
            const uint32_t _bb = smb + (uint32_t)(OBUF + (buf) * BUFSZ) * 2;          \
            const __nv_bfloat16* _kh = g_khi + base + (size_t)(k0) * DH;              \
            const __nv_bfloat16* _kl = g_klo + base + (size_t)(k0) * DH;              \
            const __nv_bfloat16* _vh = g_vthi + baseT + (k0);                         \
            const __nv_bfloat16* _vl = g_vtlo + baseT + (k0);                         \
            _Pragma("unroll")                                                         \
            for (int _i = 0; _i < 4; ++_i) {                                          \
                const int _idx = _i * 128 + tid;                                      \
                const int _r = _idx >> 3, _c = _idx & 7;                              \
                CP_ASYNC16(_bb + (uint32_t)(BKHI + _r * QLD + _c * 8) * 2,            \
                           _kh + _r * 64 + _c * 8);                                   \
                CP_ASYNC16(_bb + (uint32_t)(BKLO + _r * QLD + _c * 8) * 2,            \
                           _kl + _r * 64 + _c * 8);                                   \
                CP_ASYNC16(_bb + (uint32_t)(BVHI + _r * QLD + _c * 8) * 2,            \
                           _vh + (size_t)_r * SEQ + _c * 8);                          \
                CP_ASYNC16(_bb + (uint32_t)(BVLO + _r * QLD + _c * 8) * 2,            \
                           _vl + (size_t)_r * SEQ + _c * 8);                          \
            }                                                                         \
        } while (0)

    LOAD_TILE(0, 0);
    CP_COMMIT();

    float m_i[2] = {-1e30f, -1e30f};
    float l_i[2] = {0.f, 0.f};
    float oacc[8][4] = {};

    for (int t = 0; t < 32; ++t) {
        const int buf = t & 1;
        __syncthreads();   // consumers of buf^1 done; Q stores visible at t=0
        if (t < 31) {
            LOAD_TILE((t + 1) * 64, buf ^ 1);
            CP_COMMIT();
            CP_WAIT1();
        } else {
            CP_WAIT0();
        }
        __syncthreads();   // tile t visible

        const uint32_t kh = smb + (uint32_t)(OBUF + buf * BUFSZ + BKHI) * 2;
        const uint32_t kl = smb + (uint32_t)(OBUF + buf * BUFSZ + BKLO) * 2;
        const uint32_t vh = smb + (uint32_t)(OBUF + buf * BUFSZ + BVHI) * 2;
        const uint32_t vl = smb + (uint32_t)(OBUF + buf * BUFSZ + BVLO) * 2;
        const uint32_t pB = smb + (uint32_t)OP * 2;

        // ---- S = QK^T : (Qhi+Qlo)*Khi, then Qhi*Klo ----
        float sacc[8][4] = {};
        #pragma unroll
        for (int ks = 0; ks < 4; ++ks) {
            uint32_t ah[4], al[4];
            ldsm4(ah[0], ah[1], ah[2], ah[3],
                  smb + (uint32_t)(OQHI + (wq + a_r) * QLD + ks * 16 + a_k) * 2);
            ldsm4(al[0], al[1], al[2], al[3],
                  smb + (uint32_t)(OQLO + (wq + a_r) * QLD + ks * 16 + a_k) * 2);
            #pragma unroll
            for (int ng = 0; ng < 4; ++ng) {
                uint32_t bf[4];
                ldsm4(bf[0], bf[1], bf[2], bf[3],
                      kh + (uint32_t)((ng * 16 + b_r) * QLD + ks * 16 + b_k) * 2);
                mma16816(sacc[ng * 2 + 0], ah, bf[0], bf[1]);
                mma16816(sacc[ng * 2 + 1], ah, bf[2], bf[3]);
                mma16816(sacc[ng * 2 + 0], al, bf[0], bf[1]);
                mma16816(sacc[ng * 2 + 1], al, bf[2], bf[3]);
            }
        }
        #pragma unroll
        for (int ks = 0; ks < 4; ++ks) {
            uint32_t ah[4];
            ldsm4(ah[0], ah[1], ah[2], ah[3],
                  smb + (uint32_t)(OQHI + (wq + a_r) * QLD + ks * 16 + a_k) * 2);
            #pragma unroll
            for (int ng = 0; ng < 4; ++ng) {
                uint32_t bf[4];
                ldsm4(bf[0], bf[1], bf[2], bf[3],
                      kl + (uint32_t)((ng * 16 + b_r) * QLD + ks * 16 + b_k) * 2);
                mma16816(sacc[ng * 2 + 0], ah, bf[0], bf[1]);
                mma16816(sacc[ng * 2 + 1], ah, bf[2], bf[3]);
            }
        }

        // ---- online softmax (warp-local rows qr, qr+8) ----
        #pragma unroll
        for (int ri = 0; ri < 2; ++ri) {
            float mx = -1e30f;
            #pragma unroll
            for (int nt = 0; nt < 8; ++nt) {
                mx = fmaxf(mx, sacc[nt][ri * 2 + 0]);
                mx = fmaxf(mx, sacc[nt][ri * 2 + 1]);
            }
            mx = fmaxf(mx, __shfl_xor_sync(0xffffffffu, mx, 1));
            mx = fmaxf(mx, __shfl_xor_sync(0xffffffffu, mx, 2));
            const float mn = fmaxf(m_i[ri], mx);
            const float alpha = __expf(m_i[ri] - mn);
            m_i[ri] = mn;
            float r = 0.f;
            #pragma unroll
            for (int nt = 0; nt < 8; ++nt) {
                float p0 = __expf(sacc[nt][ri * 2 + 0] - mn);
                float p1 = __expf(sacc[nt][ri * 2 + 1] - mn);
                sacc[nt][ri * 2 + 0] = p0;
                sacc[nt][ri * 2 + 1] = p1;
                r += p0 + p1;
            }
            r += __shfl_xor_sync(0xffffffffu, r, 1);
            r += __shfl_xor_sync(0xffffffffu, r, 2);
            l_i[ri] = l_i[ri] * alpha + r;
            #pragma unroll
            for (int nt = 0; nt < 8; ++nt) {
                oacc[nt][ri * 2 + 0] *= alpha;
                oacc[nt][ri * 2 + 1] *= alpha;
            }
        }

        // ---- P hi -> smem (warp-local rows) ----
        #pragma unroll
        for (int nt = 0; nt < 8; ++nt) {
            const int col = nt * 8 + qc;
            *(__nv_bfloat162*)&sm[OP + (wq + qr) * QLD + col] =
                __nv_bfloat162(bhi(sacc[nt][0]), bhi(sacc[nt][1]));
            *(__nv_bfloat162*)&sm[OP + (wq + qr + 8) * QLD + col] =
                __nv_bfloat162(bhi(sacc[nt][2]), bhi(sacc[nt][3]));
        }
        __syncwarp();

        // ---- O += Phi@(Vhi + Vlo) ----
        #pragma unroll
        for (int ks = 0; ks < 4; ++ks) {
            uint32_t ap[4];
            ldsm4(ap[0], ap[1], ap[2], ap[3],
                  pB + (uint32_t)((wq + a_r) * QLD + ks * 16 + a_k) * 2);
            #pragma unroll
            for (int ng = 0; ng < 4; ++ng) {
                uint32_t bh[4], bl[4];
                ldsm4(bh[0], bh[1], bh[2], bh[3],
                      vh + (uint32_t)((ng * 16 + b_r) * QLD + ks * 16 + b_k) * 2);
                ldsm4(bl[0], bl[1], bl[2], bl[3],
                      vl + (uint32_t)((ng * 16 + b_r) * QLD + ks * 16 + b_k) * 2);
                mma16816(oacc[ng * 2 + 0], ap, bh[0], bh[1]);
                mma16816(oacc[ng * 2 + 1], ap, bh[2], bh[3]);
                mma16816(oacc[ng * 2 + 0], ap, bl[0], bl[1]);
                mma16816(oacc[ng * 2 + 1], ap, bl[2], bl[3]);
            }
        }
        __syncwarp();

        // ---- P lo -> smem, O += Plo@Vhi ----
        #pragma unroll
        for (int nt = 0; nt < 8; ++nt) {
            const int col = nt * 8 + qc;
            float p0 = sacc[nt][0], p1 = sacc[nt][1], p2 = sacc[nt][2], p3 = sacc[nt][3];
            __nv_bfloat16 h0 = bhi(p0), h1 = bhi(p1), h2 = bhi(p2), h3 = bhi(p3);
            *(__nv_bfloat162*)&sm[OP + (wq + qr) * QLD + col] =
                __nv_bfloat162(blo(p0, h0), blo(p1, h1));
            *(__nv_bfloat162*)&sm[OP + (wq + qr + 8) * QLD + col] =
                __nv_bfloat162(blo(p2, h2), blo(p3, h3));
        }
        __syncwarp();
        #pragma unroll
        for (int ks = 0; ks < 4; ++ks) {
            uint32_t ap[4];
            ldsm4(ap[0], ap[1], ap[2], ap[3],
                  pB + (uint32_t)((wq + a_r) * QLD + ks * 16 + a_k) * 2);
            #pragma unroll
            for (int ng = 0; ng < 4; ++ng) {
                uint32_t bh[4];
                ldsm4(bh[0], bh[1], bh[2], bh[3],
                      vh + (uint32_t)((ng * 16 + b_r) * QLD + ks * 16 + b_k) * 2);
                mma16816(oacc[ng * 2 + 0], ap, bh[0], bh[1]);
                mma16816(oacc[ng * 2 + 1], ap, bh[2], bh[3]);
            }
        }
    }

    // ---- epilogue: normalize, split hi/lo, write a_hi/a_lo [B,N,C] ----
    const float inv0 = 1.f / l_i[0];
    const float inv1 = 1.f / l_i[1];
    const int row0 = q0 + wq + qr;
    #pragma unroll
    for (int nt = 0; nt < 8; ++nt) {
        const int col = h * DH + nt * 8 + qc;
        const size_t i0 = ((size_t)b * SEQ + row0) * CDIM + col;
        const size_t i1 = ((size_t)b * SEQ + row0 + 8) * CDIM + col;
        float o00 = oacc[nt][0] * inv0, o01 = oacc[nt][1] * inv0;
        float o10 = oacc[nt][2] * inv1, o11 = oacc[nt][3] * inv1;
        __nv_bfloat16 h00 = bhi(o00), h01 = bhi(o01), h10 = bhi(o10), h11 = bhi(o11);
        *(__nv_bfloat162*)&g_a_hi[i0] = __nv_bfloat162(h00, h01);
        *(__nv_bfloat162*)&g_a_lo[i0] = __nv_bfloat162(blo(o00, h00), blo(o01, h01));
        *(__nv_bfloat162*)&g_a_hi[i1] = __nv_bfloat162(h10, h11);
        *(__nv_bfloat162*)&g_a_lo[i1] = __nv_bfloat162(blo(o10, h10), blo(o11, h11));
    }
    #undef LOAD_TILE
}

// ---------------------------------------------------------------------------
extern "C" void kernel_launch(void* const* d_in, const int* in_sizes, int n_in,
                              void* d_out, int out_size)
{
    const float* x      = (const float*)d_in[0];
    const float* qkv_w  = (const float*)d_in[1];
    const float* qkv_b  = (const float*)d_in[2];
    const float* proj_w = (const float*)d_in[3];
    const float* proj_b = (const float*)d_in[4];
    float* out = (float*)d_out;

    cudaFuncSetAttribute(mma_gemm<0>, cudaFuncAttributeMaxDynamicSharedMemorySize, GEMM_SMEM);
    cudaFuncSetAttribute(mma_gemm<1>, cudaFuncAttributeMaxDynamicSharedMemorySize, GEMM_SMEM);
    cudaFuncSetAttribute(attn_kernel, cudaFuncAttributeMaxDynamicSharedMemorySize, ATTN_SMEM);

    __nv_bfloat16 *a_hi, *a_lo, *w_hi, *w_lo;
    cudaGetSymbolAddress((void**)&a_hi, g_a_hi);
    cudaGetSymbolAddress((void**)&a_lo, g_a_lo);
    cudaGetSymbolAddress((void**)&w_hi, g_w_hi);
    cudaGetSymbolAddress((void**)&w_lo, g_w_lo);

    const int nx4 = MTOT * CDIM / 4;
    const int nw4 = 3 * CDIM * CDIM / 4;
    const int np4 = CDIM * CDIM / 4;

    split_kernel<<<(nx4 + 255) / 256, 256>>>((const float4*)x,
        (__nv_bfloat162*)a_hi, (__nv_bfloat162*)a_lo, nx4);
    split_kernel<<<(nw4 + 255) / 256, 256>>>((const float4*)qkv_w,
        (__nv_bfloat162*)w_hi, (__nv_bfloat162*)w_lo, nw4);

    mma_gemm<0><<<dim3(18, 64), 256, GEMM_SMEM>>>(a_hi, a_lo, w_hi, w_lo, qkv_b, nullptr);

    attn_kernel<<<dim3(SEQ / 64, HEADS, BATCH), 128, ATTN_SMEM>>>();

    split_kernel<<<(np4 + 255) / 256, 256>>>((const float4*)proj_w,
        (__nv_bfloat162*)w_hi, (__nv_bfloat162*)w_lo, np4);
    mma_gemm<1><<<dim3(6, 64), 256, GEMM_SMEM>>>(a_hi, a_lo, w_hi, w_lo, proj_b, out);
}

// round 8
// speedup vs baseline: 3.2446x; 1.1148x over previous
#include <cuda_runtime.h>
#include <cuda_bf16.h>
#include <cstdint>

#define HEADS 12
#define SEQ   2048
#define BATCH 4
#define DH    64
#define CDIM  768
#define MTOT  8192   // BATCH*SEQ
#define NQKV ((size_t)BATCH * HEADS * SEQ * DH)

// ---------------- scratch (allocation-free) ----------------
__device__ __align__(16) __nv_bfloat16 g_qhi[NQKV], g_qlo[NQKV];
__device__ __align__(16) __nv_bfloat16 g_khi[NQKV], g_klo[NQKV];
__device__ __align__(16) __nv_bfloat16 g_vthi[NQKV], g_vtlo[NQKV];
__device__ __align__(16) __nv_bfloat16 g_a_hi[(size_t)MTOT * CDIM];
__device__ __align__(16) __nv_bfloat16 g_a_lo[(size_t)MTOT * CDIM];
__device__ __align__(16) __nv_bfloat16 g_w_hi[(size_t)3 * CDIM * CDIM];
__device__ __align__(16) __nv_bfloat16 g_w_lo[(size_t)3 * CDIM * CDIM];

// Q prescale: 1/sqrt(64) * log2(e)  (softmax runs in exp2 domain)
#define QSCALE 0.1803368801111204f

// ---------------- helpers ----------------
__device__ __forceinline__ uint32_t smem_u32(const void* p) {
    uint32_t a;
    asm("{ .reg .u64 t; cvta.to.shared.u64 t, %1; cvt.u32.u64 %0, t; }" : "=r"(a) : "l"(p));
    return a;
}
__device__ __forceinline__ void ldsm4(uint32_t& r0, uint32_t& r1, uint32_t& r2, uint32_t& r3,
                                      uint32_t addr) {
    asm volatile("ldmatrix.sync.aligned.m8n8.x4.shared.b16 {%0,%1,%2,%3}, [%4];"
                 : "=r"(r0), "=r"(r1), "=r"(r2), "=r"(r3) : "r"(addr));
}
__device__ __forceinline__ void mma16816(float* c, const uint32_t* a, uint32_t b0, uint32_t b1) {
    asm volatile("mma.sync.aligned.m16n8k16.row.col.f32.bf16.bf16.f32 "
                 "{%0,%1,%2,%3}, {%4,%5,%6,%7}, {%8,%9}, {%0,%1,%2,%3};"
                 : "+f"(c[0]), "+f"(c[1]), "+f"(c[2]), "+f"(c[3])
                 : "r"(a[0]), "r"(a[1]), "r"(a[2]), "r"(a[3]), "r"(b0), "r"(b1));
}
__device__ __forceinline__ __nv_bfloat16 bhi(float x) { return __float2bfloat16(x); }
__device__ __forceinline__ __nv_bfloat16 blo(float x, __nv_bfloat16 h) {
    return __float2bfloat16(x - __bfloat162float(h));
}
__device__ __forceinline__ float ex2f(float x) {
    float y;
    asm("ex2.approx.f32 %0, %1;" : "=f"(y) : "f"(x));
    return y;
}
// pack two floats (lo elem, hi elem) -> bf16x2 register
__device__ __forceinline__ uint32_t packbf(float lo_, float hi_) {
    uint32_t r;
    asm("cvt.rn.bf16x2.f32 %0, %1, %2;" : "=r"(r) : "f"(hi_), "f"(lo_));
    return r;
}

#define CP_ASYNC16(dst, src) \
    asm volatile("cp.async.cg.shared.global [%0], [%1], 16;" :: "r"(dst), "l"(src))
#define CP_COMMIT() asm volatile("cp.async.commit_group;")
#define CP_WAIT1()  asm volatile("cp.async.wait_group 1;")
#define CP_WAIT0()  asm volatile("cp.async.wait_group 0;")

// ---------------------------------------------------------------------------
__global__ void split_kernel(const float4* __restrict__ src,
                             __nv_bfloat162* __restrict__ hi,
                             __nv_bfloat162* __restrict__ lo, int n4)
{
    int i = blockIdx.x * 256 + threadIdx.x;
    if (i < n4) {
        float4 v = src[i];
        __nv_bfloat16 hx = __float2bfloat16(v.x);
        __nv_bfloat16 hy = __float2bfloat16(v.y);
        __nv_bfloat16 hz = __float2bfloat16(v.z);
        __nv_bfloat16 hw = __float2bfloat16(v.w);
        hi[2 * i]     = __nv_bfloat162(hx, hy);
        hi[2 * i + 1] = __nv_bfloat162(hz, hw);
        lo[2 * i]     = __nv_bfloat162(blo(v.x, hx), blo(v.y, hy));
        lo[2 * i + 1] = __nv_bfloat162(blo(v.z, hz), blo(v.w, hw));
    }
}

// ---------------------------------------------------------------------------
// HMMA bf16x3 GEMM. MODE 0: split epilogue -> Q(prescaled by QSCALE)/K/VT.
// MODE 1: fp32 row-major output.
// ---------------------------------------------------------------------------
#define LDT 72
#define GEMM_SMEM (2 * 2 * 128 * LDT * 2)   // 73728 bytes

template <int MODE>
__global__ void __launch_bounds__(256)
mma_gemm(const __nv_bfloat16* __restrict__ a_hi, const __nv_bfloat16* __restrict__ a_lo,
         const __nv_bfloat16* __restrict__ w_hi, const __nv_bfloat16* __restrict__ w_lo,
         const float* __restrict__ bias, float* __restrict__ out)
{
    extern __shared__ __nv_bfloat16 sm[];
    const int tid  = threadIdx.x;
    const int lane = tid & 31;
    const int wrp  = tid >> 5;
    const int wm   = wrp & 1;
    const int wn   = wrp >> 1;
    const int rowBase = blockIdx.y * 128;
    const int colBase = blockIdx.x * 128;
    const int lrow = tid >> 3;
    const int lch  = tid & 7;

    const int BUF = 2 * 128 * LDT;

    const int a_r = lane & 15;
    const int a_k = (lane >> 4) * 8;
    const int b_r = (lane & 7) + ((lane >> 4) << 3);
    const int b_k = ((lane >> 3) & 1) * 8;

    float acc[4][4][4] = {};

    uint4 ra[4], rb[4];
    #define LOAD_GLOBAL(t)                                                           \
        do {                                                                         \
            const int _seg = (t) / 12;                                               \
            const int _kk  = ((t) - _seg * 12) * 64;                                 \
            const __nv_bfloat16* _A = (_seg == 1) ? a_lo : a_hi;                     \
            const __nv_bfloat16* _W = (_seg == 2) ? w_lo : w_hi;                     \
            _Pragma("unroll")                                                        \
            for (int it = 0; it < 4; ++it) {                                         \
                const int r = it * 32 + lrow;                                        \
                ra[it] = *(const uint4*)(_A + (size_t)(rowBase + r) * CDIM + _kk + lch * 8); \
                rb[it] = *(const uint4*)(_W + (size_t)(colBase + r) * CDIM + _kk + lch * 8); \
            }                                                                        \
        } while (0)

    #define STORE_SMEM(p)                                                            \
        do {                                                                         \
            _Pragma("unroll")                                                        \
            for (int it = 0; it < 4; ++it) {                                         \
                const int r = it * 32 + lrow;                                        \
                *(uint4*)&sm[(p) * BUF + r * LDT + lch * 8] = ra[it];                \
                *(uint4*)&sm[(p) * BUF + 128 * LDT + r * LDT + lch * 8] = rb[it];    \
            }                                                                        \
        } while (0)

    LOAD_GLOBAL(0);
    STORE_SMEM(0);
    __syncthreads();

    int p = 0;
    for (int t = 0; t < 36; ++t) {
        if (t < 35) LOAD_GLOBAL(t + 1);

        const uint32_t aBase = smem_u32(&sm[p * BUF]);
        const uint32_t bBase = smem_u32(&sm[p * BUF + 128 * LDT]);
        #pragma unroll
        for (int ks = 0; ks < 4; ++ks) {
            uint32_t af[4][4], bf2[2][4];
            #pragma unroll
            for (int mt = 0; mt < 4; ++mt) {
                const int row = wm * 64 + mt * 16 + a_r;
                const int col = ks * 16 + a_k;
                ldsm4(af[mt][0], af[mt][1], af[mt][2], af[mt][3],
                      aBase + (uint32_t)(row * LDT + col) * 2);
            }
            #pragma unroll
            for (int np2 = 0; np2 < 2; ++np2) {
                const int row = wn * 32 + np2 * 16 + b_r;
                const int col = ks * 16 + b_k;
                ldsm4(bf2[np2][0], bf2[np2][1], bf2[np2][2], bf2[np2][3],
                      bBase + (uint32_t)(row * LDT + col) * 2);
            }
            #pragma unroll
            for (int mt = 0; mt < 4; ++mt)
                #pragma unroll
                for (int nt = 0; nt < 4; ++nt)
                    mma16816(acc[mt][nt], af[mt],
                             bf2[nt >> 1][(nt & 1) * 2], bf2[nt >> 1][(nt & 1) * 2 + 1]);
        }
        __syncthreads();
        if (t < 35) {
            STORE_SMEM(p ^ 1);
            __syncthreads();
            p ^= 1;
        }
    }

    #pragma unroll
    for (int mt = 0; mt < 4; ++mt) {
        const int r0 = rowBase + wm * 64 + mt * 16 + (lane >> 2);
        #pragma unroll
        for (int nt = 0; nt < 4; ++nt) {
            const int c = colBase + wn * 32 + nt * 8 + (lane & 3) * 2;
            const float2 bv = *(const float2*)&bias[c];
            float vx0 = acc[mt][nt][0] + bv.x, vy0 = acc[mt][nt][1] + bv.y;
            float vx1 = acc[mt][nt][2] + bv.x, vy1 = acc[mt][nt][3] + bv.y;
            if (MODE == 0) {
                const int tsel = c / CDIM;
                const int rem  = c - tsel * CDIM;
                const int hh = rem >> 6, d = rem & 63;
                const int m0 = r0, b0 = m0 >> 11, n0 = m0 & 2047;
                const int n1 = n0 + 8;
                if (tsel == 0) { vx0 *= QSCALE; vy0 *= QSCALE; vx1 *= QSCALE; vy1 *= QSCALE; }
                __nv_bfloat16 h00 = bhi(vx0), h01 = bhi(vy0), h10 = bhi(vx1), h11 = bhi(vy1);
                if (tsel < 2) {
                    __nv_bfloat16* dh = tsel ? g_khi : g_qhi;
                    __nv_bfloat16* dl = tsel ? g_klo : g_qlo;
                    const size_t i0 = (((size_t)b0 * HEADS + hh) * SEQ + n0) * DH + d;
                    const size_t i1 = (((size_t)b0 * HEADS + hh) * SEQ + n1) * DH + d;
                    *(__nv_bfloat162*)&dh[i0] = __nv_bfloat162(h00, h01);
                    *(__nv_bfloat162*)&dl[i0] = __nv_bfloat162(blo(vx0, h00), blo(vy0, h01));
                    *(__nv_bfloat162*)&dh[i1] = __nv_bfloat162(h10, h11);
                    *(__nv_bfloat162*)&dl[i1] = __nv_bfloat162(blo(vx1, h10), blo(vy1, h11));
                } else {
                    const size_t tb = (((size_t)b0 * HEADS + hh) * DH + d) * SEQ;
                    g_vthi[tb + n0]       = h00;
                    g_vthi[tb + SEQ + n0] = h01;
                    g_vthi[tb + n1]       = h10;
                    g_vthi[tb + SEQ + n1] = h11;
                    g_vtlo[tb + n0]       = blo(vx0, h00);
                    g_vtlo[tb + SEQ + n0] = blo(vy0, h01);
                    g_vtlo[tb + n1]       = blo(vx1, h10);
                    g_vtlo[tb + SEQ + n1] = blo(vy1, h11);
                }
            } else {
                float2 v0, v1;
                v0.x = vx0; v0.y = vy0; v1.x = vx1; v1.y = vy1;
                *(float2*)&out[(size_t)r0 * CDIM + c] = v0;
                *(float2*)&out[(size_t)(r0 + 8) * CDIM + c] = v1;
            }
        }
    }
    #undef LOAD_GLOBAL
    #undef STORE_SMEM
}

// ---------------------------------------------------------------------------
// HMMA flash attention v4: Q fragments register-resident (staged once through
// buffer 0), P fragments built directly from S accumulators (no smem round
// trip), 64q x 64k tiles, 128 threads, 72KB smem -> 3 CTAs/SM.
// Smem (bf16 elems): 2 x { Khi[64][72], Klo[64][72], VThi[64][72], VTlo[64][72] }
// ---------------------------------------------------------------------------
#define QLD 72
#define MSZ (64 * QLD)          // one 64x72 matrix: 4608 elems
#define BKHI 0
#define BKLO MSZ
#define BVHI (2 * MSZ)
#define BVLO (3 * MSZ)
#define BUFSZ (4 * MSZ)         // 18432 elems
#define ATTN_SMEM (2 * BUFSZ * 2)   // 73728 bytes

__global__ void __launch_bounds__(128, 3)
attn_kernel()
{
    extern __shared__ __nv_bfloat16 sm[];
    const uint32_t smb = smem_u32(sm);

    const int q0 = blockIdx.x * 64;
    const int h  = blockIdx.y;
    const int b  = blockIdx.z;
    const size_t base  = ((size_t)(b * HEADS + h)) * SEQ * DH;   // Q/K layout
    const size_t baseT = ((size_t)(b * HEADS + h)) * DH * SEQ;   // VT layout

    const int tid  = threadIdx.x;
    const int lane = tid & 31;
    const int wrp  = tid >> 5;
    const int wq   = wrp * 16;

    const int a_r = lane & 15;
    const int a_k = (lane >> 4) * 8;
    const int b_r = (lane & 7) + ((lane >> 4) << 3);
    const int b_k = ((lane >> 3) & 1) * 8;
    const int qr  = lane >> 2;
    const int qc  = (lane & 3) * 2;

    // ---- stage Q through buffer 0, extract fragments to registers ----
    uint32_t qh[4][4], ql[4][4];
    {
        #pragma unroll
        for (int i = 0; i < 4; ++i) {
            const int idx = i * 128 + tid;       // 0..511
            const int r = idx >> 3, c8 = idx & 7;
            *(uint4*)&sm[r * QLD + c8 * 8] =
                *(const uint4*)&g_qhi[base + (size_t)(q0 + r) * DH + c8 * 8];
            *(uint4*)&sm[MSZ + r * QLD + c8 * 8] =
                *(const uint4*)&g_qlo[base + (size_t)(q0 + r) * DH + c8 * 8];
        }
        __syncthreads();
        #pragma unroll
        for (int ks = 0; ks < 4; ++ks) {
            ldsm4(qh[ks][0], qh[ks][1], qh[ks][2], qh[ks][3],
                  smb + (uint32_t)((wq + a_r) * QLD + ks * 16 + a_k) * 2);
            ldsm4(ql[ks][0], ql[ks][1], ql[ks][2], ql[ks][3],
                  smb + (uint32_t)(MSZ + (wq + a_r) * QLD + ks * 16 + a_k) * 2);
        }
        __syncthreads();   // Q reads done before cp.async overwrites buffer 0
    }

    #define LOAD_TILE(k0, buf)                                                        \
        do {                                                                          \
            const uint32_t _bb = smb + (uint32_t)((buf) * BUFSZ) * 2;                 \
            const __nv_bfloat16* _kh = g_khi + base + (size_t)(k0) * DH;              \
            const __nv_bfloat16* _kl = g_klo + base + (size_t)(k0) * DH;              \
            const __nv_bfloat16* _vh = g_vthi + baseT + (k0);                         \
            const __nv_bfloat16* _vl = g_vtlo + baseT + (k0);                         \
            _Pragma("unroll")                                                         \
            for (int _i = 0; _i < 4; ++_i) {                                          \
                const int _idx = _i * 128 + tid;                                      \
                const int _r = _idx >> 3, _c = _idx & 7;                              \
                CP_ASYNC16(_bb + (uint32_t)(BKHI + _r * QLD + _c * 8) * 2,            \
                           _kh + _r * 64 + _c * 8);                                   \
                CP_ASYNC16(_bb + (uint32_t)(BKLO + _r * QLD + _c * 8) * 2,            \
                           _kl + _r * 64 + _c * 8);                                   \
                CP_ASYNC16(_bb + (uint32_t)(BVHI + _r * QLD + _c * 8) * 2,            \
                           _vh + (size_t)_r * SEQ + _c * 8);                          \
                CP_ASYNC16(_bb + (uint32_t)(BVLO + _r * QLD + _c * 8) * 2,            \
                           _vl + (size_t)_r * SEQ + _c * 8);                          \
            }                                                                         \
        } while (0)

    LOAD_TILE(0, 0);
    CP_COMMIT();

    float m_i[2] = {-1e30f, -1e30f};
    float l_i[2] = {0.f, 0.f};
    float oacc[8][4] = {};

    for (int t = 0; t < 32; ++t) {
        const int buf = t & 1;
        __syncthreads();   // all warps done reading buf^1
        if (t < 31) {
            LOAD_TILE((t + 1) * 64, buf ^ 1);
            CP_COMMIT();
            CP_WAIT1();
        } else {
            CP_WAIT0();
        }
        __syncthreads();   // tile t visible

        const uint32_t kh = smb + (uint32_t)(buf * BUFSZ + BKHI) * 2;
        const uint32_t kl = smb + (uint32_t)(buf * BUFSZ + BKLO) * 2;
        const uint32_t vh = smb + (uint32_t)(buf * BUFSZ + BVHI) * 2;
        const uint32_t vl = smb + (uint32_t)(buf * BUFSZ + BVLO) * 2;

        // ---- S = QK^T : (Qhi+Qlo)*Khi, then Qhi*Klo (Q frags in registers) ----
        float sacc[8][4] = {};
        #pragma unroll
        for (int ks = 0; ks < 4; ++ks) {
            #pragma unroll
            for (int ng = 0; ng < 4; ++ng) {
                uint32_t bf[4];
                ldsm4(bf[0], bf[1], bf[2], bf[3],
                      kh + (uint32_t)((ng * 16 + b_r) * QLD + ks * 16 + b_k) * 2);
                mma16816(sacc[ng * 2 + 0], qh[ks], bf[0], bf[1]);
                mma16816(sacc[ng * 2 + 1], qh[ks], bf[2], bf[3]);
                mma16816(sacc[ng * 2 + 0], ql[ks], bf[0], bf[1]);
                mma16816(sacc[ng * 2 + 1], ql[ks], bf[2], bf[3]);
            }
        }
        #pragma unroll
        for (int ks = 0; ks < 4; ++ks) {
            #pragma unroll
            for (int ng = 0; ng < 4; ++ng) {
                uint32_t bf[4];
                ldsm4(bf[0], bf[1], bf[2], bf[3],
                      kl + (uint32_t)((ng * 16 + b_r) * QLD + ks * 16 + b_k) * 2);
                mma16816(sacc[ng * 2 + 0], qh[ks], bf[0], bf[1]);
                mma16816(sacc[ng * 2 + 1], qh[ks], bf[2], bf[3]);
            }
        }

        // ---- online softmax in exp2 domain (warp-local rows qr, qr+8) ----
        #pragma unroll
        for (int ri = 0; ri < 2; ++ri) {
            float mx = -1e30f;
            #pragma unroll
            for (int nt = 0; nt < 8; ++nt) {
                mx = fmaxf(mx, sacc[nt][ri * 2 + 0]);
                mx = fmaxf(mx, sacc[nt][ri * 2 + 1]);
            }
            mx = fmaxf(mx, __shfl_xor_sync(0xffffffffu, mx, 1));
            mx = fmaxf(mx, __shfl_xor_sync(0xffffffffu, mx, 2));
            const float mn = fmaxf(m_i[ri], mx);
            const float alpha = ex2f(m_i[ri] - mn);
            m_i[ri] = mn;
            float r = 0.f;
            #pragma unroll
            for (int nt = 0; nt < 8; ++nt) {
                float p0 = ex2f(sacc[nt][ri * 2 + 0] - mn);
                float p1 = ex2f(sacc[nt][ri * 2 + 1] - mn);
                sacc[nt][ri * 2 + 0] = p0;
                sacc[nt][ri * 2 + 1] = p1;
                r += p0 + p1;
            }
            r += __shfl_xor_sync(0xffffffffu, r, 1);
            r += __shfl_xor_sync(0xffffffffu, r, 2);
            l_i[ri] = l_i[ri] * alpha + r;
            #pragma unroll
            for (int nt = 0; nt < 8; ++nt) {
                oacc[nt][ri * 2 + 0] *= alpha;
                oacc[nt][ri * 2 + 1] *= alpha;
            }
        }

        // ---- PV: P fragments direct from sacc (no smem). O += Phi(Vhi+Vlo)+PloVhi ----
        #pragma unroll
        for (int ks = 0; ks < 4; ++ks) {
            // A-fragment (m16k16) for k-cols ks*16..+15 from S accumulator tiles 2ks, 2ks+1
            uint32_t ph[4], pl[4];
            {
                const float s00 = sacc[2 * ks][0],     s01 = sacc[2 * ks][1];
                const float s02 = sacc[2 * ks][2],     s03 = sacc[2 * ks][3];
                const float s10 = sacc[2 * ks + 1][0], s11 = sacc[2 * ks + 1][1];
                const float s12 = sacc[2 * ks + 1][2], s13 = sacc[2 * ks + 1][3];
                ph[0] = packbf(s00, s01);
                ph[1] = packbf(s02, s03);
                ph[2] = packbf(s10, s11);
                ph[3] = packbf(s12, s13);
                __nv_bfloat16 h00 = bhi(s00), h01 = bhi(s01), h02 = bhi(s02), h03 = bhi(s03);
                __nv_bfloat16 h10 = bhi(s10), h11 = bhi(s11), h12 = bhi(s12), h13 = bhi(s13);
                pl[0] = packbf(s00 - __bfloat162float(h00), s01 - __bfloat162float(h01));
                pl[1] = packbf(s02 - __bfloat162float(h02), s03 - __bfloat162float(h03));
                pl[2] = packbf(s10 - __bfloat162float(h10), s11 - __bfloat162float(h11));
                pl[3] = packbf(s12 - __bfloat162float(h12), s13 - __bfloat162float(h13));
            }
            #pragma unroll
            for (int ng = 0; ng < 4; ++ng) {
                uint32_t bh[4], bl[4];
                ldsm4(bh[0], bh[1], bh[2], bh[3],
                      vh + (uint32_t)((ng * 16 + b_r) * QLD + ks * 16 + b_k) * 2);
                ldsm4(bl[0], bl[1], bl[2], bl[3],
                      vl + (uint32_t)((ng * 16 + b_r) * QLD + ks * 16 + b_k) * 2);
                mma16816(oacc[ng * 2 + 0], ph, bh[0], bh[1]);
                mma16816(oacc[ng * 2 + 1], ph, bh[2], bh[3]);
                mma16816(oacc[ng * 2 + 0], ph, bl[0], bl[1]);
                mma16816(oacc[ng * 2 + 1], ph, bl[2], bl[3]);
                mma16816(oacc[ng * 2 + 0], pl, bh[0], bh[1]);
                mma16816(oacc[ng * 2 + 1], pl, bh[2], bh[3]);
            }
        }
    }

    // ---- epilogue: normalize, split hi/lo, write a_hi/a_lo [B,N,C] ----
    const float inv0 = 1.f / l_i[0];
    const float inv1 = 1.f / l_i[1];
    const int row0 = q0 + wq + qr;
    #pragma unroll
    for (int nt = 0; nt < 8; ++nt) {
        const int col = h * DH + nt * 8 + qc;
        const size_t i0 = ((size_t)b * SEQ + row0) * CDIM + col;
        const size_t i1 = ((size_t)b * SEQ + row0 + 8) * CDIM + col;
        float o00 = oacc[nt][0] * inv0, o01 = oacc[nt][1] * inv0;
        float o10 = oacc[nt][2] * inv1, o11 = oacc[nt][3] * inv1;
        __nv_bfloat16 h00 = bhi(o00), h01 = bhi(o01), h10 = bhi(o10), h11 = bhi(o11);
        *(__nv_bfloat162*)&g_a_hi[i0] = __nv_bfloat162(h00, h01);
        *(__nv_bfloat162*)&g_a_lo[i0] = __nv_bfloat162(blo(o00, h00), blo(o01, h01));
        *(__nv_bfloat162*)&g_a_hi[i1] = __nv_bfloat162(h10, h11);
        *(__nv_bfloat162*)&g_a_lo[i1] = __nv_bfloat162(blo(o10, h10), blo(o11, h11));
    }
    #undef LOAD_TILE
}

// ---------------------------------------------------------------------------
extern "C" void kernel_launch(void* const* d_in, const int* in_sizes, int n_in,
                              void* d_out, int out_size)
{
    const float* x      = (const float*)d_in[0];
    const float* qkv_w  = (const float*)d_in[1];
    const float* qkv_b  = (const float*)d_in[2];
    const float* proj_w = (const float*)d_in[3];
    const float* proj_b = (const float*)d_in[4];
    float* out = (float*)d_out;

    cudaFuncSetAttribute(mma_gemm<0>, cudaFuncAttributeMaxDynamicSharedMemorySize, GEMM_SMEM);
    cudaFuncSetAttribute(mma_gemm<1>, cudaFuncAttributeMaxDynamicSharedMemorySize, GEMM_SMEM);
    cudaFuncSetAttribute(attn_kernel, cudaFuncAttributeMaxDynamicSharedMemorySize, ATTN_SMEM);

    __nv_bfloat16 *a_hi, *a_lo, *w_hi, *w_lo;
    cudaGetSymbolAddress((void**)&a_hi, g_a_hi);
    cudaGetSymbolAddress((void**)&a_lo, g_a_lo);
    cudaGetSymbolAddress((void**)&w_hi, g_w_hi);
    cudaGetSymbolAddress((void**)&w_lo, g_w_lo);

    const int nx4 = MTOT * CDIM / 4;
    const int nw4 = 3 * CDIM * CDIM / 4;
    const int np4 = CDIM * CDIM / 4;

    split_kernel<<<(nx4 + 255) / 256, 256>>>((const float4*)x,
        (__nv_bfloat162*)a_hi, (__nv_bfloat162*)a_lo, nx4);
    split_kernel<<<(nw4 + 255) / 256, 256>>>((const float4*)qkv_w,
        (__nv_bfloat162*)w_hi, (__nv_bfloat162*)w_lo, nw4);

    mma_gemm<0><<<dim3(18, 64), 256, GEMM_SMEM>>>(a_hi, a_lo, w_hi, w_lo, qkv_b, nullptr);

    attn_kernel<<<dim3(SEQ / 64, HEADS, BATCH), 128, ATTN_SMEM>>>();

    split_kernel<<<(np4 + 255) / 256, 256>>>((const float4*)proj_w,
        (__nv_bfloat162*)w_hi, (__nv_bfloat162*)w_lo, np4);
    mma_gemm<1><<<dim3(6, 64), 256, GEMM_SMEM>>>(a_hi, a_lo, w_hi, w_lo, proj_b, out);
}

// round 9
// speedup vs baseline: 3.3201x; 1.0233x over previous
#include <cuda_runtime.h>
#include <cuda_bf16.h>
#include <cstdint>

#define HEADS 12
#define SEQ   2048
#define BATCH 4
#define DH    64
#define CDIM  768
#define MTOT  8192   // BATCH*SEQ
#define NQKV ((size_t)BATCH * HEADS * SEQ * DH)

// ---------------- scratch (allocation-free) ----------------
__device__ __align__(16) __nv_bfloat16 g_qhi[NQKV], g_qlo[NQKV];
__device__ __align__(16) __nv_bfloat16 g_khi[NQKV], g_klo[NQKV];
__device__ __align__(16) __nv_bfloat16 g_vthi[NQKV], g_vtlo[NQKV];
__device__ __align__(16) __nv_bfloat16 g_a_hi[(size_t)MTOT * CDIM];
__device__ __align__(16) __nv_bfloat16 g_a_lo[(size_t)MTOT * CDIM];
__device__ __align__(16) __nv_bfloat16 g_w_hi[(size_t)3 * CDIM * CDIM];
__device__ __align__(16) __nv_bfloat16 g_w_lo[(size_t)3 * CDIM * CDIM];

// Q prescale: 1/sqrt(64) * log2(e)  (softmax runs in exp2 domain)
#define QSCALE 0.1803368801111204f

// ---------------- helpers ----------------
__device__ __forceinline__ uint32_t smem_u32(const void* p) {
    uint32_t a;
    asm("{ .reg .u64 t; cvta.to.shared.u64 t, %1; cvt.u32.u64 %0, t; }" : "=r"(a) : "l"(p));
    return a;
}
__device__ __forceinline__ void ldsm4(uint32_t& r0, uint32_t& r1, uint32_t& r2, uint32_t& r3,
                                      uint32_t addr) {
    asm volatile("ldmatrix.sync.aligned.m8n8.x4.shared.b16 {%0,%1,%2,%3}, [%4];"
                 : "=r"(r0), "=r"(r1), "=r"(r2), "=r"(r3) : "r"(addr));
}
__device__ __forceinline__ void mma16816(float* c, const uint32_t* a, uint32_t b0, uint32_t b1) {
    asm volatile("mma.sync.aligned.m16n8k16.row.col.f32.bf16.bf16.f32 "
                 "{%0,%1,%2,%3}, {%4,%5,%6,%7}, {%8,%9}, {%0,%1,%2,%3};"
                 : "+f"(c[0]), "+f"(c[1]), "+f"(c[2]), "+f"(c[3])
                 : "r"(a[0]), "r"(a[1]), "r"(a[2]), "r"(a[3]), "r"(b0), "r"(b1));
}
__device__ __forceinline__ __nv_bfloat16 bhi(float x) { return __float2bfloat16(x); }
__device__ __forceinline__ __nv_bfloat16 blo(float x, __nv_bfloat16 h) {
    return __float2bfloat16(x - __bfloat162float(h));
}
__device__ __forceinline__ float ex2f(float x) {
    float y;
    asm("ex2.approx.f32 %0, %1;" : "=f"(y) : "f"(x));
    return y;
}
__device__ __forceinline__ uint32_t packbf(float lo_, float hi_) {
    uint32_t r;
    asm("cvt.rn.bf16x2.f32 %0, %1, %2;" : "=r"(r) : "f"(hi_), "f"(lo_));
    return r;
}

#define CP_ASYNC16(dst, src) \
    asm volatile("cp.async.cg.shared.global [%0], [%1], 16;" :: "r"(dst), "l"(src))
#define CP_COMMIT() asm volatile("cp.async.commit_group;")
#define CP_WAIT1()  asm volatile("cp.async.wait_group 1;")
#define CP_WAIT0()  asm volatile("cp.async.wait_group 0;")

// ---------------------------------------------------------------------------
__global__ void split_kernel(const float4* __restrict__ src,
                             __nv_bfloat162* __restrict__ hi,
                             __nv_bfloat162* __restrict__ lo, int n4)
{
    int i = blockIdx.x * 256 + threadIdx.x;
    if (i < n4) {
        float4 v = src[i];
        __nv_bfloat16 hx = __float2bfloat16(v.x);
        __nv_bfloat16 hy = __float2bfloat16(v.y);
        __nv_bfloat16 hz = __float2bfloat16(v.z);
        __nv_bfloat16 hw = __float2bfloat16(v.w);
        hi[2 * i]     = __nv_bfloat162(hx, hy);
        hi[2 * i + 1] = __nv_bfloat162(hz, hw);
        lo[2 * i]     = __nv_bfloat162(blo(v.x, hx), blo(v.y, hy));
        lo[2 * i + 1] = __nv_bfloat162(blo(v.z, hz), blo(v.w, hw));
    }
}

// ---------------------------------------------------------------------------
// HMMA bf16x3 GEMM v2: single K sweep, Ahi/Alo/Whi/Wlo staged together per
// 32-wide chunk, all 3 error-comp products issued per fragment load.
// CTA 128x128, 256 threads (8 warps, 2m x 4n), cp.async double-buffered,
// LDT2=40 padding (conflict-free ldsm). 80KB smem -> 2 CTAs/SM.
// MODE 0: split epilogue -> Q(prescaled)/K/VT; MODE 1: fp32 row-major.
// ---------------------------------------------------------------------------
#define LDT2 40
#define GM_MSZ (128 * LDT2)            // 5120 elems per matrix
#define GAHI 0
#define GALO GM_MSZ
#define GWHI (2 * GM_MSZ)
#define GWLO (3 * GM_MSZ)
#define GM_BUF (4 * GM_MSZ)            // 20480 elems
#define GEMM_SMEM (2 * GM_BUF * 2)     // 81920 bytes
#define NCHUNK 24                      // 768 / 32

template <int MODE>
__global__ void __launch_bounds__(256, 2)
mma_gemm(const __nv_bfloat16* __restrict__ a_hi, const __nv_bfloat16* __restrict__ a_lo,
         const __nv_bfloat16* __restrict__ w_hi, const __nv_bfloat16* __restrict__ w_lo,
         const float* __restrict__ bias, float* __restrict__ out)
{
    extern __shared__ __nv_bfloat16 sm[];
    const uint32_t smb = smem_u32(sm);
    const int tid  = threadIdx.x;
    const int lane = tid & 31;
    const int wrp  = tid >> 5;
    const int wm   = wrp & 1;
    const int wn   = wrp >> 1;
    const int rowBase = blockIdx.y * 128;
    const int colBase = blockIdx.x * 128;

    const int a_r = lane & 15;
    const int a_k = (lane >> 4) * 8;
    const int b_r = (lane & 7) + ((lane >> 4) << 3);
    const int b_k = ((lane >> 3) & 1) * 8;

    float acc[4][4][4] = {};

    // per-chunk cp.async: 128 rows x 4 16B-chunks per matrix, 2 iters x 256 thr
    #define LOAD_CHUNK(kk, buf)                                                       \
        do {                                                                          \
            const uint32_t _bb = smb + (uint32_t)((buf) * GM_BUF) * 2;                \
            _Pragma("unroll")                                                         \
            for (int _i = 0; _i < 2; ++_i) {                                          \
                const int _idx = _i * 256 + tid;                                      \
                const int _r = _idx >> 2, _c = _idx & 3;                              \
                const size_t _ga = (size_t)(rowBase + _r) * CDIM + (kk) + _c * 8;     \
                const size_t _gw = (size_t)(colBase + _r) * CDIM + (kk) + _c * 8;     \
                const uint32_t _so = (uint32_t)(_r * LDT2 + _c * 8) * 2;              \
                CP_ASYNC16(_bb + GAHI * 2 + _so, a_hi + _ga);                         \
                CP_ASYNC16(_bb + GALO * 2 + _so, a_lo + _ga);                         \
                CP_ASYNC16(_bb + GWHI * 2 + _so, w_hi + _gw);                         \
                CP_ASYNC16(_bb + GWLO * 2 + _so, w_lo + _gw);                         \
            }                                                                         \
        } while (0)

    LOAD_CHUNK(0, 0);
    CP_COMMIT();

    for (int t = 0; t < NCHUNK; ++t) {
        const int buf = t & 1;
        __syncthreads();               // consumers of buf^1 done
        if (t < NCHUNK - 1) {
            LOAD_CHUNK((t + 1) * 32, buf ^ 1);
            CP_COMMIT();
            CP_WAIT1();
        } else {
            CP_WAIT0();
        }
        __syncthreads();               // chunk t visible

        const uint32_t ahB = smb + (uint32_t)(buf * GM_BUF + GAHI) * 2;
        const uint32_t alB = smb + (uint32_t)(buf * GM_BUF + GALO) * 2;
        const uint32_t whB = smb + (uint32_t)(buf * GM_BUF + GWHI) * 2;
        const uint32_t wlB = smb + (uint32_t)(buf * GM_BUF + GWLO) * 2;

        #pragma unroll
        for (int ks = 0; ks < 2; ++ks) {
            uint32_t ah[4][4], al[4][4], wh2[2][4], wl2[2][4];
            #pragma unroll
            for (int mt = 0; mt < 4; ++mt) {
                const uint32_t off =
                    (uint32_t)((wm * 64 + mt * 16 + a_r) * LDT2 + ks * 16 + a_k) * 2;
                ldsm4(ah[mt][0], ah[mt][1], ah[mt][2], ah[mt][3], ahB + off);
                ldsm4(al[mt][0], al[mt][1], al[mt][2], al[mt][3], alB + off);
            }
            #pragma unroll
            for (int np2 = 0; np2 < 2; ++np2) {
                const uint32_t off =
                    (uint32_t)((wn * 32 + np2 * 16 + b_r) * LDT2 + ks * 16 + b_k) * 2;
                ldsm4(wh2[np2][0], wh2[np2][1], wh2[np2][2], wh2[np2][3], whB + off);
                ldsm4(wl2[np2][0], wl2[np2][1], wl2[np2][2], wl2[np2][3], wlB + off);
            }
            #pragma unroll
            for (int mt = 0; mt < 4; ++mt)
                #pragma unroll
                for (int nt = 0; nt < 4; ++nt) {
                    const uint32_t bh0 = wh2[nt >> 1][(nt & 1) * 2];
                    const uint32_t bh1 = wh2[nt >> 1][(nt & 1) * 2 + 1];
                    const uint32_t bl0 = wl2[nt >> 1][(nt & 1) * 2];
                    const uint32_t bl1 = wl2[nt >> 1][(nt & 1) * 2 + 1];
                    mma16816(acc[mt][nt], ah[mt], bh0, bh1);
                    mma16816(acc[mt][nt], al[mt], bh0, bh1);
                    mma16816(acc[mt][nt], ah[mt], bl0, bl1);
                }
        }
    }
    #undef LOAD_CHUNK

    #pragma unroll
    for (int mt = 0; mt < 4; ++mt) {
        const int r0 = rowBase + wm * 64 + mt * 16 + (lane >> 2);
        #pragma unroll
        for (int nt = 0; nt < 4; ++nt) {
            const int c = colBase + wn * 32 + nt * 8 + (lane & 3) * 2;
            const float2 bv = *(const float2*)&bias[c];
            float vx0 = acc[mt][nt][0] + bv.x, vy0 = acc[mt][nt][1] + bv.y;
            float vx1 = acc[mt][nt][2] + bv.x, vy1 = acc[mt][nt][3] + bv.y;
            if (MODE == 0) {
                const int tsel = c / CDIM;
                const int rem  = c - tsel * CDIM;
                const int hh = rem >> 6, d = rem & 63;
                const int m0 = r0, b0 = m0 >> 11, n0 = m0 & 2047;
                const int n1 = n0 + 8;
                if (tsel == 0) { vx0 *= QSCALE; vy0 *= QSCALE; vx1 *= QSCALE; vy1 *= QSCALE; }
                __nv_bfloat16 h00 = bhi(vx0), h01 = bhi(vy0), h10 = bhi(vx1), h11 = bhi(vy1);
                if (tsel < 2) {
                    __nv_bfloat16* dh = tsel ? g_khi : g_qhi;
                    __nv_bfloat16* dl = tsel ? g_klo : g_qlo;
                    const size_t i0 = (((size_t)b0 * HEADS + hh) * SEQ + n0) * DH + d;
                    const size_t i1 = (((size_t)b0 * HEADS + hh) * SEQ + n1) * DH + d;
                    *(__nv_bfloat162*)&dh[i0] = __nv_bfloat162(h00, h01);
                    *(__nv_bfloat162*)&dl[i0] = __nv_bfloat162(blo(vx0, h00), blo(vy0, h01));
                    *(__nv_bfloat162*)&dh[i1] = __nv_bfloat162(h10, h11);
                    *(__nv_bfloat162*)&dl[i1] = __nv_bfloat162(blo(vx1, h10), blo(vy1, h11));
                } else {
                    const size_t tb = (((size_t)b0 * HEADS + hh) * DH + d) * SEQ;
                    g_vthi[tb + n0]       = h00;
                    g_vthi[tb + SEQ + n0] = h01;
                    g_vthi[tb + n1]       = h10;
                    g_vthi[tb + SEQ + n1] = h11;
                    g_vtlo[tb + n0]       = blo(vx0, h00);
                    g_vtlo[tb + SEQ + n0] = blo(vy0, h01);
                    g_vtlo[tb + n1]       = blo(vx1, h10);
                    g_vtlo[tb + SEQ + n1] = blo(vy1, h11);
                }
            } else {
                float2 v0, v1;
                v0.x = vx0; v0.y = vy0; v1.x = vx1; v1.y = vy1;
                *(float2*)&out[(size_t)r0 * CDIM + c] = v0;
                *(float2*)&out[(size_t)(r0 + 8) * CDIM + c] = v1;
            }
        }
    }
}

// ---------------------------------------------------------------------------
// HMMA flash attention v4 (unchanged from round 8): Q fragments register-
// resident, P fragments direct from S accumulators, 64q x 64k tiles,
// 128 threads, 72KB smem -> 3 CTAs/SM.
// ---------------------------------------------------------------------------
#define QLD 72
#define MSZ (64 * QLD)
#define BKHI 0
#define BKLO MSZ
#define BVHI (2 * MSZ)
#define BVLO (3 * MSZ)
#define BUFSZ (4 * MSZ)
#define ATTN_SMEM (2 * BUFSZ * 2)   // 73728 bytes

__global__ void __launch_bounds__(128, 3)
attn_kernel()
{
    extern __shared__ __nv_bfloat16 sm[];
    const uint32_t smb = smem_u32(sm);

    const int q0 = blockIdx.x * 64;
    const int h  = blockIdx.y;
    const int b  = blockIdx.z;
    const size_t base  = ((size_t)(b * HEADS + h)) * SEQ * DH;
    const size_t baseT = ((size_t)(b * HEADS + h)) * DH * SEQ;

    const int tid  = threadIdx.x;
    const int lane = tid & 31;
    const int wrp  = tid >> 5;
    const int wq   = wrp * 16;

    const int a_r = lane & 15;
    const int a_k = (lane >> 4) * 8;
    const int b_r = (lane & 7) + ((lane >> 4) << 3);
    const int b_k = ((lane >> 3) & 1) * 8;
    const int qr  = lane >> 2;
    const int qc  = (lane & 3) * 2;

    uint32_t qh[4][4], ql[4][4];
    {
        #pragma unroll
        for (int i = 0; i < 4; ++i) {
            const int idx = i * 128 + tid;
            const int r = idx >> 3, c8 = idx & 7;
            *(uint4*)&sm[r * QLD + c8 * 8] =
                *(const uint4*)&g_qhi[base + (size_t)(q0 + r) * DH + c8 * 8];
            *(uint4*)&sm[MSZ + r * QLD + c8 * 8] =
                *(const uint4*)&g_qlo[base + (size_t)(q0 + r) * DH + c8 * 8];
        }
        __syncthreads();
        #pragma unroll
        for (int ks = 0; ks < 4; ++ks) {
            ldsm4(qh[ks][0], qh[ks][1], qh[ks][2], qh[ks][3],
                  smb + (uint32_t)((wq + a_r) * QLD + ks * 16 + a_k) * 2);
            ldsm4(ql[ks][0], ql[ks][1], ql[ks][2], ql[ks][3],
                  smb + (uint32_t)(MSZ + (wq + a_r) * QLD + ks * 16 + a_k) * 2);
        }
        __syncthreads();
    }

    #define LOAD_TILE(k0, buf)                                                        \
        do {                                                                          \
            const uint32_t _bb = smb + (uint32_t)((buf) * BUFSZ) * 2;                 \
            const __nv_bfloat16* _kh = g_khi + base + (size_t)(k0) * DH;              \
            const __nv_bfloat16* _kl = g_klo + base + (size_t)(k0) * DH;              \
            const __nv_bfloat16* _vh = g_vthi + baseT + (k0);                         \
            const __nv_bfloat16* _vl = g_vtlo + baseT + (k0);                         \
            _Pragma("unroll")                                                         \
            for (int _i = 0; _i < 4; ++_i) {                                          \
                const int _idx = _i * 128 + tid;                                      \
                const int _r = _idx >> 3, _c = _idx & 7;                              \
                CP_ASYNC16(_bb + (uint32_t)(BKHI + _r * QLD + _c * 8) * 2,            \
                           _kh + _r * 64 + _c * 8);                                   \
                CP_ASYNC16(_bb + (uint32_t)(BKLO + _r * QLD + _c * 8) * 2,            \
                           _kl + _r * 64 + _c * 8);                                   \
                CP_ASYNC16(_bb + (uint32_t)(BVHI + _r * QLD + _c * 8) * 2,            \
                           _vh + (size_t)_r * SEQ + _c * 8);                          \
                CP_ASYNC16(_bb + (uint32_t)(BVLO + _r * QLD + _c * 8) * 2,            \
                           _vl + (size_t)_r * SEQ + _c * 8);                          \
            }                                                                         \
        } while (0)

    LOAD_TILE(0, 0);
    CP_COMMIT();

    float m_i[2] = {-1e30f, -1e30f};
    float l_i[2] = {0.f, 0.f};
    float oacc[8][4] = {};

    for (int t = 0; t < 32; ++t) {
        const int buf = t & 1;
        __syncthreads();
        if (t < 31) {
            LOAD_TILE((t + 1) * 64, buf ^ 1);
            CP_COMMIT();
            CP_WAIT1();
        } else {
            CP_WAIT0();
        }
        __syncthreads();

        const uint32_t kh = smb + (uint32_t)(buf * BUFSZ + BKHI) * 2;
        const uint32_t kl = smb + (uint32_t)(buf * BUFSZ + BKLO) * 2;
        const uint32_t vh = smb + (uint32_t)(buf * BUFSZ + BVHI) * 2;
        const uint32_t vl = smb + (uint32_t)(buf * BUFSZ + BVLO) * 2;

        float sacc[8][4] = {};
        #pragma unroll
        for (int ks = 0; ks < 4; ++ks) {
            #pragma unroll
            for (int ng = 0; ng < 4; ++ng) {
                uint32_t bf[4];
                ldsm4(bf[0], bf[1], bf[2], bf[3],
                      kh + (uint32_t)((ng * 16 + b_r) * QLD + ks * 16 + b_k) * 2);
                mma16816(sacc[ng * 2 + 0], qh[ks], bf[0], bf[1]);
                mma16816(sacc[ng * 2 + 1], qh[ks], bf[2], bf[3]);
                mma16816(sacc[ng * 2 + 0], ql[ks], bf[0], bf[1]);
                mma16816(sacc[ng * 2 + 1], ql[ks], bf[2], bf[3]);
            }
        }
        #pragma unroll
        for (int ks = 0; ks < 4; ++ks) {
            #pragma unroll
            for (int ng = 0; ng < 4; ++ng) {
                uint32_t bf[4];
                ldsm4(bf[0], bf[1], bf[2], bf[3],
                      kl + (uint32_t)((ng * 16 + b_r) * QLD + ks * 16 + b_k) * 2);
                mma16816(sacc[ng * 2 + 0], qh[ks], bf[0], bf[1]);
                mma16816(sacc[ng * 2 + 1], qh[ks], bf[2], bf[3]);
            }
        }

        #pragma unroll
        for (int ri = 0; ri < 2; ++ri) {
            float mx = -1e30f;
            #pragma unroll
            for (int nt = 0; nt < 8; ++nt) {
                mx = fmaxf(mx, sacc[nt][ri * 2 + 0]);
                mx = fmaxf(mx, sacc[nt][ri * 2 + 1]);
            }
            mx = fmaxf(mx, __shfl_xor_sync(0xffffffffu, mx, 1));
            mx = fmaxf(mx, __shfl_xor_sync(0xffffffffu, mx, 2));
            const float mn = fmaxf(m_i[ri], mx);
            const float alpha = ex2f(m_i[ri] - mn);
            m_i[ri] = mn;
            float r = 0.f;
            #pragma unroll
            for (int nt = 0; nt < 8; ++nt) {
                float p0 = ex2f(sacc[nt][ri * 2 + 0] - mn);
                float p1 = ex2f(sacc[nt][ri * 2 + 1] - mn);
                sacc[nt][ri * 2 + 0] = p0;
                sacc[nt][ri * 2 + 1] = p1;
                r += p0 + p1;
            }
            r += __shfl_xor_sync(0xffffffffu, r, 1);
            r += __shfl_xor_sync(0xffffffffu, r, 2);
            l_i[ri] = l_i[ri] * alpha + r;
            #pragma unroll
            for (int nt = 0; nt < 8; ++nt) {
                oacc[nt][ri * 2 + 0] *= alpha;
                oacc[nt][ri * 2 + 1] *= alpha;
            }
        }

        #pragma unroll
        for (int ks = 0; ks < 4; ++ks) {
            uint32_t ph[4], pl[4];
            {
                const float s00 = sacc[2 * ks][0],     s01 = sacc[2 * ks][1];
                const float s02 = sacc[2 * ks][2],     s03 = sacc[2 * ks][3];
                const float s10 = sacc[2 * ks + 1][0], s11 = sacc[2 * ks + 1][1];
                const float s12 = sacc[2 * ks + 1][2], s13 = sacc[2 * ks + 1][3];
                ph[0] = packbf(s00, s01);
                ph[1] = packbf(s02, s03);
                ph[2] = packbf(s10, s11);
                ph[3] = packbf(s12, s13);
                __nv_bfloat16 h00 = bhi(s00), h01 = bhi(s01), h02 = bhi(s02), h03 = bhi(s03);
                __nv_bfloat16 h10 = bhi(s10), h11 = bhi(s11), h12 = bhi(s12), h13 = bhi(s13);
                pl[0] = packbf(s00 - __bfloat162float(h00), s01 - __bfloat162float(h01));
                pl[1] = packbf(s02 - __bfloat162float(h02), s03 - __bfloat162float(h03));
                pl[2] = packbf(s10 - __bfloat162float(h10), s11 - __bfloat162float(h11));
                pl[3] = packbf(s12 - __bfloat162float(h12), s13 - __bfloat162float(h13));
            }
            #pragma unroll
            for (int ng = 0; ng < 4; ++ng) {
                uint32_t bh[4], bl[4];
                ldsm4(bh[0], bh[1], bh[2], bh[3],
                      vh + (uint32_t)((ng * 16 + b_r) * QLD + ks * 16 + b_k) * 2);
                ldsm4(bl[0], bl[1], bl[2], bl[3],
                      vl + (uint32_t)((ng * 16 + b_r) * QLD + ks * 16 + b_k) * 2);
                mma16816(oacc[ng * 2 + 0], ph, bh[0], bh[1]);
                mma16816(oacc[ng * 2 + 1], ph, bh[2], bh[3]);
                mma16816(oacc[ng * 2 + 0], ph, bl[0], bl[1]);
                mma16816(oacc[ng * 2 + 1], ph, bl[2], bl[3]);
                mma16816(oacc[ng * 2 + 0], pl, bh[0], bh[1]);
                mma16816(oacc[ng * 2 + 1], pl, bh[2], bh[3]);
            }
        }
    }

    const float inv0 = 1.f / l_i[0];
    const float inv1 = 1.f / l_i[1];
    const int row0 = q0 + wq + qr;
    #pragma unroll
    for (int nt = 0; nt < 8; ++nt) {
        const int col = h * DH + nt * 8 + qc;
        const size_t i0 = ((size_t)b * SEQ + row0) * CDIM + col;
        const size_t i1 = ((size_t)b * SEQ + row0 + 8) * CDIM + col;
        float o00 = oacc[nt][0] * inv0, o01 = oacc[nt][1] * inv0;
        float o10 = oacc[nt][2] * inv1, o11 = oacc[nt][3] * inv1;
        __nv_bfloat16 h00 = bhi(o00), h01 = bhi(o01), h10 = bhi(o10), h11 = bhi(o11);
        *(__nv_bfloat162*)&g_a_hi[i0] = __nv_bfloat162(h00, h01);
        *(__nv_bfloat162*)&g_a_lo[i0] = __nv_bfloat162(blo(o00, h00), blo(o01, h01));
        *(__nv_bfloat162*)&g_a_hi[i1] = __nv_bfloat162(h10, h11);
        *(__nv_bfloat162*)&g_a_lo[i1] = __nv_bfloat162(blo(o10, h10), blo(o11, h11));
    }
    #undef LOAD_TILE
}

// ---------------------------------------------------------------------------
extern "C" void kernel_launch(void* const* d_in, const int* in_sizes, int n_in,
                              void* d_out, int out_size)
{
    const float* x      = (const float*)d_in[0];
    const float* qkv_w  = (const float*)d_in[1];
    const float* qkv_b  = (const float*)d_in[2];
    const float* proj_w = (const float*)d_in[3];
    const float* proj_b = (const float*)d_in[4];
    float* out = (float*)d_out;

    cudaFuncSetAttribute(mma_gemm<0>, cudaFuncAttributeMaxDynamicSharedMemorySize, GEMM_SMEM);
    cudaFuncSetAttribute(mma_gemm<1>, cudaFuncAttributeMaxDynamicSharedMemorySize, GEMM_SMEM);
    cudaFuncSetAttribute(attn_kernel, cudaFuncAttributeMaxDynamicSharedMemorySize, ATTN_SMEM);

    __nv_bfloat16 *a_hi, *a_lo, *w_hi, *w_lo;
    cudaGetSymbolAddress((void**)&a_hi, g_a_hi);
    cudaGetSymbolAddress((void**)&a_lo, g_a_lo);
    cudaGetSymbolAddress((void**)&w_hi, g_w_hi);
    cudaGetSymbolAddress((void**)&w_lo, g_w_lo);

    const int nx4 = MTOT * CDIM / 4;
    const int nw4 = 3 * CDIM * CDIM / 4;
    const int np4 = CDIM * CDIM / 4;

    split_kernel<<<(nx4 + 255) / 256, 256>>>((const float4*)x,
        (__nv_bfloat162*)a_hi, (__nv_bfloat162*)a_lo, nx4);
    split_kernel<<<(nw4 + 255) / 256, 256>>>((const float4*)qkv_w,
        (__nv_bfloat162*)w_hi, (__nv_bfloat162*)w_lo, nw4);

    mma_gemm<0><<<dim3(18, 64), 256, GEMM_SMEM>>>(a_hi, a_lo, w_hi, w_lo, qkv_b, nullptr);

    attn_kernel<<<dim3(SEQ / 64, HEADS, BATCH), 128, ATTN_SMEM>>>();

    split_kernel<<<(np4 + 255) / 256, 256>>>((const float4*)proj_w,
        (__nv_bfloat162*)w_hi, (__nv_bfloat162*)w_lo, np4);
    mma_gemm<1><<<dim3(6, 64), 256, GEMM_SMEM>>>(a_hi, a_lo, w_hi, w_lo, proj_b, out);
}

// round 10
// speedup vs baseline: 3.3840x; 1.0193x over previous
#include <cuda_runtime.h>
#include <cuda_bf16.h>
#include <cstdint>

#define HEADS 12
#define SEQ   2048
#define BATCH 4
#define DH    64
#define CDIM  768
#define MTOT  8192   // BATCH*SEQ
#define NQKV ((size_t)BATCH * HEADS * SEQ * DH)

// ---------------- scratch (allocation-free) ----------------
// Q (prescaled), K, V all in [B,H,N,D], bf16 hi/lo
__device__ __align__(16) __nv_bfloat16 g_qhi[NQKV], g_qlo[NQKV];
__device__ __align__(16) __nv_bfloat16 g_khi[NQKV], g_klo[NQKV];
__device__ __align__(16) __nv_bfloat16 g_vhi[NQKV], g_vlo[NQKV];
__device__ __align__(16) __nv_bfloat16 g_a_hi[(size_t)MTOT * CDIM];
__device__ __align__(16) __nv_bfloat16 g_a_lo[(size_t)MTOT * CDIM];
__device__ __align__(16) __nv_bfloat16 g_w_hi[(size_t)3 * CDIM * CDIM];
__device__ __align__(16) __nv_bfloat16 g_w_lo[(size_t)3 * CDIM * CDIM];

// Q prescale: 1/sqrt(64) * log2(e)  (softmax runs in exp2 domain)
#define QSCALE 0.1803368801111204f

// ---------------- helpers ----------------
__device__ __forceinline__ uint32_t smem_u32(const void* p) {
    uint32_t a;
    asm("{ .reg .u64 t; cvta.to.shared.u64 t, %1; cvt.u32.u64 %0, t; }" : "=r"(a) : "l"(p));
    return a;
}
__device__ __forceinline__ void ldsm4(uint32_t& r0, uint32_t& r1, uint32_t& r2, uint32_t& r3,
                                      uint32_t addr) {
    asm volatile("ldmatrix.sync.aligned.m8n8.x4.shared.b16 {%0,%1,%2,%3}, [%4];"
                 : "=r"(r0), "=r"(r1), "=r"(r2), "=r"(r3) : "r"(addr));
}
__device__ __forceinline__ void ldsm4t(uint32_t& r0, uint32_t& r1, uint32_t& r2, uint32_t& r3,
                                       uint32_t addr) {
    asm volatile("ldmatrix.sync.aligned.m8n8.x4.trans.shared.b16 {%0,%1,%2,%3}, [%4];"
                 : "=r"(r0), "=r"(r1), "=r"(r2), "=r"(r3) : "r"(addr));
}
__device__ __forceinline__ void mma16816(float* c, const uint32_t* a, uint32_t b0, uint32_t b1) {
    asm volatile("mma.sync.aligned.m16n8k16.row.col.f32.bf16.bf16.f32 "
                 "{%0,%1,%2,%3}, {%4,%5,%6,%7}, {%8,%9}, {%0,%1,%2,%3};"
                 : "+f"(c[0]), "+f"(c[1]), "+f"(c[2]), "+f"(c[3])
                 : "r"(a[0]), "r"(a[1]), "r"(a[2]), "r"(a[3]), "r"(b0), "r"(b1));
}
__device__ __forceinline__ __nv_bfloat16 bhi(float x) { return __float2bfloat16(x); }
__device__ __forceinline__ __nv_bfloat16 blo(float x, __nv_bfloat16 h) {
    return __float2bfloat16(x - __bfloat162float(h));
}
__device__ __forceinline__ float ex2f(float x) {
    float y;
    asm("ex2.approx.f32 %0, %1;" : "=f"(y) : "f"(x));
    return y;
}
__device__ __forceinline__ uint32_t packbf(float lo_, float hi_) {
    uint32_t r;
    asm("cvt.rn.bf16x2.f32 %0, %1, %2;" : "=r"(r) : "f"(hi_), "f"(lo_));
    return r;
}

#define CP_ASYNC16(dst, src) \
    asm volatile("cp.async.cg.shared.global [%0], [%1], 16;" :: "r"(dst), "l"(src))
#define CP_COMMIT() asm volatile("cp.async.commit_group;")
#define CP_WAIT1()  asm volatile("cp.async.wait_group 1;")
#define CP_WAIT0()  asm volatile("cp.async.wait_group 0;")

// ---------------------------------------------------------------------------
__global__ void split_kernel(const float4* __restrict__ src,
                             __nv_bfloat162* __restrict__ hi,
                             __nv_bfloat162* __restrict__ lo, int n4)
{
    int i = blockIdx.x * 256 + threadIdx.x;
    if (i < n4) {
        float4 v = src[i];
        __nv_bfloat16 hx = __float2bfloat16(v.x);
        __nv_bfloat16 hy = __float2bfloat16(v.y);
        __nv_bfloat16 hz = __float2bfloat16(v.z);
        __nv_bfloat16 hw = __float2bfloat16(v.w);
        hi[2 * i]     = __nv_bfloat162(hx, hy);
        hi[2 * i + 1] = __nv_bfloat162(hz, hw);
        lo[2 * i]     = __nv_bfloat162(blo(v.x, hx), blo(v.y, hy));
        lo[2 * i + 1] = __nv_bfloat162(blo(v.z, hz), blo(v.w, hw));
    }
}

// ---------------------------------------------------------------------------
// HMMA bf16x3 GEMM v2: single K sweep, Ahi/Alo/Whi/Wlo staged together.
// MODE 0: split epilogue -> Q(prescaled)/K/V, all [B,H,N,D], coalesced stores.
// MODE 1: fp32 row-major.
// ---------------------------------------------------------------------------
#define LDT2 40
#define GM_MSZ (128 * LDT2)
#define GAHI 0
#define GALO GM_MSZ
#define GWHI (2 * GM_MSZ)
#define GWLO (3 * GM_MSZ)
#define GM_BUF (4 * GM_MSZ)
#define GEMM_SMEM (2 * GM_BUF * 2)     // 81920 bytes
#define NCHUNK 24

template <int MODE>
__global__ void __launch_bounds__(256, 2)
mma_gemm(const __nv_bfloat16* __restrict__ a_hi, const __nv_bfloat16* __restrict__ a_lo,
         const __nv_bfloat16* __restrict__ w_hi, const __nv_bfloat16* __restrict__ w_lo,
         const float* __restrict__ bias, float* __restrict__ out)
{
    extern __shared__ __nv_bfloat16 sm[];
    const uint32_t smb = smem_u32(sm);
    const int tid  = threadIdx.x;
    const int lane = tid & 31;
    const int wrp  = tid >> 5;
    const int wm   = wrp & 1;
    const int wn   = wrp >> 1;
    const int rowBase = blockIdx.y * 128;
    const int colBase = blockIdx.x * 128;

    const int a_r = lane & 15;
    const int a_k = (lane >> 4) * 8;
    const int b_r = (lane & 7) + ((lane >> 4) << 3);
    const int b_k = ((lane >> 3) & 1) * 8;

    float acc[4][4][4] = {};

    #define LOAD_CHUNK(kk, buf)                                                       \
        do {                                                                          \
            const uint32_t _bb = smb + (uint32_t)((buf) * GM_BUF) * 2;                \
            _Pragma("unroll")                                                         \
            for (int _i = 0; _i < 2; ++_i) {                                          \
                const int _idx = _i * 256 + tid;                                      \
                const int _r = _idx >> 2, _c = _idx & 3;                              \
                const size_t _ga = (size_t)(rowBase + _r) * CDIM + (kk) + _c * 8;     \
                const size_t _gw = (size_t)(colBase + _r) * CDIM + (kk) + _c * 8;     \
                const uint32_t _so = (uint32_t)(_r * LDT2 + _c * 8) * 2;              \
                CP_ASYNC16(_bb + GAHI * 2 + _so, a_hi + _ga);                         \
                CP_ASYNC16(_bb + GALO * 2 + _so, a_lo + _ga);                         \
                CP_ASYNC16(_bb + GWHI * 2 + _so, w_hi + _gw);                         \
                CP_ASYNC16(_bb + GWLO * 2 + _so, w_lo + _gw);                         \
            }                                                                         \
        } while (0)

    LOAD_CHUNK(0, 0);
    CP_COMMIT();

    for (int t = 0; t < NCHUNK; ++t) {
        const int buf = t & 1;
        __syncthreads();
        if (t < NCHUNK - 1) {
            LOAD_CHUNK((t + 1) * 32, buf ^ 1);
            CP_COMMIT();
            CP_WAIT1();
        } else {
            CP_WAIT0();
        }
        __syncthreads();

        const uint32_t ahB = smb + (uint32_t)(buf * GM_BUF + GAHI) * 2;
        const uint32_t alB = smb + (uint32_t)(buf * GM_BUF + GALO) * 2;
        const uint32_t whB = smb + (uint32_t)(buf * GM_BUF + GWHI) * 2;
        const uint32_t wlB = smb + (uint32_t)(buf * GM_BUF + GWLO) * 2;

        #pragma unroll
        for (int ks = 0; ks < 2; ++ks) {
            uint32_t ah[4][4], al[4][4], wh2[2][4], wl2[2][4];
            #pragma unroll
            for (int mt = 0; mt < 4; ++mt) {
                const uint32_t off =
                    (uint32_t)((wm * 64 + mt * 16 + a_r) * LDT2 + ks * 16 + a_k) * 2;
                ldsm4(ah[mt][0], ah[mt][1], ah[mt][2], ah[mt][3], ahB + off);
                ldsm4(al[mt][0], al[mt][1], al[mt][2], al[mt][3], alB + off);
            }
            #pragma unroll
            for (int np2 = 0; np2 < 2; ++np2) {
                const uint32_t off =
                    (uint32_t)((wn * 32 + np2 * 16 + b_r) * LDT2 + ks * 16 + b_k) * 2;
                ldsm4(wh2[np2][0], wh2[np2][1], wh2[np2][2], wh2[np2][3], whB + off);
                ldsm4(wl2[np2][0], wl2[np2][1], wl2[np2][2], wl2[np2][3], wlB + off);
            }
            #pragma unroll
            for (int mt = 0; mt < 4; ++mt)
                #pragma unroll
                for (int nt = 0; nt < 4; ++nt) {
                    const uint32_t bh0 = wh2[nt >> 1][(nt & 1) * 2];
                    const uint32_t bh1 = wh2[nt >> 1][(nt & 1) * 2 + 1];
                    const uint32_t bl0 = wl2[nt >> 1][(nt & 1) * 2];
                    const uint32_t bl1 = wl2[nt >> 1][(nt & 1) * 2 + 1];
                    mma16816(acc[mt][nt], ah[mt], bh0, bh1);
                    mma16816(acc[mt][nt], al[mt], bh0, bh1);
                    mma16816(acc[mt][nt], ah[mt], bl0, bl1);
                }
        }
    }
    #undef LOAD_CHUNK

    #pragma unroll
    for (int mt = 0; mt < 4; ++mt) {
        const int r0 = rowBase + wm * 64 + mt * 16 + (lane >> 2);
        #pragma unroll
        for (int nt = 0; nt < 4; ++nt) {
            const int c = colBase + wn * 32 + nt * 8 + (lane & 3) * 2;
            const float2 bv = *(const float2*)&bias[c];
            float vx0 = acc[mt][nt][0] + bv.x, vy0 = acc[mt][nt][1] + bv.y;
            float vx1 = acc[mt][nt][2] + bv.x, vy1 = acc[mt][nt][3] + bv.y;
            if (MODE == 0) {
                const int tsel = c / CDIM;
                const int rem  = c - tsel * CDIM;
                const int hh = rem >> 6, d = rem & 63;
                const int m0 = r0, b0 = m0 >> 11, n0 = m0 & 2047;
                const int n1 = n0 + 8;
                if (tsel == 0) { vx0 *= QSCALE; vy0 *= QSCALE; vx1 *= QSCALE; vy1 *= QSCALE; }
                __nv_bfloat16 h00 = bhi(vx0), h01 = bhi(vy0), h10 = bhi(vx1), h11 = bhi(vy1);
                __nv_bfloat16* dh = (tsel == 0) ? g_qhi : (tsel == 1) ? g_khi : g_vhi;
                __nv_bfloat16* dl = (tsel == 0) ? g_qlo : (tsel == 1) ? g_klo : g_vlo;
                const size_t i0 = (((size_t)b0 * HEADS + hh) * SEQ + n0) * DH + d;
                const size_t i1 = (((size_t)b0 * HEADS + hh) * SEQ + n1) * DH + d;
                *(__nv_bfloat162*)&dh[i0] = __nv_bfloat162(h00, h01);
                *(__nv_bfloat162*)&dl[i0] = __nv_bfloat162(blo(vx0, h00), blo(vy0, h01));
                *(__nv_bfloat162*)&dh[i1] = __nv_bfloat162(h10, h11);
                *(__nv_bfloat162*)&dl[i1] = __nv_bfloat162(blo(vx1, h10), blo(vy1, h11));
            } else {
                float2 v0, v1;
                v0.x = vx0; v0.y = vy0; v1.x = vx1; v1.y = vy1;
                *(float2*)&out[(size_t)r0 * CDIM + c] = v0;
                *(float2*)&out[(size_t)(r0 + 8) * CDIM + c] = v1;
            }
        }
    }
}

// ---------------------------------------------------------------------------
// HMMA flash attention v5: V stored row-major [k][d] like K; PV B-fragments
// via ldmatrix.trans. Q fragments register-resident, P fragments direct from
// S accumulators. 64q x 64k tiles, 128 threads, 72KB smem -> 3 CTAs/SM.
// ---------------------------------------------------------------------------
#define QLD 72
#define MSZ (64 * QLD)
#define BKHI 0
#define BKLO MSZ
#define BVHI (2 * MSZ)
#define BVLO (3 * MSZ)
#define BUFSZ (4 * MSZ)
#define ATTN_SMEM (2 * BUFSZ * 2)   // 73728 bytes

__global__ void __launch_bounds__(128, 3)
attn_kernel()
{
    extern __shared__ __nv_bfloat16 sm[];
    const uint32_t smb = smem_u32(sm);

    const int q0 = blockIdx.x * 64;
    const int h  = blockIdx.y;
    const int b  = blockIdx.z;
    const size_t base = ((size_t)(b * HEADS + h)) * SEQ * DH;

    const int tid  = threadIdx.x;
    const int lane = tid & 31;
    const int wrp  = tid >> 5;
    const int wq   = wrp * 16;

    const int a_r = lane & 15;
    const int a_k = (lane >> 4) * 8;
    const int b_r = (lane & 7) + ((lane >> 4) << 3);
    const int b_k = ((lane >> 3) & 1) * 8;
    // trans-ldsm lane mapping for V[k][d] tiles
    const int v_k = (lane & 7) + (((lane >> 3) & 1) << 3);
    const int v_d = (lane >> 4) * 8;
    const int qr  = lane >> 2;
    const int qc  = (lane & 3) * 2;

    uint32_t qh[4][4], ql[4][4];
    {
        #pragma unroll
        for (int i = 0; i < 4; ++i) {
            const int idx = i * 128 + tid;
            const int r = idx >> 3, c8 = idx & 7;
            *(uint4*)&sm[r * QLD + c8 * 8] =
                *(const uint4*)&g_qhi[base + (size_t)(q0 + r) * DH + c8 * 8];
            *(uint4*)&sm[MSZ + r * QLD + c8 * 8] =
                *(const uint4*)&g_qlo[base + (size_t)(q0 + r) * DH + c8 * 8];
        }
        __syncthreads();
        #pragma unroll
        for (int ks = 0; ks < 4; ++ks) {
            ldsm4(qh[ks][0], qh[ks][1], qh[ks][2], qh[ks][3],
                  smb + (uint32_t)((wq + a_r) * QLD + ks * 16 + a_k) * 2);
            ldsm4(ql[ks][0], ql[ks][1], ql[ks][2], ql[ks][3],
                  smb + (uint32_t)(MSZ + (wq + a_r) * QLD + ks * 16 + a_k) * 2);
        }
        __syncthreads();
    }

    // K and V tiles share the same [row 64][col 64] addressing now
    #define LOAD_TILE(k0, buf)                                                        \
        do {                                                                          \
            const uint32_t _bb = smb + (uint32_t)((buf) * BUFSZ) * 2;                 \
            const __nv_bfloat16* _kh = g_khi + base + (size_t)(k0) * DH;              \
            const __nv_bfloat16* _kl = g_klo + base + (size_t)(k0) * DH;              \
            const __nv_bfloat16* _vh = g_vhi + base + (size_t)(k0) * DH;              \
            const __nv_bfloat16* _vl = g_vlo + base + (size_t)(k0) * DH;              \
            _Pragma("unroll")                                                         \
            for (int _i = 0; _i < 4; ++_i) {                                          \
                const int _idx = _i * 128 + tid;                                      \
                const int _r = _idx >> 3, _c = _idx & 7;                              \
                const uint32_t _so = (uint32_t)(_r * QLD + _c * 8) * 2;               \
                const size_t _go = (size_t)_r * 64 + _c * 8;                          \
                CP_ASYNC16(_bb + BKHI * 2 + _so, _kh + _go);                          \
                CP_ASYNC16(_bb + BKLO * 2 + _so, _kl + _go);                          \
                CP_ASYNC16(_bb + BVHI * 2 + _so, _vh + _go);                          \
                CP_ASYNC16(_bb + BVLO * 2 + _so, _vl + _go);                          \
            }                                                                         \
        } while (0)

    LOAD_TILE(0, 0);
    CP_COMMIT();

    float m_i[2] = {-1e30f, -1e30f};
    float l_i[2] = {0.f, 0.f};
    float oacc[8][4] = {};

    for (int t = 0; t < 32; ++t) {
        const int buf = t & 1;
        __syncthreads();
        if (t < 31) {
            LOAD_TILE((t + 1) * 64, buf ^ 1);
            CP_COMMIT();
            CP_WAIT1();
        } else {
            CP_WAIT0();
        }
        __syncthreads();

        const uint32_t kh = smb + (uint32_t)(buf * BUFSZ + BKHI) * 2;
        const uint32_t kl = smb + (uint32_t)(buf * BUFSZ + BKLO) * 2;
        const uint32_t vh = smb + (uint32_t)(buf * BUFSZ + BVHI) * 2;
        const uint32_t vl = smb + (uint32_t)(buf * BUFSZ + BVLO) * 2;

        // ---- S = QK^T ----
        float sacc[8][4] = {};
        #pragma unroll
        for (int ks = 0; ks < 4; ++ks) {
            #pragma unroll
            for (int ng = 0; ng < 4; ++ng) {
                uint32_t bf[4];
                ldsm4(bf[0], bf[1], bf[2], bf[3],
                      kh + (uint32_t)((ng * 16 + b_r) * QLD + ks * 16 + b_k) * 2);
                mma16816(sacc[ng * 2 + 0], qh[ks], bf[0], bf[1]);
                mma16816(sacc[ng * 2 + 1], qh[ks], bf[2], bf[3]);
                mma16816(sacc[ng * 2 + 0], ql[ks], bf[0], bf[1]);
                mma16816(sacc[ng * 2 + 1], ql[ks], bf[2], bf[3]);
            }
        }
        #pragma unroll
        for (int ks = 0; ks < 4; ++ks) {
            #pragma unroll
            for (int ng = 0; ng < 4; ++ng) {
                uint32_t bf[4];
                ldsm4(bf[0], bf[1], bf[2], bf[3],
                      kl + (uint32_t)((ng * 16 + b_r) * QLD + ks * 16 + b_k) * 2);
                mma16816(sacc[ng * 2 + 0], qh[ks], bf[0], bf[1]);
                mma16816(sacc[ng * 2 + 1], qh[ks], bf[2], bf[3]);
            }
        }

        // ---- online softmax (exp2 domain, warp-local rows qr, qr+8) ----
        #pragma unroll
        for (int ri = 0; ri < 2; ++ri) {
            float mx = -1e30f;
            #pragma unroll
            for (int nt = 0; nt < 8; ++nt) {
                mx = fmaxf(mx, sacc[nt][ri * 2 + 0]);
                mx = fmaxf(mx, sacc[nt][ri * 2 + 1]);
            }
            mx = fmaxf(mx, __shfl_xor_sync(0xffffffffu, mx, 1));
            mx = fmaxf(mx, __shfl_xor_sync(0xffffffffu, mx, 2));
            const float mn = fmaxf(m_i[ri], mx);
            const float alpha = ex2f(m_i[ri] - mn);
            m_i[ri] = mn;
            float r = 0.f;
            #pragma unroll
            for (int nt = 0; nt < 8; ++nt) {
                float p0 = ex2f(sacc[nt][ri * 2 + 0] - mn);
                float p1 = ex2f(sacc[nt][ri * 2 + 1] - mn);
                sacc[nt][ri * 2 + 0] = p0;
                sacc[nt][ri * 2 + 1] = p1;
                r += p0 + p1;
            }
            r += __shfl_xor_sync(0xffffffffu, r, 1);
            r += __shfl_xor_sync(0xffffffffu, r, 2);
            l_i[ri] = l_i[ri] * alpha + r;
            #pragma unroll
            for (int nt = 0; nt < 8; ++nt) {
                oacc[nt][ri * 2 + 0] *= alpha;
                oacc[nt][ri * 2 + 1] *= alpha;
            }
        }

        // ---- PV: P frags direct from sacc, V frags via ldmatrix.trans ----
        #pragma unroll
        for (int ks = 0; ks < 4; ++ks) {
            uint32_t ph[4], pl[4];
            {
                const float s00 = sacc[2 * ks][0],     s01 = sacc[2 * ks][1];
                const float s02 = sacc[2 * ks][2],     s03 = sacc[2 * ks][3];
                const float s10 = sacc[2 * ks + 1][0], s11 = sacc[2 * ks + 1][1];
                const float s12 = sacc[2 * ks + 1][2], s13 = sacc[2 * ks + 1][3];
                ph[0] = packbf(s00, s01);
                ph[1] = packbf(s02, s03);
                ph[2] = packbf(s10, s11);
                ph[3] = packbf(s12, s13);
                pl[0] = packbf(s00 - __uint_as_float(ph[0] << 16),
                               s01 - __uint_as_float(ph[0] & 0xffff0000u));
                pl[1] = packbf(s02 - __uint_as_float(ph[1] << 16),
                               s03 - __uint_as_float(ph[1] & 0xffff0000u));
                pl[2] = packbf(s10 - __uint_as_float(ph[2] << 16),
                               s11 - __uint_as_float(ph[2] & 0xffff0000u));
                pl[3] = packbf(s12 - __uint_as_float(ph[3] << 16),
                               s13 - __uint_as_float(ph[3] & 0xffff0000u));
            }
            const uint32_t vrow = (uint32_t)((ks * 16 + v_k) * QLD) * 2;
            #pragma unroll
            for (int ng = 0; ng < 4; ++ng) {
                uint32_t bh[4], bl[4];
                const uint32_t voff = vrow + (uint32_t)(ng * 16 + v_d) * 2;
                ldsm4t(bh[0], bh[1], bh[2], bh[3], vh + voff);
                ldsm4t(bl[0], bl[1], bl[2], bl[3], vl + voff);
                mma16816(oacc[ng * 2 + 0], ph, bh[0], bh[1]);
                mma16816(oacc[ng * 2 + 1], ph, bh[2], bh[3]);
                mma16816(oacc[ng * 2 + 0], ph, bl[0], bl[1]);
                mma16816(oacc[ng * 2 + 1], ph, bl[2], bl[3]);
                mma16816(oacc[ng * 2 + 0], pl, bh[0], bh[1]);
                mma16816(oacc[ng * 2 + 1], pl, bh[2], bh[3]);
            }
        }
    }

    // ---- epilogue: normalize, split hi/lo, write a_hi/a_lo [B,N,C] ----
    const float inv0 = 1.f / l_i[0];
    const float inv1 = 1.f / l_i[1];
    const int row0 = q0 + wq + qr;
    #pragma unroll
    for (int nt = 0; nt < 8; ++nt) {
        const int col = h * DH + nt * 8 + qc;
        const size_t i0 = ((size_t)b * SEQ + row0) * CDIM + col;
        const size_t i1 = ((size_t)b * SEQ + row0 + 8) * CDIM + col;
        float o00 = oacc[nt][0] * inv0, o01 = oacc[nt][1] * inv0;
        float o10 = oacc[nt][2] * inv1, o11 = oacc[nt][3] * inv1;
        __nv_bfloat16 h00 = bhi(o00), h01 = bhi(o01), h10 = bhi(o10), h11 = bhi(o11);
        *(__nv_bfloat162*)&g_a_hi[i0] = __nv_bfloat162(h00, h01);
        *(__nv_bfloat162*)&g_a_lo[i0] = __nv_bfloat162(blo(o00, h00), blo(o01, h01));
        *(__nv_bfloat162*)&g_a_hi[i1] = __nv_bfloat162(h10, h11);
        *(__nv_bfloat162*)&g_a_lo[i1] = __nv_bfloat162(blo(o10, h10), blo(o11, h11));
    }
    #undef LOAD_TILE
}

// ---------------------------------------------------------------------------
extern "C" void kernel_launch(void* const* d_in, const int* in_sizes, int n_in,
                              void* d_out, int out_size)
{
    const float* x      = (const float*)d_in[0];
    const float* qkv_w  = (const float*)d_in[1];
    const float* qkv_b  = (const float*)d_in[2];
    const float* proj_w = (const float*)d_in[3];
    const float* proj_b = (const float*)d_in[4];
    float* out = (float*)d_out;

    cudaFuncSetAttribute(mma_gemm<0>, cudaFuncAttributeMaxDynamicSharedMemorySize, GEMM_SMEM);
    cudaFuncSetAttribute(mma_gemm<1>, cudaFuncAttributeMaxDynamicSharedMemorySize, GEMM_SMEM);
    cudaFuncSetAttribute(attn_kernel, cudaFuncAttributeMaxDynamicSharedMemorySize, ATTN_SMEM);

    __nv_bfloat16 *a_hi, *a_lo, *w_hi, *w_lo;
    cudaGetSymbolAddress((void**)&a_hi, g_a_hi);
    cudaGetSymbolAddress((void**)&a_lo, g_a_lo);
    cudaGetSymbolAddress((void**)&w_hi, g_w_hi);
    cudaGetSymbolAddress((void**)&w_lo, g_w_lo);

    const int nx4 = MTOT * CDIM / 4;
    const int nw4 = 3 * CDIM * CDIM / 4;
    const int np4 = CDIM * CDIM / 4;

    split_kernel<<<(nx4 + 255) / 256, 256>>>((const float4*)x,
        (__nv_bfloat162*)a_hi, (__nv_bfloat162*)a_lo, nx4);
    split_kernel<<<(nw4 + 255) / 256, 256>>>((const float4*)qkv_w,
        (__nv_bfloat162*)w_hi, (__nv_bfloat162*)w_lo, nw4);

    mma_gemm<0><<<dim3(18, 64), 256, GEMM_SMEM>>>(a_hi, a_lo, w_hi, w_lo, qkv_b, nullptr);

    attn_kernel<<<dim3(SEQ / 64, HEADS, BATCH), 128, ATTN_SMEM>>>();

    split_kernel<<<(np4 + 255) / 256, 256>>>((const float4*)proj_w,
        (__nv_bfloat162*)w_hi, (__nv_bfloat162*)w_lo, np4);
    mma_gemm<1><<<dim3(6, 64), 256, GEMM_SMEM>>>(a_hi, a_lo, w_hi, w_lo, proj_b, out);
}